// round 12
// baseline (speedup 1.0000x reference)
#include <cuda_runtime.h>
#include <cstdint>
#include <math.h>

// Problem constants (B=128 trees, depth D=6, NPT=127)
#define Hh     450
#define NNODE  16256   // 128*127
#define NEDGE  32256   // 2*128*126
#define Vv     780     // vocabulary size

// Scratch (static device globals; allocation-free kernel_launch)
// No zero-init needed — every nm/nrm location is STOREd before any
// accumulate or read (up levels store sibling sums; lvl11 stores leaf nm).
__device__ float g_Tz [Vv*Hh];
__device__ float g_Th [Vv*Hh];
__device__ float g_Tr [Vv*Hh];
__device__ float g_Tg [Vv*Hh];
__device__ float g_Tm [Vv*Hh];     // leaf message table sigmoid(Tz)*tanh(Th)
__device__ float g_TR [Vv*Hh];     // TRu = Tm @ Ur
__device__ float g_m  [NEDGE*Hh];
__device__ float g_rm [NEDGE*Hh];
__device__ float g_nm [NNODE*Hh];
__device__ float g_nrm[NNODE*Hh];

__device__ __forceinline__ float sigmoidf_(float v){ return 1.0f/(1.0f+expf(-v)); }

// 8-byte cp.async with zero-fill when invalid (used by k_final)
__device__ __forceinline__ void cpa8(unsigned int dst, const float* src, bool valid){
  int sz = valid ? 8 : 0;
  asm volatile("cp.async.ca.shared.global [%0], [%1], 8, %2;\n"
               :: "r"(dst), "l"(src), "r"(sz));
}
__device__ __forceinline__ unsigned int sptr(const void* p){
  return (unsigned int)__cvta_generic_to_shared(p);
}
#define CP_COMMIT() asm volatile("cp.async.commit_group;\n" ::)
#define CP_WAIT1()  asm volatile("cp.async.wait_group 1;\n" ::)
#define CP_WAIT0()  asm volatile("cp.async.wait_group 0;\n" ::)

// ---------------------------------------------------------------------------
// Fused vocab-table GEMM: T[z] = emb @ W[z] + bias[z]   (M=780, N=K=450)
// ---------------------------------------------------------------------------
__global__ __launch_bounds__(256) void k_vocab4(
    const float* __restrict__ emb,
    const float* __restrict__ W0, const float* __restrict__ b0,
    const float* __restrict__ W1, const float* __restrict__ b1,
    const float* __restrict__ W2, const float* __restrict__ b2,
    const float* __restrict__ W3, const float* __restrict__ b3){
  __shared__ float As[8][64];
  __shared__ float Bs[8][128];
  int which = blockIdx.z;
  const float* W    = (which==0)?W0:(which==1)?W1:(which==2)?W2:W3;
  const float* bias = (which==0)?b0:(which==1)?b1:(which==2)?b2:b3;
  float* T = (which==0)?g_Tz:(which==1)?g_Th:(which==2)?g_Tr:g_Tg;
  int bm = blockIdx.x*64, bn = blockIdx.y*128;
  int tid = threadIdx.x, ty = tid>>4, tx = tid&15;
  float acc[4][8] = {};
  int lr = tid>>2, lk = (tid&3)*2;
  int rr = bm + lr; if (rr >= Vv) rr = Vv-1;
  const float* Ar = emb + (size_t)rr*Hh;
  int kr = tid>>5, nc = (tid&31)*4;

  for (int k0=0; k0<Hh; k0+=8){
    {
      int gk = k0 + lk;
      float2 v = (gk<Hh)? *(const float2*)(Ar+gk) : make_float2(0.f,0.f);
      As[lk][lr] = v.x; As[lk+1][lr] = v.y;
    }
    {
      int gk = k0 + kr;
      const float* Br = W + (size_t)gk*Hh;
      #pragma unroll
      for (int u=0;u<4;u+=2){
        int gn = bn + nc + u;
        float2 v = (gk<Hh && gn<Hh)? *(const float2*)(Br+gn) : make_float2(0.f,0.f);
        Bs[kr][nc+u] = v.x; Bs[kr][nc+u+1] = v.y;
      }
    }
    __syncthreads();
    #pragma unroll
    for (int kk=0; kk<8; kk++){
      float4 a0 = *(const float4*)&As[kk][ty*4];
      float4 b0v = *(const float4*)&Bs[kk][tx*8];
      float4 b1v = *(const float4*)&Bs[kk][tx*8+4];
      float a[4] = {a0.x,a0.y,a0.z,a0.w};
      float b[8] = {b0v.x,b0v.y,b0v.z,b0v.w,b1v.x,b1v.y,b1v.z,b1v.w};
      #pragma unroll
      for (int i=0;i<4;i++)
        #pragma unroll
        for (int j=0;j<8;j++) acc[i][j] = fmaf(a[i], b[j], acc[i][j]);
    }
    __syncthreads();
  }
  #pragma unroll
  for (int i=0;i<4;i++){
    int r = bm + ty*4 + i;
    if (r >= Vv) continue;
    #pragma unroll
    for (int j=0;j<8;j+=2){
      int c = bn + tx*8 + j;
      if (c >= Hh) continue;
      float2 bv = *(const float2*)(bias + c);
      *(float2*)(T + (size_t)r*Hh + c) =
          make_float2(acc[i][j]+bv.x, acc[i][j+1]+bv.y);
    }
  }
}

// ---------------------------------------------------------------------------
// Tm table: Tm[w] = sigmoid(Tz[w]) * tanh(Th[w])   (pointwise, 780x450)
// ---------------------------------------------------------------------------
__global__ void k_tm(){
  int i2 = blockIdx.x*blockDim.x + threadIdx.x;
  const int N2 = Vv*Hh/2;
  if (i2 < N2){
    float2 a = ((const float2*)g_Tz)[i2];
    float2 b = ((const float2*)g_Th)[i2];
    ((float2*)g_Tm)[i2] = make_float2(sigmoidf_(a.x)*tanhf(b.x),
                                      sigmoidf_(a.y)*tanhf(b.y));
  }
}

// ---------------------------------------------------------------------------
// Vocab TR GEMM: g_TR = g_Tm @ Ur   (M=780, N=K=450)
// 64x64x8 tile, 4x4 microtile -> 104 blocks
// ---------------------------------------------------------------------------
__global__ __launch_bounds__(256) void k_vocabTR(const float* __restrict__ Ur){
  __shared__ float As[8][64];
  __shared__ float Bs[8][64];
  int bm = blockIdx.x*64, bn = blockIdx.y*64;
  int tid = threadIdx.x, ty = tid>>4, tx = tid&15;
  float acc[4][4] = {};
  int lr = tid>>2, lk = (tid&3)*2;
  int rr = bm + lr; if (rr >= Vv) rr = Vv-1;
  const float* Ar = g_Tm + (size_t)rr*Hh;
  int kr = tid>>5, cn = (tid&31)*2;

  for (int k0=0; k0<Hh; k0+=8){
    {
      int gk = k0 + lk;
      float2 v = (gk<Hh)? *(const float2*)(Ar+gk) : make_float2(0.f,0.f);
      As[lk][lr] = v.x; As[lk+1][lr] = v.y;
    }
    {
      int gk = k0 + kr, gn = bn + cn;
      float2 v = (gk<Hh && gn<Hh)? *(const float2*)(Ur + (size_t)gk*Hh + gn)
                                 : make_float2(0.f,0.f);
      Bs[kr][cn] = v.x; Bs[kr][cn+1] = v.y;
    }
    __syncthreads();
    #pragma unroll
    for (int kk=0; kk<8; kk++){
      float4 a0 = *(const float4*)&As[kk][ty*4];
      float4 b0 = *(const float4*)&Bs[kk][tx*4];
      float a[4] = {a0.x,a0.y,a0.z,a0.w};
      float b[4] = {b0.x,b0.y,b0.z,b0.w};
      #pragma unroll
      for (int i=0;i<4;i++)
        #pragma unroll
        for (int j=0;j<4;j++) acc[i][j] = fmaf(a[i], b[j], acc[i][j]);
    }
    __syncthreads();
  }
  #pragma unroll
  for (int i=0;i<4;i++){
    int r = bm + ty*4 + i;
    if (r >= Vv) continue;
    #pragma unroll
    for (int j=0;j<4;j+=2){
      int c = bn + tx*4 + j;
      if (c >= Hh) continue;
      *(float2*)(g_TR + (size_t)r*Hh + c) = make_float2(acc[i][j], acc[i][j+1]);
    }
  }
}

// ---------------------------------------------------------------------------
// Leaf level (lvl0): one block per SIBLING PAIR. STOREs nm/nrm (first write).
// ---------------------------------------------------------------------------
__global__ void k_leaf(const int* __restrict__ sched, const int* __restrict__ srcv,
                       const int* __restrict__ dstv, const int* __restrict__ wid){
  int b  = blockIdx.x;
  int e0 = sched[2*b], e1 = sched[2*b+1];
  int w0 = wid[srcv[e0]], w1 = wid[srcv[e1]];
  int d  = dstv[e0];                // sibling pair shares dst
  int wd = wid[d];
  int c = threadIdx.x*2;
  if (c >= Hh) return;
  float2 tm0 = *(const float2*)(g_Tm + (size_t)w0*Hh + c);
  float2 tm1 = *(const float2*)(g_Tm + (size_t)w1*Hh + c);
  float2 tr0 = *(const float2*)(g_TR + (size_t)w0*Hh + c);
  float2 tr1 = *(const float2*)(g_TR + (size_t)w1*Hh + c);
  float2 xr  = *(const float2*)(g_Tr + (size_t)wd*Hh + c);
  float2 rm0 = make_float2(sigmoidf_(tr0.x+xr.x)*tm0.x, sigmoidf_(tr0.y+xr.y)*tm0.y);
  float2 rm1 = make_float2(sigmoidf_(tr1.x+xr.x)*tm1.x, sigmoidf_(tr1.y+xr.y)*tm1.y);
  *(float2*)(g_m  + (size_t)e0*Hh + c) = tm0;
  *(float2*)(g_m  + (size_t)e1*Hh + c) = tm1;
  *(float2*)(g_rm + (size_t)e0*Hh + c) = rm0;
  *(float2*)(g_rm + (size_t)e1*Hh + c) = rm1;
  size_t idx = (size_t)d*Hh + c;
  *(float2*)(g_nm+idx)  = make_float2(tm0.x+tm1.x, tm0.y+tm1.y);   // STORE
  *(float2*)(g_nrm+idx) = make_float2(rm0.x+rm1.x, rm0.y+rm1.y);   // STORE
}

// ---------------------------------------------------------------------------
// GEMM A big (dual, 128x64x8, 8x4 microtile, reg-prefetch):
//   Z = S@WzB, MT = ARM@WhB ; m_new = (1-z)*s + z*mt
// dstout=0: write g_m[e];  dstout=1 (lvl11): write g_nm[dst[e]] directly
// (lvl11 m is consumed only by nm; dst unique; replaces scat11 kernel)
// ---------------------------------------------------------------------------
__global__ __launch_bounds__(256) void k_gemmA_b(
    const int* __restrict__ sched, const int* __restrict__ srcv,
    const int* __restrict__ revv,  const int* __restrict__ dstv,
    const int* __restrict__ wid,
    const float* __restrict__ WzB, const float* __restrict__ WhB,
    int sub, int dstout){
  __shared__ float Ss[8][128], Rs[8][128];
  __shared__ float Bz[8][64],  Bh[8][64];
  __shared__ int s_out[128], s_se[128], s_rv[128], s_w[128];
  int bm = blockIdx.x*128, bn = blockIdx.y*64;
  int tid = threadIdx.x;
  if (tid < 128){
    int e = sched[bm + tid];
    int se = srcv[e];
    s_out[tid] = dstout ? dstv[e] : e;
    s_se[tid] = se; s_rv[tid] = revv[e]; s_w[tid] = wid[se];
  }
  __syncthreads();
  int ty = tid>>4, tx = tid&15;
  float accZ[8][4] = {}, accH[8][4] = {};
  int lr = tid>>1, lk = (tid&1)*4;
  const float* nmr = g_nm  + (size_t)s_se[lr]*Hh;
  const float* nrr = g_nrm + (size_t)s_se[lr]*Hh;
  const float* mr  = g_m   + (size_t)s_rv[lr]*Hh;
  const float* rmr = g_rm  + (size_t)s_rv[lr]*Hh;
  int kr = tid>>5, ncB = (tid&31)*2;

  float2 pm[2], pr[2], pz, ph;
  #pragma unroll
  for (int u=0;u<2;u++){
    int gk = lk + 2*u;
    float2 vm = make_float2(0.f,0.f), vr = make_float2(0.f,0.f);
    if (gk < Hh){
      vm = *(const float2*)(nmr+gk); vr = *(const float2*)(nrr+gk);
      if (sub){
        float2 a = *(const float2*)(mr+gk), b = *(const float2*)(rmr+gk);
        vm.x -= a.x; vm.y -= a.y; vr.x -= b.x; vr.y -= b.y;
      }
    }
    pm[u] = vm; pr[u] = vr;
  }
  {
    int gk = kr, gn = bn + ncB;
    bool ok = (gk<Hh) && (gn<Hh);
    pz = ok? *(const float2*)(WzB + (size_t)gk*Hh + gn) : make_float2(0.f,0.f);
    ph = ok? *(const float2*)(WhB + (size_t)gk*Hh + gn) : make_float2(0.f,0.f);
  }

  for (int k0=0; k0<Hh; k0+=8){
    Ss[lk  ][lr] = pm[0].x; Ss[lk+1][lr] = pm[0].y;
    Ss[lk+2][lr] = pm[1].x; Ss[lk+3][lr] = pm[1].y;
    Rs[lk  ][lr] = pr[0].x; Rs[lk+1][lr] = pr[0].y;
    Rs[lk+2][lr] = pr[1].x; Rs[lk+3][lr] = pr[1].y;
    Bz[kr][ncB] = pz.x; Bz[kr][ncB+1] = pz.y;
    Bh[kr][ncB] = ph.x; Bh[kr][ncB+1] = ph.y;
    __syncthreads();
    int kn = k0 + 8;
    if (kn < Hh){
      #pragma unroll
      for (int u=0;u<2;u++){
        int gk = kn + lk + 2*u;
        float2 vm = make_float2(0.f,0.f), vr = make_float2(0.f,0.f);
        if (gk < Hh){
          vm = *(const float2*)(nmr+gk); vr = *(const float2*)(nrr+gk);
          if (sub){
            float2 a = *(const float2*)(mr+gk), b = *(const float2*)(rmr+gk);
            vm.x -= a.x; vm.y -= a.y; vr.x -= b.x; vr.y -= b.y;
          }
        }
        pm[u] = vm; pr[u] = vr;
      }
      int gk = kn + kr, gn = bn + ncB;
      bool ok = (gk<Hh) && (gn<Hh);
      pz = ok? *(const float2*)(WzB + (size_t)gk*Hh + gn) : make_float2(0.f,0.f);
      ph = ok? *(const float2*)(WhB + (size_t)gk*Hh + gn) : make_float2(0.f,0.f);
    }
    #pragma unroll
    for (int kk=0; kk<8; kk++){
      float4 a0 = *(const float4*)&Ss[kk][ty*8];
      float4 a1 = *(const float4*)&Ss[kk][ty*8+4];
      float4 r0 = *(const float4*)&Rs[kk][ty*8];
      float4 r1 = *(const float4*)&Rs[kk][ty*8+4];
      float4 bz = *(const float4*)&Bz[kk][tx*4];
      float4 bh = *(const float4*)&Bh[kk][tx*4];
      float a[8] = {a0.x,a0.y,a0.z,a0.w,a1.x,a1.y,a1.z,a1.w};
      float w[8] = {r0.x,r0.y,r0.z,r0.w,r1.x,r1.y,r1.z,r1.w};
      float vz[4] = {bz.x,bz.y,bz.z,bz.w};
      float vh[4] = {bh.x,bh.y,bh.z,bh.w};
      #pragma unroll
      for (int i=0;i<8;i++)
        #pragma unroll
        for (int j=0;j<4;j++){
          accZ[i][j] = fmaf(a[i], vz[j], accZ[i][j]);
          accH[i][j] = fmaf(w[i], vh[j], accH[i][j]);
        }
    }
    __syncthreads();
  }
  #pragma unroll
  for (int i=0;i<8;i++){
    int r = ty*8 + i;
    int se = s_se[r], oidx = s_out[r], rv = s_rv[r], w = s_w[r];
    const float* xz = g_Tz + (size_t)w*Hh;
    const float* xh = g_Th + (size_t)w*Hh;
    const float* nm = g_nm + (size_t)se*Hh;
    const float* mrr= g_m  + (size_t)rv*Hh;
    float* mo = (dstout ? g_nm : g_m) + (size_t)oidx*Hh;
    #pragma unroll
    for (int j=0;j<4;j+=2){
      int c = bn + tx*4 + j;
      if (c >= Hh) continue;
      float2 xzv = *(const float2*)(xz+c), xhv = *(const float2*)(xh+c);
      float2 nmv = *(const float2*)(nm+c);
      float2 mv  = sub ? *(const float2*)(mrr+c) : make_float2(0.f,0.f);
      float z0 = sigmoidf_(accZ[i][j]   + xzv.x), mt0 = tanhf(accH[i][j]   + xhv.x);
      float z1 = sigmoidf_(accZ[i][j+1] + xzv.y), mt1 = tanhf(accH[i][j+1] + xhv.y);
      float s0 = nmv.x - mv.x, s1 = nmv.y - mv.y;
      *(float2*)(mo+c) = make_float2((1.f-z0)*s0 + z0*mt0,
                                     (1.f-z1)*s1 + z1*mt1);
    }
  }
}

// ---------------------------------------------------------------------------
// GEMM A mid (dual, 64x64x16, 4x4 microtile): for Ne in {2048,4096}
// ---------------------------------------------------------------------------
__global__ __launch_bounds__(256) void k_gemmA_m(
    const int* __restrict__ sched, const int* __restrict__ srcv,
    const int* __restrict__ revv,  const int* __restrict__ wid,
    const float* __restrict__ WzB, const float* __restrict__ WhB, int sub){
  __shared__ float Ss[16][64], Rs[16][64];
  __shared__ float Bz[16][64], Bh[16][64];
  __shared__ int s_eid[64], s_se[64], s_rv[64], s_w[64];
  int bm = blockIdx.x*64, bn = blockIdx.y*64;
  int tid = threadIdx.x;
  if (tid < 64){
    int e = sched[bm + tid];
    int se = srcv[e];
    s_eid[tid] = e; s_se[tid] = se; s_rv[tid] = revv[e]; s_w[tid] = wid[se];
  }
  __syncthreads();
  int ty = tid>>4, tx = tid&15;
  float accZ[4][4] = {}, accH[4][4] = {};
  int lr = tid>>2, lk = (tid&3)*4;
  const float* nmr = g_nm  + (size_t)s_se[lr]*Hh;
  const float* nrr = g_nrm + (size_t)s_se[lr]*Hh;
  const float* mr  = g_m   + (size_t)s_rv[lr]*Hh;
  const float* rmr = g_rm  + (size_t)s_rv[lr]*Hh;
  int kr = tid>>4, nc = (tid&15)*4;

  for (int k0=0; k0<Hh; k0+=16){
    #pragma unroll
    for (int u=0;u<2;u++){
      int gk = k0 + lk + 2*u;
      float2 vm = make_float2(0.f,0.f), vr = make_float2(0.f,0.f);
      if (gk < Hh){
        vm = *(const float2*)(nmr+gk); vr = *(const float2*)(nrr+gk);
        if (sub){
          float2 a = *(const float2*)(mr+gk), b = *(const float2*)(rmr+gk);
          vm.x -= a.x; vm.y -= a.y; vr.x -= b.x; vr.y -= b.y;
        }
      }
      Ss[lk+2*u][lr] = vm.x; Ss[lk+2*u+1][lr] = vm.y;
      Rs[lk+2*u][lr] = vr.x; Rs[lk+2*u+1][lr] = vr.y;
    }
    {
      int gk = k0 + kr;
      const float* zr = WzB + (size_t)gk*Hh;
      const float* hr = WhB + (size_t)gk*Hh;
      #pragma unroll
      for (int u=0;u<2;u++){
        int gn = bn + nc + 2*u;
        bool ok = (gk<Hh) && (gn<Hh);
        float2 vz = ok? *(const float2*)(zr+gn) : make_float2(0.f,0.f);
        float2 vh = ok? *(const float2*)(hr+gn) : make_float2(0.f,0.f);
        Bz[kr][nc+2*u] = vz.x; Bz[kr][nc+2*u+1] = vz.y;
        Bh[kr][nc+2*u] = vh.x; Bh[kr][nc+2*u+1] = vh.y;
      }
    }
    __syncthreads();
    #pragma unroll
    for (int kk=0; kk<16; kk++){
      float4 a0 = *(const float4*)&Ss[kk][ty*4];
      float4 r0 = *(const float4*)&Rs[kk][ty*4];
      float4 bz = *(const float4*)&Bz[kk][tx*4];
      float4 bh = *(const float4*)&Bh[kk][tx*4];
      float a[4] = {a0.x,a0.y,a0.z,a0.w};
      float w[4] = {r0.x,r0.y,r0.z,r0.w};
      float vz[4] = {bz.x,bz.y,bz.z,bz.w};
      float vh[4] = {bh.x,bh.y,bh.z,bh.w};
      #pragma unroll
      for (int i=0;i<4;i++)
        #pragma unroll
        for (int j=0;j<4;j++){
          accZ[i][j] = fmaf(a[i], vz[j], accZ[i][j]);
          accH[i][j] = fmaf(w[i], vh[j], accH[i][j]);
        }
    }
    __syncthreads();
  }
  #pragma unroll
  for (int i=0;i<4;i++){
    int r = ty*4 + i;
    int se = s_se[r], e = s_eid[r], rv = s_rv[r], w = s_w[r];
    const float* xz = g_Tz + (size_t)w*Hh;
    const float* xh = g_Th + (size_t)w*Hh;
    const float* nm = g_nm + (size_t)se*Hh;
    const float* mrr= g_m  + (size_t)rv*Hh;
    float* mo = g_m + (size_t)e*Hh;
    #pragma unroll
    for (int j=0;j<4;j+=2){
      int c = bn + tx*4 + j;
      if (c >= Hh) continue;
      float2 xzv = *(const float2*)(xz+c), xhv = *(const float2*)(xh+c);
      float2 nmv = *(const float2*)(nm+c);
      float2 mv  = sub ? *(const float2*)(mrr+c) : make_float2(0.f,0.f);
      float z0 = sigmoidf_(accZ[i][j]   + xzv.x), mt0 = tanhf(accH[i][j]   + xhv.x);
      float z1 = sigmoidf_(accZ[i][j+1] + xzv.y), mt1 = tanhf(accH[i][j+1] + xhv.y);
      float s0 = nmv.x - mv.x, s1 = nmv.y - mv.y;
      *(float2*)(mo+c) = make_float2((1.f-z0)*s0 + z0*mt0,
                                     (1.f-z1)*s1 + z1*mt1);
    }
  }
}

// ---------------------------------------------------------------------------
// GEMM B mid (64x128x16, 4x8 microtile): for Ne >= 2048
// up=1: STORE nm/nrm (sibling pair) + write g_rm; up=0: accumulate, skip g_rm
// ---------------------------------------------------------------------------
__global__ __launch_bounds__(256) void k_gemmB_m(
    const int* __restrict__ sched, const int* __restrict__ dstv,
    const int* __restrict__ wid, const float* __restrict__ Ur, int up){
  __shared__ float As[16][64];
  __shared__ float Bs[16][128];
  __shared__ int s_eid[64], s_de[64], s_wd[64];
  int bm = blockIdx.x*64, bn = blockIdx.y*128;
  int tid = threadIdx.x;
  if (tid < 64){
    int e = sched[bm + tid];
    int de = dstv[e];
    s_eid[tid] = e; s_de[tid] = de; s_wd[tid] = wid[de];
  }
  __syncthreads();
  int ty = tid>>4, tx = tid&15;
  float acc[4][8] = {};
  int lr = tid>>2, lk = (tid&3)*4;
  const float* Ar = g_m + (size_t)s_eid[lr]*Hh;
  int kr = tid>>4, nc = (tid&15)*8;

  for (int k0=0; k0<Hh; k0+=16){
    #pragma unroll
    for (int u=0;u<2;u++){
      int gk = k0 + lk + 2*u;
      float2 v = (gk<Hh)? *(const float2*)(Ar+gk) : make_float2(0.f,0.f);
      As[lk+2*u][lr] = v.x; As[lk+2*u+1][lr] = v.y;
    }
    {
      int gk = k0 + kr;
      const float* Br = Ur + (size_t)gk*Hh;
      #pragma unroll
      for (int u=0;u<4;u++){
        int gn = bn + nc + 2*u;
        float2 v = (gk<Hh && gn<Hh)? *(const float2*)(Br+gn) : make_float2(0.f,0.f);
        Bs[kr][nc+2*u] = v.x; Bs[kr][nc+2*u+1] = v.y;
      }
    }
    __syncthreads();
    #pragma unroll
    for (int kk=0; kk<16; kk++){
      float4 a0 = *(const float4*)&As[kk][ty*4];
      float4 b0 = *(const float4*)&Bs[kk][tx*8];
      float4 b1 = *(const float4*)&Bs[kk][tx*8+4];
      float a[4] = {a0.x,a0.y,a0.z,a0.w};
      float b[8] = {b0.x,b0.y,b0.z,b0.w,b1.x,b1.y,b1.z,b1.w};
      #pragma unroll
      for (int i=0;i<4;i++)
        #pragma unroll
        for (int j=0;j<8;j++) acc[i][j] = fmaf(a[i], b[j], acc[i][j]);
    }
    __syncthreads();
  }
  #pragma unroll
  for (int q=0;q<4;q++){
    int c = bn + tx*8 + 2*q;
    if (c >= Hh) continue;
    #pragma unroll
    for (int i=0;i<4;i+=2){
      int r0 = ty*4 + i, r1 = r0 + 1;
      int e0 = s_eid[r0], e1 = s_eid[r1];
      int d0 = s_de[r0],  d1 = s_de[r1];
      int w0 = s_wd[r0],  w1 = s_wd[r1];
      float2 mv0 = *(const float2*)(g_m + (size_t)e0*Hh + c);
      float2 mv1 = *(const float2*)(g_m + (size_t)e1*Hh + c);
      float2 x0  = *(const float2*)(g_Tr + (size_t)w0*Hh + c);
      float2 x1  = *(const float2*)(g_Tr + (size_t)w1*Hh + c);
      float2 rm0 = make_float2(sigmoidf_(acc[i][2*q]+x0.x)*mv0.x,
                               sigmoidf_(acc[i][2*q+1]+x0.y)*mv0.y);
      float2 rm1 = make_float2(sigmoidf_(acc[i+1][2*q]+x1.x)*mv1.x,
                               sigmoidf_(acc[i+1][2*q+1]+x1.y)*mv1.y);
      if (up){
        *(float2*)(g_rm + (size_t)e0*Hh + c) = rm0;
        *(float2*)(g_rm + (size_t)e1*Hh + c) = rm1;
        size_t idx = (size_t)d0*Hh + c;               // sibling pair: STORE
        *(float2*)(g_nm+idx)  = make_float2(mv0.x+mv1.x, mv0.y+mv1.y);
        *(float2*)(g_nrm+idx) = make_float2(rm0.x+rm1.x, rm0.y+rm1.y);
      } else {                                        // down: accumulate
        size_t i0 = (size_t)d0*Hh + c, i1 = (size_t)d1*Hh + c;
        float2 a0v = *(float2*)(g_nm+i0), b0v = *(float2*)(g_nrm+i0);
        a0v.x += mv0.x; a0v.y += mv0.y; b0v.x += rm0.x; b0v.y += rm0.y;
        *(float2*)(g_nm+i0) = a0v; *(float2*)(g_nrm+i0) = b0v;
        float2 a1v = *(float2*)(g_nm+i1), b1v = *(float2*)(g_nrm+i1);
        a1v.x += mv1.x; a1v.y += mv1.y; b1v.x += rm1.x; b1v.y += rm1.y;
        *(float2*)(g_nm+i1) = a1v; *(float2*)(g_nrm+i1) = b1v;
      }
    }
  }
}

// ---------------------------------------------------------------------------
// Small-level variants (32x32x16, 2x2 microtile, 256 threads)
// ---------------------------------------------------------------------------
__global__ __launch_bounds__(256) void k_gemmA_s(
    const int* __restrict__ sched, const int* __restrict__ srcv,
    const int* __restrict__ revv,  const int* __restrict__ wid,
    const float* __restrict__ WzB, const float* __restrict__ WhB, int sub){
  __shared__ float Ss[16][32], Rs[16][32], Bz[16][32], Bh[16][32];
  __shared__ int s_eid[32], s_se[32], s_rv[32], s_w[32];
  int bm = blockIdx.x*32, bn = blockIdx.y*32;
  int tid = threadIdx.x;
  if (tid < 32){
    int e = sched[bm + tid];
    int se = srcv[e];
    s_eid[tid] = e; s_se[tid] = se; s_rv[tid] = revv[e]; s_w[tid] = wid[se];
  }
  __syncthreads();
  int ty = tid>>4, tx = tid&15;
  float accZ[2][2] = {}, accH[2][2] = {};
  int lr = tid>>3, lk = (tid&7)*2;
  const float* nmr = g_nm  + (size_t)s_se[lr]*Hh;
  const float* nrr = g_nrm + (size_t)s_se[lr]*Hh;
  const float* mr  = g_m   + (size_t)s_rv[lr]*Hh;
  const float* rmr = g_rm  + (size_t)s_rv[lr]*Hh;
  int kr = tid>>4, cn = (tid&15)*2;

  for (int k0=0; k0<Hh; k0+=16){
    {
      int gk = k0 + lk;
      float2 vm = make_float2(0.f,0.f), vr = make_float2(0.f,0.f);
      if (gk < Hh){
        vm = *(const float2*)(nmr+gk); vr = *(const float2*)(nrr+gk);
        if (sub){
          float2 a = *(const float2*)(mr+gk), b = *(const float2*)(rmr+gk);
          vm.x -= a.x; vm.y -= a.y; vr.x -= b.x; vr.y -= b.y;
        }
      }
      Ss[lk][lr] = vm.x; Ss[lk+1][lr] = vm.y;
      Rs[lk][lr] = vr.x; Rs[lk+1][lr] = vr.y;
    }
    {
      int gk = k0 + kr, gn = bn + cn;
      bool ok = (gk<Hh) && (gn<Hh);
      float2 vz = ok? *(const float2*)(WzB + (size_t)gk*Hh + gn) : make_float2(0.f,0.f);
      float2 vh = ok? *(const float2*)(WhB + (size_t)gk*Hh + gn) : make_float2(0.f,0.f);
      Bz[kr][cn] = vz.x; Bz[kr][cn+1] = vz.y;
      Bh[kr][cn] = vh.x; Bh[kr][cn+1] = vh.y;
    }
    __syncthreads();
    #pragma unroll
    for (int kk=0; kk<16; kk++){
      float a0=Ss[kk][ty*2], a1=Ss[kk][ty*2+1];
      float w0=Rs[kk][ty*2], w1=Rs[kk][ty*2+1];
      float z0=Bz[kk][tx*2], z1=Bz[kk][tx*2+1];
      float h0=Bh[kk][tx*2], h1=Bh[kk][tx*2+1];
      accZ[0][0]=fmaf(a0,z0,accZ[0][0]); accZ[0][1]=fmaf(a0,z1,accZ[0][1]);
      accZ[1][0]=fmaf(a1,z0,accZ[1][0]); accZ[1][1]=fmaf(a1,z1,accZ[1][1]);
      accH[0][0]=fmaf(w0,h0,accH[0][0]); accH[0][1]=fmaf(w0,h1,accH[0][1]);
      accH[1][0]=fmaf(w1,h0,accH[1][0]); accH[1][1]=fmaf(w1,h1,accH[1][1]);
    }
    __syncthreads();
  }
  #pragma unroll
  for (int i=0;i<2;i++){
    int r = ty*2 + i;
    int se = s_se[r], e = s_eid[r], rv = s_rv[r], w = s_w[r];
    #pragma unroll
    for (int j=0;j<2;j++){
      int c = bn + tx*2 + j;
      if (c >= Hh) continue;
      float z  = sigmoidf_(accZ[i][j] + g_Tz[(size_t)w*Hh + c]);
      float mt = tanhf   (accH[i][j] + g_Th[(size_t)w*Hh + c]);
      float s  = g_nm[(size_t)se*Hh + c] - (sub ? g_m[(size_t)rv*Hh + c] : 0.f);
      g_m[(size_t)e*Hh + c] = (1.f - z)*s + z*mt;
    }
  }
}

__global__ __launch_bounds__(256) void k_gemmB_s(
    const int* __restrict__ sched, const int* __restrict__ dstv,
    const int* __restrict__ wid, const float* __restrict__ Ur, int up){
  __shared__ float As[16][32], Bs[16][32];
  __shared__ int s_eid[32], s_de[32], s_wd[32];
  int bm = blockIdx.x*32, bn = blockIdx.y*32;
  int tid = threadIdx.x;
  if (tid < 32){
    int e = sched[bm + tid];
    int de = dstv[e];
    s_eid[tid] = e; s_de[tid] = de; s_wd[tid] = wid[de];
  }
  __syncthreads();
  int ty = tid>>4, tx = tid&15;
  float acc[2][2] = {};
  int lr = tid>>3, lk = (tid&7)*2;
  const float* Ar = g_m + (size_t)s_eid[lr]*Hh;
  int kr = tid>>4, cn = (tid&15)*2;

  for (int k0=0; k0<Hh; k0+=16){
    {
      int gk = k0 + lk;
      float2 v = (gk<Hh)? *(const float2*)(Ar+gk) : make_float2(0.f,0.f);
      As[lk][lr] = v.x; As[lk+1][lr] = v.y;
    }
    {
      int gk = k0 + kr, gn = bn + cn;
      float2 v = ((gk<Hh)&&(gn<Hh))? *(const float2*)(Ur + (size_t)gk*Hh + gn)
                                   : make_float2(0.f,0.f);
      Bs[kr][cn] = v.x; Bs[kr][cn+1] = v.y;
    }
    __syncthreads();
    #pragma unroll
    for (int kk=0; kk<16; kk++){
      float a0=As[kk][ty*2], a1=As[kk][ty*2+1];
      float b0=Bs[kk][tx*2], b1=Bs[kk][tx*2+1];
      acc[0][0]=fmaf(a0,b0,acc[0][0]); acc[0][1]=fmaf(a0,b1,acc[0][1]);
      acc[1][0]=fmaf(a1,b0,acc[1][0]); acc[1][1]=fmaf(a1,b1,acc[1][1]);
    }
    __syncthreads();
  }
  int r0 = ty*2, r1 = ty*2+1;
  int e0 = s_eid[r0], e1 = s_eid[r1];
  int d0 = s_de[r0],  d1 = s_de[r1];
  int w0 = s_wd[r0],  w1 = s_wd[r1];
  #pragma unroll
  for (int j=0;j<2;j++){
    int c = bn + tx*2 + j;
    if (c >= Hh) continue;
    float mv0 = g_m[(size_t)e0*Hh + c];
    float mv1 = g_m[(size_t)e1*Hh + c];
    float rm0 = sigmoidf_(acc[0][j] + g_Tr[(size_t)w0*Hh + c]) * mv0;
    float rm1 = sigmoidf_(acc[1][j] + g_Tr[(size_t)w1*Hh + c]) * mv1;
    if (up){
      g_rm[(size_t)e0*Hh + c] = rm0;
      g_rm[(size_t)e1*Hh + c] = rm1;
      size_t idx = (size_t)d0*Hh + c;   // sibling pair: STORE
      g_nm[idx]  = mv0 + mv1;
      g_nrm[idx] = rm0 + rm1;
    } else {
      g_nm[(size_t)d0*Hh + c]  += mv0;
      g_nrm[(size_t)d0*Hh + c] += rm0;
      g_nm[(size_t)d1*Hh + c]  += mv1;
      g_nrm[(size_t)d1*Hh + c] += rm1;
    }
  }
}

// ---------------------------------------------------------------------------
// Final readout (cp.async double-buffered, 2 CTAs/SM):
// out = relu(Tg[wid[r]] + node_m @ WgB)
// ---------------------------------------------------------------------------
__global__ __launch_bounds__(256,2) void k_final(
    const int* __restrict__ wid, const float* __restrict__ WgB,
    float* __restrict__ out){
  __shared__ float2 As2[2][8][128];
  __shared__ float  Bs [2][16][128];
  int bm = blockIdx.x*128, bn = blockIdx.y*128;
  int tid = threadIdx.x, ty = tid>>4, tx = tid&15;
  float acc[8][8] = {};
  int lr = tid>>1, lk = (tid&1)*8;
  const float* Ar = g_nm + (size_t)(bm+lr)*Hh;
  int kr = tid>>4, nc = (tid&15)*8;

  const int T = (Hh + 15)/16;
  {
    #pragma unroll
    for (int u=0;u<4;u++){
      int gk = lk + 2*u;
      cpa8(sptr(&As2[0][(lk>>1)+u][lr]), Ar + gk, gk < Hh);
    }
    const float* Br = WgB + (size_t)kr*Hh;
    #pragma unroll
    for (int u=0;u<4;u++){
      int gn = bn + nc + 2*u;
      cpa8(sptr(&Bs[0][kr][nc+2*u]), Br + ((gn<Hh)? gn : 0), (kr<Hh) && (gn<Hh));
    }
    CP_COMMIT();
  }
  for (int t=0; t<T; t++){
    int buf = t & 1;
    if (t+1 < T){
      int k0 = (t+1)*16, nb = buf^1;
      #pragma unroll
      for (int u=0;u<4;u++){
        int gk = k0 + lk + 2*u;
        cpa8(sptr(&As2[nb][(lk>>1)+u][lr]), Ar + ((gk<Hh)? gk : 0), gk < Hh);
      }
      int gkB = k0 + kr;
      const float* Br = WgB + (size_t)((gkB<Hh)? gkB : 0)*Hh;
      #pragma unroll
      for (int u=0;u<4;u++){
        int gn = bn + nc + 2*u;
        cpa8(sptr(&Bs[nb][kr][nc+2*u]), Br + ((gn<Hh)? gn : 0),
             (gkB<Hh) && (gn<Hh));
      }
      CP_COMMIT();
      CP_WAIT1();
    } else {
      CP_WAIT0();
    }
    __syncthreads();
    #pragma unroll
    for (int kp=0; kp<8; kp++){
      float2 a2[8];
      #pragma unroll
      for (int i=0;i<8;i+=2){
        float4 t4 = *(const float4*)&As2[buf][kp][ty*8+i];
        a2[i]   = make_float2(t4.x, t4.y);
        a2[i+1] = make_float2(t4.z, t4.w);
      }
      float4 b00 = *(const float4*)&Bs[buf][2*kp  ][tx*8];
      float4 b01 = *(const float4*)&Bs[buf][2*kp  ][tx*8+4];
      float4 b10 = *(const float4*)&Bs[buf][2*kp+1][tx*8];
      float4 b11 = *(const float4*)&Bs[buf][2*kp+1][tx*8+4];
      float b0[8] = {b00.x,b00.y,b00.z,b00.w,b01.x,b01.y,b01.z,b01.w};
      float b1[8] = {b10.x,b10.y,b10.z,b10.w,b11.x,b11.y,b11.z,b11.w};
      #pragma unroll
      for (int i=0;i<8;i++)
        #pragma unroll
        for (int j=0;j<8;j++){
          acc[i][j] = fmaf(a2[i].x, b0[j], acc[i][j]);
          acc[i][j] = fmaf(a2[i].y, b1[j], acc[i][j]);
        }
    }
    __syncthreads();
  }
  #pragma unroll
  for (int i=0;i<8;i++){
    int r = bm + ty*8 + i;
    const float* xg = g_Tg + (size_t)wid[r]*Hh;
    #pragma unroll
    for (int j=0;j<8;j+=2){
      int c = bn + tx*8 + j;
      if (c >= Hh) continue;
      float2 xv = *(const float2*)(xg + c);
      *(float2*)(out + (size_t)r*Hh + c) =
          make_float2(fmaxf(acc[i][j]+xv.x,0.f), fmaxf(acc[i][j+1]+xv.y,0.f));
    }
  }
}

// ---------------------------------------------------------------------------
// kernel_launch
// Inputs: 0 wid, 1 src, 2 dst, 3 rev, 4 sched, 5 emb, 6 Wz, 7 bz,
//         8 Wr, 9 Ur, 10 bur, 11 Wh, 12 bh, 13 Wg, 14 bg
// ---------------------------------------------------------------------------
extern "C" void kernel_launch(void* const* d_in, const int* in_sizes, int n_in,
                              void* d_out, int out_size) {
  const int*   wid   = (const int*)  d_in[0];
  const int*   srcv  = (const int*)  d_in[1];
  const int*   dstv  = (const int*)  d_in[2];
  const int*   revv  = (const int*)  d_in[3];
  const int*   sched = (const int*)  d_in[4];
  const float* emb   = (const float*)d_in[5];
  const float* Wz    = (const float*)d_in[6];
  const float* bz    = (const float*)d_in[7];
  const float* Wr    = (const float*)d_in[8];
  const float* Ur    = (const float*)d_in[9];
  const float* bur   = (const float*)d_in[10];
  const float* Wh    = (const float*)d_in[11];
  const float* bh    = (const float*)d_in[12];
  const float* Wg    = (const float*)d_in[13];
  const float* bg    = (const float*)d_in[14];
  float* out = (float*)d_out;

  const int lmax = in_sizes[4] / 12;   // 8192
  static const int NeTab[12] = {8192,4096,2048,1024,512,256,
                                 256,512,1024,2048,4096,8192};

  // vocab tables (no zero-init needed anywhere)
  dim3 gv((Vv + 63)/64, 4, 4);
  k_vocab4<<<gv, 256>>>(emb, Wz, bz, Wh, bh, Wr, bur, Wg, bg);
  k_tm<<<(Vv*(Hh/2) + 255)/256, 256>>>();
  dim3 gtr((Vv + 63)/64, 8);
  k_vocabTR<<<gtr, 256>>>(Ur);

  // level 0: vocab-table gather + sibling-pair STORE scatter (no edge GEMM)
  k_leaf<<<NeTab[0]/2, 256>>>(sched, srcv, dstv, wid);

  // levels 1..10
  for (int lvl = 1; lvl < 11; lvl++) {
    int Ne  = NeTab[lvl];
    int sub = (lvl >= 6) ? 1 : 0;
    int up  = (lvl <  6) ? 1 : 0;
    const int* sc = sched + lvl*lmax;
    if (Ne >= 2048){
      dim3 gA(Ne/64, 8);
      dim3 gB(Ne/64, 4);
      k_gemmA_m<<<gA, 256>>>(sc, srcv, revv, wid, Wz + Hh*Hh, Wh + Hh*Hh, sub);
      k_gemmB_m<<<gB, 256>>>(sc, dstv, wid, Ur, up);
    } else {
      dim3 g(Ne/32, 15);
      k_gemmA_s<<<g, 256>>>(sc, srcv, revv, wid, Wz + Hh*Hh, Wh + Hh*Hh, sub);
      k_gemmB_s<<<g, 256>>>(sc, dstv, wid, Ur, up);
    }
  }
  // level 11: m_new GEMM writing DIRECTLY into nm[dst] (replaces scat11)
  {
    const int* sc = sched + 11*lmax;
    dim3 gA(NeTab[11]/128, 8);
    k_gemmA_b<<<gA, 256>>>(sc, srcv, revv, dstv, wid,
                           Wz + Hh*Hh, Wh + Hh*Hh, 1, 1);
  }

  // readout
  dim3 gf(NNODE/128, 4);
  k_final<<<gf, 256>>>(wid, Wg + Hh*Hh, out);
}

// round 13
// speedup vs baseline: 1.0467x; 1.0467x over previous
#include <cuda_runtime.h>
#include <cstdint>
#include <math.h>

// Problem constants (B=128 trees, depth D=6, NPT=127)
#define Hh     450
#define NNODE  16256   // 128*127
#define NEDGE  32256   // 2*128*126
#define Vv     780     // vocabulary size

// Scratch (static device globals; allocation-free kernel_launch)
// No zero-init needed — every nm/nrm location is STOREd before any
// accumulate or read (up levels store sibling sums; lvl11 stores leaf nm).
__device__ float g_Tz [Vv*Hh];
__device__ float g_Th [Vv*Hh];
__device__ float g_Tr [Vv*Hh];
__device__ float g_Tg [Vv*Hh];
__device__ float g_Tm [Vv*Hh];     // leaf message table sigmoid(Tz)*tanh(Th)
__device__ float g_TR [Vv*Hh];     // TRu = Tm @ Ur
__device__ float g_m  [NEDGE*Hh];
__device__ float g_rm [NEDGE*Hh];
__device__ float g_nm [NNODE*Hh];
__device__ float g_nrm[NNODE*Hh];

__device__ __forceinline__ float sigmoidf_(float v){ return 1.0f/(1.0f+expf(-v)); }

// 8-byte cp.async with zero-fill when invalid (used by k_final)
__device__ __forceinline__ void cpa8(unsigned int dst, const float* src, bool valid){
  int sz = valid ? 8 : 0;
  asm volatile("cp.async.ca.shared.global [%0], [%1], 8, %2;\n"
               :: "r"(dst), "l"(src), "r"(sz));
}
__device__ __forceinline__ unsigned int sptr(const void* p){
  return (unsigned int)__cvta_generic_to_shared(p);
}
#define CP_COMMIT() asm volatile("cp.async.commit_group;\n" ::)
#define CP_WAIT1()  asm volatile("cp.async.wait_group 1;\n" ::)
#define CP_WAIT0()  asm volatile("cp.async.wait_group 0;\n" ::)

// ---------------------------------------------------------------------------
// Fused vocab-table GEMM: T[z] = emb @ W[z] + bias[z]   (M=780, N=K=450)
// ---------------------------------------------------------------------------
__global__ __launch_bounds__(256) void k_vocab4(
    const float* __restrict__ emb,
    const float* __restrict__ W0, const float* __restrict__ b0,
    const float* __restrict__ W1, const float* __restrict__ b1,
    const float* __restrict__ W2, const float* __restrict__ b2,
    const float* __restrict__ W3, const float* __restrict__ b3){
  __shared__ float As[8][64];
  __shared__ float Bs[8][128];
  int which = blockIdx.z;
  const float* W    = (which==0)?W0:(which==1)?W1:(which==2)?W2:W3;
  const float* bias = (which==0)?b0:(which==1)?b1:(which==2)?b2:b3;
  float* T = (which==0)?g_Tz:(which==1)?g_Th:(which==2)?g_Tr:g_Tg;
  int bm = blockIdx.x*64, bn = blockIdx.y*128;
  int tid = threadIdx.x, ty = tid>>4, tx = tid&15;
  float acc[4][8] = {};
  int lr = tid>>2, lk = (tid&3)*2;
  int rr = bm + lr; if (rr >= Vv) rr = Vv-1;
  const float* Ar = emb + (size_t)rr*Hh;
  int kr = tid>>5, nc = (tid&31)*4;

  for (int k0=0; k0<Hh; k0+=8){
    {
      int gk = k0 + lk;
      float2 v = (gk<Hh)? *(const float2*)(Ar+gk) : make_float2(0.f,0.f);
      As[lk][lr] = v.x; As[lk+1][lr] = v.y;
    }
    {
      int gk = k0 + kr;
      const float* Br = W + (size_t)gk*Hh;
      #pragma unroll
      for (int u=0;u<4;u+=2){
        int gn = bn + nc + u;
        float2 v = (gk<Hh && gn<Hh)? *(const float2*)(Br+gn) : make_float2(0.f,0.f);
        Bs[kr][nc+u] = v.x; Bs[kr][nc+u+1] = v.y;
      }
    }
    __syncthreads();
    #pragma unroll
    for (int kk=0; kk<8; kk++){
      float4 a0 = *(const float4*)&As[kk][ty*4];
      float4 b0v = *(const float4*)&Bs[kk][tx*8];
      float4 b1v = *(const float4*)&Bs[kk][tx*8+4];
      float a[4] = {a0.x,a0.y,a0.z,a0.w};
      float b[8] = {b0v.x,b0v.y,b0v.z,b0v.w,b1v.x,b1v.y,b1v.z,b1v.w};
      #pragma unroll
      for (int i=0;i<4;i++)
        #pragma unroll
        for (int j=0;j<8;j++) acc[i][j] = fmaf(a[i], b[j], acc[i][j]);
    }
    __syncthreads();
  }
  #pragma unroll
  for (int i=0;i<4;i++){
    int r = bm + ty*4 + i;
    if (r >= Vv) continue;
    #pragma unroll
    for (int j=0;j<8;j+=2){
      int c = bn + tx*8 + j;
      if (c >= Hh) continue;
      float2 bv = *(const float2*)(bias + c);
      *(float2*)(T + (size_t)r*Hh + c) =
          make_float2(acc[i][j]+bv.x, acc[i][j+1]+bv.y);
    }
  }
}

// ---------------------------------------------------------------------------
// Tm table: Tm[w] = sigmoid(Tz[w]) * tanh(Th[w])   (pointwise, 780x450)
// ---------------------------------------------------------------------------
__global__ void k_tm(){
  int i2 = blockIdx.x*blockDim.x + threadIdx.x;
  const int N2 = Vv*Hh/2;
  if (i2 < N2){
    float2 a = ((const float2*)g_Tz)[i2];
    float2 b = ((const float2*)g_Th)[i2];
    ((float2*)g_Tm)[i2] = make_float2(sigmoidf_(a.x)*tanhf(b.x),
                                      sigmoidf_(a.y)*tanhf(b.y));
  }
}

// ---------------------------------------------------------------------------
// Vocab TR GEMM: g_TR = g_Tm @ Ur   (M=780, N=K=450)
// 64x64x8 tile, 4x4 microtile -> 104 blocks
// ---------------------------------------------------------------------------
__global__ __launch_bounds__(256) void k_vocabTR(const float* __restrict__ Ur){
  __shared__ float As[8][64];
  __shared__ float Bs[8][64];
  int bm = blockIdx.x*64, bn = blockIdx.y*64;
  int tid = threadIdx.x, ty = tid>>4, tx = tid&15;
  float acc[4][4] = {};
  int lr = tid>>2, lk = (tid&3)*2;
  int rr = bm + lr; if (rr >= Vv) rr = Vv-1;
  const float* Ar = g_Tm + (size_t)rr*Hh;
  int kr = tid>>5, cn = (tid&31)*2;

  for (int k0=0; k0<Hh; k0+=8){
    {
      int gk = k0 + lk;
      float2 v = (gk<Hh)? *(const float2*)(Ar+gk) : make_float2(0.f,0.f);
      As[lk][lr] = v.x; As[lk+1][lr] = v.y;
    }
    {
      int gk = k0 + kr, gn = bn + cn;
      float2 v = (gk<Hh && gn<Hh)? *(const float2*)(Ur + (size_t)gk*Hh + gn)
                                 : make_float2(0.f,0.f);
      Bs[kr][cn] = v.x; Bs[kr][cn+1] = v.y;
    }
    __syncthreads();
    #pragma unroll
    for (int kk=0; kk<8; kk++){
      float4 a0 = *(const float4*)&As[kk][ty*4];
      float4 b0 = *(const float4*)&Bs[kk][tx*4];
      float a[4] = {a0.x,a0.y,a0.z,a0.w};
      float b[4] = {b0.x,b0.y,b0.z,b0.w};
      #pragma unroll
      for (int i=0;i<4;i++)
        #pragma unroll
        for (int j=0;j<4;j++) acc[i][j] = fmaf(a[i], b[j], acc[i][j]);
    }
    __syncthreads();
  }
  #pragma unroll
  for (int i=0;i<4;i++){
    int r = bm + ty*4 + i;
    if (r >= Vv) continue;
    #pragma unroll
    for (int j=0;j<4;j+=2){
      int c = bn + tx*4 + j;
      if (c >= Hh) continue;
      *(float2*)(g_TR + (size_t)r*Hh + c) = make_float2(acc[i][j], acc[i][j+1]);
    }
  }
}

// ---------------------------------------------------------------------------
// Leaf level (lvl0): one block per SIBLING PAIR. STOREs nm/nrm (first write).
// ---------------------------------------------------------------------------
__global__ void k_leaf(const int* __restrict__ sched, const int* __restrict__ srcv,
                       const int* __restrict__ dstv, const int* __restrict__ wid){
  int b  = blockIdx.x;
  int e0 = sched[2*b], e1 = sched[2*b+1];
  int w0 = wid[srcv[e0]], w1 = wid[srcv[e1]];
  int d  = dstv[e0];                // sibling pair shares dst
  int wd = wid[d];
  int c = threadIdx.x*2;
  if (c >= Hh) return;
  float2 tm0 = *(const float2*)(g_Tm + (size_t)w0*Hh + c);
  float2 tm1 = *(const float2*)(g_Tm + (size_t)w1*Hh + c);
  float2 tr0 = *(const float2*)(g_TR + (size_t)w0*Hh + c);
  float2 tr1 = *(const float2*)(g_TR + (size_t)w1*Hh + c);
  float2 xr  = *(const float2*)(g_Tr + (size_t)wd*Hh + c);
  float2 rm0 = make_float2(sigmoidf_(tr0.x+xr.x)*tm0.x, sigmoidf_(tr0.y+xr.y)*tm0.y);
  float2 rm1 = make_float2(sigmoidf_(tr1.x+xr.x)*tm1.x, sigmoidf_(tr1.y+xr.y)*tm1.y);
  *(float2*)(g_m  + (size_t)e0*Hh + c) = tm0;
  *(float2*)(g_m  + (size_t)e1*Hh + c) = tm1;
  *(float2*)(g_rm + (size_t)e0*Hh + c) = rm0;
  *(float2*)(g_rm + (size_t)e1*Hh + c) = rm1;
  size_t idx = (size_t)d*Hh + c;
  *(float2*)(g_nm+idx)  = make_float2(tm0.x+tm1.x, tm0.y+tm1.y);   // STORE
  *(float2*)(g_nrm+idx) = make_float2(rm0.x+rm1.x, rm0.y+rm1.y);   // STORE
}

// ---------------------------------------------------------------------------
// GEMM A big (dual, 128x64x8, 8x4 microtile, reg-prefetch):
//   Z = S@WzB, MT = ARM@WhB ; m_new = (1-z)*s + z*mt
// dstout=0: write g_m[e];  dstout=1 (lvl11): write g_nm[dst[e]] directly
// ---------------------------------------------------------------------------
__global__ __launch_bounds__(256) void k_gemmA_b(
    const int* __restrict__ sched, const int* __restrict__ srcv,
    const int* __restrict__ revv,  const int* __restrict__ dstv,
    const int* __restrict__ wid,
    const float* __restrict__ WzB, const float* __restrict__ WhB,
    int sub, int dstout){
  __shared__ float Ss[8][128], Rs[8][128];
  __shared__ float Bz[8][64],  Bh[8][64];
  __shared__ int s_out[128], s_se[128], s_rv[128], s_w[128];
  int bm = blockIdx.x*128, bn = blockIdx.y*64;
  int tid = threadIdx.x;
  if (tid < 128){
    int e = sched[bm + tid];
    int se = srcv[e];
    s_out[tid] = dstout ? dstv[e] : e;
    s_se[tid] = se; s_rv[tid] = revv[e]; s_w[tid] = wid[se];
  }
  __syncthreads();
  int ty = tid>>4, tx = tid&15;
  float accZ[8][4] = {}, accH[8][4] = {};
  int lr = tid>>1, lk = (tid&1)*4;
  const float* nmr = g_nm  + (size_t)s_se[lr]*Hh;
  const float* nrr = g_nrm + (size_t)s_se[lr]*Hh;
  const float* mr  = g_m   + (size_t)s_rv[lr]*Hh;
  const float* rmr = g_rm  + (size_t)s_rv[lr]*Hh;
  int kr = tid>>5, ncB = (tid&31)*2;

  float2 pm[2], pr[2], pz, ph;
  #pragma unroll
  for (int u=0;u<2;u++){
    int gk = lk + 2*u;
    float2 vm = make_float2(0.f,0.f), vr = make_float2(0.f,0.f);
    if (gk < Hh){
      vm = *(const float2*)(nmr+gk); vr = *(const float2*)(nrr+gk);
      if (sub){
        float2 a = *(const float2*)(mr+gk), b = *(const float2*)(rmr+gk);
        vm.x -= a.x; vm.y -= a.y; vr.x -= b.x; vr.y -= b.y;
      }
    }
    pm[u] = vm; pr[u] = vr;
  }
  {
    int gk = kr, gn = bn + ncB;
    bool ok = (gk<Hh) && (gn<Hh);
    pz = ok? *(const float2*)(WzB + (size_t)gk*Hh + gn) : make_float2(0.f,0.f);
    ph = ok? *(const float2*)(WhB + (size_t)gk*Hh + gn) : make_float2(0.f,0.f);
  }

  for (int k0=0; k0<Hh; k0+=8){
    Ss[lk  ][lr] = pm[0].x; Ss[lk+1][lr] = pm[0].y;
    Ss[lk+2][lr] = pm[1].x; Ss[lk+3][lr] = pm[1].y;
    Rs[lk  ][lr] = pr[0].x; Rs[lk+1][lr] = pr[0].y;
    Rs[lk+2][lr] = pr[1].x; Rs[lk+3][lr] = pr[1].y;
    Bz[kr][ncB] = pz.x; Bz[kr][ncB+1] = pz.y;
    Bh[kr][ncB] = ph.x; Bh[kr][ncB+1] = ph.y;
    __syncthreads();
    int kn = k0 + 8;
    if (kn < Hh){
      #pragma unroll
      for (int u=0;u<2;u++){
        int gk = kn + lk + 2*u;
        float2 vm = make_float2(0.f,0.f), vr = make_float2(0.f,0.f);
        if (gk < Hh){
          vm = *(const float2*)(nmr+gk); vr = *(const float2*)(nrr+gk);
          if (sub){
            float2 a = *(const float2*)(mr+gk), b = *(const float2*)(rmr+gk);
            vm.x -= a.x; vm.y -= a.y; vr.x -= b.x; vr.y -= b.y;
          }
        }
        pm[u] = vm; pr[u] = vr;
      }
      int gk = kn + kr, gn = bn + ncB;
      bool ok = (gk<Hh) && (gn<Hh);
      pz = ok? *(const float2*)(WzB + (size_t)gk*Hh + gn) : make_float2(0.f,0.f);
      ph = ok? *(const float2*)(WhB + (size_t)gk*Hh + gn) : make_float2(0.f,0.f);
    }
    #pragma unroll
    for (int kk=0; kk<8; kk++){
      float4 a0 = *(const float4*)&Ss[kk][ty*8];
      float4 a1 = *(const float4*)&Ss[kk][ty*8+4];
      float4 r0 = *(const float4*)&Rs[kk][ty*8];
      float4 r1 = *(const float4*)&Rs[kk][ty*8+4];
      float4 bz = *(const float4*)&Bz[kk][tx*4];
      float4 bh = *(const float4*)&Bh[kk][tx*4];
      float a[8] = {a0.x,a0.y,a0.z,a0.w,a1.x,a1.y,a1.z,a1.w};
      float w[8] = {r0.x,r0.y,r0.z,r0.w,r1.x,r1.y,r1.z,r1.w};
      float vz[4] = {bz.x,bz.y,bz.z,bz.w};
      float vh[4] = {bh.x,bh.y,bh.z,bh.w};
      #pragma unroll
      for (int i=0;i<8;i++)
        #pragma unroll
        for (int j=0;j<4;j++){
          accZ[i][j] = fmaf(a[i], vz[j], accZ[i][j]);
          accH[i][j] = fmaf(w[i], vh[j], accH[i][j]);
        }
    }
    __syncthreads();
  }
  #pragma unroll
  for (int i=0;i<8;i++){
    int r = ty*8 + i;
    int se = s_se[r], oidx = s_out[r], rv = s_rv[r], w = s_w[r];
    const float* xz = g_Tz + (size_t)w*Hh;
    const float* xh = g_Th + (size_t)w*Hh;
    const float* nm = g_nm + (size_t)se*Hh;
    const float* mrr= g_m  + (size_t)rv*Hh;
    float* mo = (dstout ? g_nm : g_m) + (size_t)oidx*Hh;
    #pragma unroll
    for (int j=0;j<4;j+=2){
      int c = bn + tx*4 + j;
      if (c >= Hh) continue;
      float2 xzv = *(const float2*)(xz+c), xhv = *(const float2*)(xh+c);
      float2 nmv = *(const float2*)(nm+c);
      float2 mv  = sub ? *(const float2*)(mrr+c) : make_float2(0.f,0.f);
      float z0 = sigmoidf_(accZ[i][j]   + xzv.x), mt0 = tanhf(accH[i][j]   + xhv.x);
      float z1 = sigmoidf_(accZ[i][j+1] + xzv.y), mt1 = tanhf(accH[i][j+1] + xhv.y);
      float s0 = nmv.x - mv.x, s1 = nmv.y - mv.y;
      *(float2*)(mo+c) = make_float2((1.f-z0)*s0 + z0*mt0,
                                     (1.f-z1)*s1 + z1*mt1);
    }
  }
}

// ---------------------------------------------------------------------------
// GEMM B mid (64x128x16, 4x8 microtile): for Ne >= 2048
// up=1: STORE nm/nrm (sibling pair) + write g_rm; up=0: accumulate, skip g_rm
// ---------------------------------------------------------------------------
__global__ __launch_bounds__(256) void k_gemmB_m(
    const int* __restrict__ sched, const int* __restrict__ dstv,
    const int* __restrict__ wid, const float* __restrict__ Ur, int up){
  __shared__ float As[16][64];
  __shared__ float Bs[16][128];
  __shared__ int s_eid[64], s_de[64], s_wd[64];
  int bm = blockIdx.x*64, bn = blockIdx.y*128;
  int tid = threadIdx.x;
  if (tid < 64){
    int e = sched[bm + tid];
    int de = dstv[e];
    s_eid[tid] = e; s_de[tid] = de; s_wd[tid] = wid[de];
  }
  __syncthreads();
  int ty = tid>>4, tx = tid&15;
  float acc[4][8] = {};
  int lr = tid>>2, lk = (tid&3)*4;
  const float* Ar = g_m + (size_t)s_eid[lr]*Hh;
  int kr = tid>>4, nc = (tid&15)*8;

  for (int k0=0; k0<Hh; k0+=16){
    #pragma unroll
    for (int u=0;u<2;u++){
      int gk = k0 + lk + 2*u;
      float2 v = (gk<Hh)? *(const float2*)(Ar+gk) : make_float2(0.f,0.f);
      As[lk+2*u][lr] = v.x; As[lk+2*u+1][lr] = v.y;
    }
    {
      int gk = k0 + kr;
      const float* Br = Ur + (size_t)gk*Hh;
      #pragma unroll
      for (int u=0;u<4;u++){
        int gn = bn + nc + 2*u;
        float2 v = (gk<Hh && gn<Hh)? *(const float2*)(Br+gn) : make_float2(0.f,0.f);
        Bs[kr][nc+2*u] = v.x; Bs[kr][nc+2*u+1] = v.y;
      }
    }
    __syncthreads();
    #pragma unroll
    for (int kk=0; kk<16; kk++){
      float4 a0 = *(const float4*)&As[kk][ty*4];
      float4 b0 = *(const float4*)&Bs[kk][tx*8];
      float4 b1 = *(const float4*)&Bs[kk][tx*8+4];
      float a[4] = {a0.x,a0.y,a0.z,a0.w};
      float b[8] = {b0.x,b0.y,b0.z,b0.w,b1.x,b1.y,b1.z,b1.w};
      #pragma unroll
      for (int i=0;i<4;i++)
        #pragma unroll
        for (int j=0;j<8;j++) acc[i][j] = fmaf(a[i], b[j], acc[i][j]);
    }
    __syncthreads();
  }
  #pragma unroll
  for (int q=0;q<4;q++){
    int c = bn + tx*8 + 2*q;
    if (c >= Hh) continue;
    #pragma unroll
    for (int i=0;i<4;i+=2){
      int r0 = ty*4 + i, r1 = r0 + 1;
      int e0 = s_eid[r0], e1 = s_eid[r1];
      int d0 = s_de[r0],  d1 = s_de[r1];
      int w0 = s_wd[r0],  w1 = s_wd[r1];
      float2 mv0 = *(const float2*)(g_m + (size_t)e0*Hh + c);
      float2 mv1 = *(const float2*)(g_m + (size_t)e1*Hh + c);
      float2 x0  = *(const float2*)(g_Tr + (size_t)w0*Hh + c);
      float2 x1  = *(const float2*)(g_Tr + (size_t)w1*Hh + c);
      float2 rm0 = make_float2(sigmoidf_(acc[i][2*q]+x0.x)*mv0.x,
                               sigmoidf_(acc[i][2*q+1]+x0.y)*mv0.y);
      float2 rm1 = make_float2(sigmoidf_(acc[i+1][2*q]+x1.x)*mv1.x,
                               sigmoidf_(acc[i+1][2*q+1]+x1.y)*mv1.y);
      if (up){
        *(float2*)(g_rm + (size_t)e0*Hh + c) = rm0;
        *(float2*)(g_rm + (size_t)e1*Hh + c) = rm1;
        size_t idx = (size_t)d0*Hh + c;               // sibling pair: STORE
        *(float2*)(g_nm+idx)  = make_float2(mv0.x+mv1.x, mv0.y+mv1.y);
        *(float2*)(g_nrm+idx) = make_float2(rm0.x+rm1.x, rm0.y+rm1.y);
      } else {                                        // down: accumulate
        size_t i0 = (size_t)d0*Hh + c, i1 = (size_t)d1*Hh + c;
        float2 a0v = *(float2*)(g_nm+i0), b0v = *(float2*)(g_nrm+i0);
        a0v.x += mv0.x; a0v.y += mv0.y; b0v.x += rm0.x; b0v.y += rm0.y;
        *(float2*)(g_nm+i0) = a0v; *(float2*)(g_nrm+i0) = b0v;
        float2 a1v = *(float2*)(g_nm+i1), b1v = *(float2*)(g_nrm+i1);
        a1v.x += mv1.x; a1v.y += mv1.y; b1v.x += rm1.x; b1v.y += rm1.y;
        *(float2*)(g_nm+i1) = a1v; *(float2*)(g_nrm+i1) = b1v;
      }
    }
  }
}

// ---------------------------------------------------------------------------
// Small-level variants (32x32x16, 2x2 microtile, 256 threads)
// ---------------------------------------------------------------------------
__global__ __launch_bounds__(256) void k_gemmA_s(
    const int* __restrict__ sched, const int* __restrict__ srcv,
    const int* __restrict__ revv,  const int* __restrict__ wid,
    const float* __restrict__ WzB, const float* __restrict__ WhB, int sub){
  __shared__ float Ss[16][32], Rs[16][32], Bz[16][32], Bh[16][32];
  __shared__ int s_eid[32], s_se[32], s_rv[32], s_w[32];
  int bm = blockIdx.x*32, bn = blockIdx.y*32;
  int tid = threadIdx.x;
  if (tid < 32){
    int e = sched[bm + tid];
    int se = srcv[e];
    s_eid[tid] = e; s_se[tid] = se; s_rv[tid] = revv[e]; s_w[tid] = wid[se];
  }
  __syncthreads();
  int ty = tid>>4, tx = tid&15;
  float accZ[2][2] = {}, accH[2][2] = {};
  int lr = tid>>3, lk = (tid&7)*2;
  const float* nmr = g_nm  + (size_t)s_se[lr]*Hh;
  const float* nrr = g_nrm + (size_t)s_se[lr]*Hh;
  const float* mr  = g_m   + (size_t)s_rv[lr]*Hh;
  const float* rmr = g_rm  + (size_t)s_rv[lr]*Hh;
  int kr = tid>>4, cn = (tid&15)*2;

  for (int k0=0; k0<Hh; k0+=16){
    {
      int gk = k0 + lk;
      float2 vm = make_float2(0.f,0.f), vr = make_float2(0.f,0.f);
      if (gk < Hh){
        vm = *(const float2*)(nmr+gk); vr = *(const float2*)(nrr+gk);
        if (sub){
          float2 a = *(const float2*)(mr+gk), b = *(const float2*)(rmr+gk);
          vm.x -= a.x; vm.y -= a.y; vr.x -= b.x; vr.y -= b.y;
        }
      }
      Ss[lk][lr] = vm.x; Ss[lk+1][lr] = vm.y;
      Rs[lk][lr] = vr.x; Rs[lk+1][lr] = vr.y;
    }
    {
      int gk = k0 + kr, gn = bn + cn;
      bool ok = (gk<Hh) && (gn<Hh);
      float2 vz = ok? *(const float2*)(WzB + (size_t)gk*Hh + gn) : make_float2(0.f,0.f);
      float2 vh = ok? *(const float2*)(WhB + (size_t)gk*Hh + gn) : make_float2(0.f,0.f);
      Bz[kr][cn] = vz.x; Bz[kr][cn+1] = vz.y;
      Bh[kr][cn] = vh.x; Bh[kr][cn+1] = vh.y;
    }
    __syncthreads();
    #pragma unroll
    for (int kk=0; kk<16; kk++){
      float a0=Ss[kk][ty*2], a1=Ss[kk][ty*2+1];
      float w0=Rs[kk][ty*2], w1=Rs[kk][ty*2+1];
      float z0=Bz[kk][tx*2], z1=Bz[kk][tx*2+1];
      float h0=Bh[kk][tx*2], h1=Bh[kk][tx*2+1];
      accZ[0][0]=fmaf(a0,z0,accZ[0][0]); accZ[0][1]=fmaf(a0,z1,accZ[0][1]);
      accZ[1][0]=fmaf(a1,z0,accZ[1][0]); accZ[1][1]=fmaf(a1,z1,accZ[1][1]);
      accH[0][0]=fmaf(w0,h0,accH[0][0]); accH[0][1]=fmaf(w0,h1,accH[0][1]);
      accH[1][0]=fmaf(w1,h0,accH[1][0]); accH[1][1]=fmaf(w1,h1,accH[1][1]);
    }
    __syncthreads();
  }
  #pragma unroll
  for (int i=0;i<2;i++){
    int r = ty*2 + i;
    int se = s_se[r], e = s_eid[r], rv = s_rv[r], w = s_w[r];
    #pragma unroll
    for (int j=0;j<2;j++){
      int c = bn + tx*2 + j;
      if (c >= Hh) continue;
      float z  = sigmoidf_(accZ[i][j] + g_Tz[(size_t)w*Hh + c]);
      float mt = tanhf   (accH[i][j] + g_Th[(size_t)w*Hh + c]);
      float s  = g_nm[(size_t)se*Hh + c] - (sub ? g_m[(size_t)rv*Hh + c] : 0.f);
      g_m[(size_t)e*Hh + c] = (1.f - z)*s + z*mt;
    }
  }
}

__global__ __launch_bounds__(256) void k_gemmB_s(
    const int* __restrict__ sched, const int* __restrict__ dstv,
    const int* __restrict__ wid, const float* __restrict__ Ur, int up){
  __shared__ float As[16][32], Bs[16][32];
  __shared__ int s_eid[32], s_de[32], s_wd[32];
  int bm = blockIdx.x*32, bn = blockIdx.y*32;
  int tid = threadIdx.x;
  if (tid < 32){
    int e = sched[bm + tid];
    int de = dstv[e];
    s_eid[tid] = e; s_de[tid] = de; s_wd[tid] = wid[de];
  }
  __syncthreads();
  int ty = tid>>4, tx = tid&15;
  float acc[2][2] = {};
  int lr = tid>>3, lk = (tid&7)*2;
  const float* Ar = g_m + (size_t)s_eid[lr]*Hh;
  int kr = tid>>4, cn = (tid&15)*2;

  for (int k0=0; k0<Hh; k0+=16){
    {
      int gk = k0 + lk;
      float2 v = (gk<Hh)? *(const float2*)(Ar+gk) : make_float2(0.f,0.f);
      As[lk][lr] = v.x; As[lk+1][lr] = v.y;
    }
    {
      int gk = k0 + kr, gn = bn + cn;
      float2 v = ((gk<Hh)&&(gn<Hh))? *(const float2*)(Ur + (size_t)gk*Hh + gn)
                                   : make_float2(0.f,0.f);
      Bs[kr][cn] = v.x; Bs[kr][cn+1] = v.y;
    }
    __syncthreads();
    #pragma unroll
    for (int kk=0; kk<16; kk++){
      float a0=As[kk][ty*2], a1=As[kk][ty*2+1];
      float b0=Bs[kk][tx*2], b1=Bs[kk][tx*2+1];
      acc[0][0]=fmaf(a0,b0,acc[0][0]); acc[0][1]=fmaf(a0,b1,acc[0][1]);
      acc[1][0]=fmaf(a1,b0,acc[1][0]); acc[1][1]=fmaf(a1,b1,acc[1][1]);
    }
    __syncthreads();
  }
  int r0 = ty*2, r1 = ty*2+1;
  int e0 = s_eid[r0], e1 = s_eid[r1];
  int d0 = s_de[r0],  d1 = s_de[r1];
  int w0 = s_wd[r0],  w1 = s_wd[r1];
  #pragma unroll
  for (int j=0;j<2;j++){
    int c = bn + tx*2 + j;
    if (c >= Hh) continue;
    float mv0 = g_m[(size_t)e0*Hh + c];
    float mv1 = g_m[(size_t)e1*Hh + c];
    float rm0 = sigmoidf_(acc[0][j] + g_Tr[(size_t)w0*Hh + c]) * mv0;
    float rm1 = sigmoidf_(acc[1][j] + g_Tr[(size_t)w1*Hh + c]) * mv1;
    if (up){
      g_rm[(size_t)e0*Hh + c] = rm0;
      g_rm[(size_t)e1*Hh + c] = rm1;
      size_t idx = (size_t)d0*Hh + c;   // sibling pair: STORE
      g_nm[idx]  = mv0 + mv1;
      g_nrm[idx] = rm0 + rm1;
    } else {
      g_nm[(size_t)d0*Hh + c]  += mv0;
      g_nrm[(size_t)d0*Hh + c] += rm0;
      g_nm[(size_t)d1*Hh + c]  += mv1;
      g_nrm[(size_t)d1*Hh + c] += rm1;
    }
  }
}

// ---------------------------------------------------------------------------
// Final readout (cp.async double-buffered, 2 CTAs/SM):
// out = relu(Tg[wid[r]] + node_m @ WgB)
// ---------------------------------------------------------------------------
__global__ __launch_bounds__(256,2) void k_final(
    const int* __restrict__ wid, const float* __restrict__ WgB,
    float* __restrict__ out){
  __shared__ float2 As2[2][8][128];
  __shared__ float  Bs [2][16][128];
  int bm = blockIdx.x*128, bn = blockIdx.y*128;
  int tid = threadIdx.x, ty = tid>>4, tx = tid&15;
  float acc[8][8] = {};
  int lr = tid>>1, lk = (tid&1)*8;
  const float* Ar = g_nm + (size_t)(bm+lr)*Hh;
  int kr = tid>>4, nc = (tid&15)*8;

  const int T = (Hh + 15)/16;
  {
    #pragma unroll
    for (int u=0;u<4;u++){
      int gk = lk + 2*u;
      cpa8(sptr(&As2[0][(lk>>1)+u][lr]), Ar + gk, gk < Hh);
    }
    const float* Br = WgB + (size_t)kr*Hh;
    #pragma unroll
    for (int u=0;u<4;u++){
      int gn = bn + nc + 2*u;
      cpa8(sptr(&Bs[0][kr][nc+2*u]), Br + ((gn<Hh)? gn : 0), (kr<Hh) && (gn<Hh));
    }
    CP_COMMIT();
  }
  for (int t=0; t<T; t++){
    int buf = t & 1;
    if (t+1 < T){
      int k0 = (t+1)*16, nb = buf^1;
      #pragma unroll
      for (int u=0;u<4;u++){
        int gk = k0 + lk + 2*u;
        cpa8(sptr(&As2[nb][(lk>>1)+u][lr]), Ar + ((gk<Hh)? gk : 0), gk < Hh);
      }
      int gkB = k0 + kr;
      const float* Br = WgB + (size_t)((gkB<Hh)? gkB : 0)*Hh;
      #pragma unroll
      for (int u=0;u<4;u++){
        int gn = bn + nc + 2*u;
        cpa8(sptr(&Bs[nb][kr][nc+2*u]), Br + ((gn<Hh)? gn : 0),
             (gkB<Hh) && (gn<Hh));
      }
      CP_COMMIT();
      CP_WAIT1();
    } else {
      CP_WAIT0();
    }
    __syncthreads();
    #pragma unroll
    for (int kp=0; kp<8; kp++){
      float2 a2[8];
      #pragma unroll
      for (int i=0;i<8;i+=2){
        float4 t4 = *(const float4*)&As2[buf][kp][ty*8+i];
        a2[i]   = make_float2(t4.x, t4.y);
        a2[i+1] = make_float2(t4.z, t4.w);
      }
      float4 b00 = *(const float4*)&Bs[buf][2*kp  ][tx*8];
      float4 b01 = *(const float4*)&Bs[buf][2*kp  ][tx*8+4];
      float4 b10 = *(const float4*)&Bs[buf][2*kp+1][tx*8];
      float4 b11 = *(const float4*)&Bs[buf][2*kp+1][tx*8+4];
      float b0[8] = {b00.x,b00.y,b00.z,b00.w,b01.x,b01.y,b01.z,b01.w};
      float b1[8] = {b10.x,b10.y,b10.z,b10.w,b11.x,b11.y,b11.z,b11.w};
      #pragma unroll
      for (int i=0;i<8;i++)
        #pragma unroll
        for (int j=0;j<8;j++){
          acc[i][j] = fmaf(a2[i].x, b0[j], acc[i][j]);
          acc[i][j] = fmaf(a2[i].y, b1[j], acc[i][j]);
        }
    }
    __syncthreads();
  }
  #pragma unroll
  for (int i=0;i<8;i++){
    int r = bm + ty*8 + i;
    const float* xg = g_Tg + (size_t)wid[r]*Hh;
    #pragma unroll
    for (int j=0;j<8;j+=2){
      int c = bn + tx*8 + j;
      if (c >= Hh) continue;
      float2 xv = *(const float2*)(xg + c);
      *(float2*)(out + (size_t)r*Hh + c) =
          make_float2(fmaxf(acc[i][j]+xv.x,0.f), fmaxf(acc[i][j+1]+xv.y,0.f));
    }
  }
}

// ---------------------------------------------------------------------------
// kernel_launch
// Inputs: 0 wid, 1 src, 2 dst, 3 rev, 4 sched, 5 emb, 6 Wz, 7 bz,
//         8 Wr, 9 Ur, 10 bur, 11 Wh, 12 bh, 13 Wg, 14 bg
// ---------------------------------------------------------------------------
extern "C" void kernel_launch(void* const* d_in, const int* in_sizes, int n_in,
                              void* d_out, int out_size) {
  const int*   wid   = (const int*)  d_in[0];
  const int*   srcv  = (const int*)  d_in[1];
  const int*   dstv  = (const int*)  d_in[2];
  const int*   revv  = (const int*)  d_in[3];
  const int*   sched = (const int*)  d_in[4];
  const float* emb   = (const float*)d_in[5];
  const float* Wz    = (const float*)d_in[6];
  const float* bz    = (const float*)d_in[7];
  const float* Wr    = (const float*)d_in[8];
  const float* Ur    = (const float*)d_in[9];
  const float* bur   = (const float*)d_in[10];
  const float* Wh    = (const float*)d_in[11];
  const float* bh    = (const float*)d_in[12];
  const float* Wg    = (const float*)d_in[13];
  const float* bg    = (const float*)d_in[14];
  float* out = (float*)d_out;

  const int lmax = in_sizes[4] / 12;   // 8192
  static const int NeTab[12] = {8192,4096,2048,1024,512,256,
                                 256,512,1024,2048,4096,8192};

  // vocab tables (no zero-init needed anywhere)
  dim3 gv((Vv + 63)/64, 4, 4);
  k_vocab4<<<gv, 256>>>(emb, Wz, bz, Wh, bh, Wr, bur, Wg, bg);
  k_tm<<<(Vv*(Hh/2) + 255)/256, 256>>>();
  dim3 gtr((Vv + 63)/64, 8);
  k_vocabTR<<<gtr, 256>>>(Ur);

  // level 0: vocab-table gather + sibling-pair STORE scatter (no edge GEMM)
  k_leaf<<<NeTab[0]/2, 256>>>(sched, srcv, dstv, wid);

  // levels 1..10
  for (int lvl = 1; lvl < 11; lvl++) {
    int Ne  = NeTab[lvl];
    int sub = (lvl >= 6) ? 1 : 0;
    int up  = (lvl <  6) ? 1 : 0;
    const int* sc = sched + lvl*lmax;
    if (Ne >= 2048){
      dim3 gA(Ne/128, 8);
      dim3 gB(Ne/64, 4);
      k_gemmA_b<<<gA, 256>>>(sc, srcv, revv, dstv, wid,
                             Wz + Hh*Hh, Wh + Hh*Hh, sub, 0);
      k_gemmB_m<<<gB, 256>>>(sc, dstv, wid, Ur, up);
    } else {
      dim3 g(Ne/32, 15);
      k_gemmA_s<<<g, 256>>>(sc, srcv, revv, wid, Wz + Hh*Hh, Wh + Hh*Hh, sub);
      k_gemmB_s<<<g, 256>>>(sc, dstv, wid, Ur, up);
    }
  }
  // level 11: m_new GEMM writing DIRECTLY into nm[dst] (replaces scat11)
  {
    const int* sc = sched + 11*lmax;
    dim3 gA(NeTab[11]/128, 8);
    k_gemmA_b<<<gA, 256>>>(sc, srcv, revv, dstv, wid,
                           Wz + Hh*Hh, Wh + Hh*Hh, 1, 1);
  }

  // readout
  dim3 gf(NNODE/128, 4);
  k_final<<<gf, 256>>>(wid, Wg + Hh*Hh, out);
}

// round 14
// speedup vs baseline: 1.0669x; 1.0193x over previous
#include <cuda_runtime.h>
#include <cstdint>
#include <math.h>

// Problem constants (B=128 trees, depth D=6, NPT=127)
#define Hh     450
#define NNODE  16256   // 128*127
#define NEDGE  32256   // 2*128*126
#define Vv     780     // vocabulary size

// Scratch (static device globals; allocation-free kernel_launch)
// No zero-init needed — every nm/nrm location is STOREd before any
// accumulate or read (up levels store sibling sums; lvl11 stores leaf nm).
__device__ float g_Tz [Vv*Hh];
__device__ float g_Th [Vv*Hh];
__device__ float g_Tr [Vv*Hh];
__device__ float g_Tg [Vv*Hh];
__device__ float g_Tm [Vv*Hh];     // leaf message table sigmoid(Tz)*tanh(Th)
__device__ float g_TR [Vv*Hh];     // TRu = Tm @ Ur
__device__ float g_m  [NEDGE*Hh];
__device__ float g_rm [NEDGE*Hh];
__device__ float g_nm [NNODE*Hh];
__device__ float g_nrm[NNODE*Hh];

__device__ __forceinline__ float sigmoidf_(float v){ return 1.0f/(1.0f+expf(-v)); }

// 8-byte cp.async with zero-fill when invalid (used by k_final)
__device__ __forceinline__ void cpa8(unsigned int dst, const float* src, bool valid){
  int sz = valid ? 8 : 0;
  asm volatile("cp.async.ca.shared.global [%0], [%1], 8, %2;\n"
               :: "r"(dst), "l"(src), "r"(sz));
}
__device__ __forceinline__ unsigned int sptr(const void* p){
  return (unsigned int)__cvta_generic_to_shared(p);
}
#define CP_COMMIT() asm volatile("cp.async.commit_group;\n" ::)
#define CP_WAIT1()  asm volatile("cp.async.wait_group 1;\n" ::)
#define CP_WAIT0()  asm volatile("cp.async.wait_group 0;\n" ::)

// ---------------------------------------------------------------------------
// Fused vocab-table GEMM: T[z] = emb @ W[z] + bias[z]   (M=780, N=K=450)
// ---------------------------------------------------------------------------
__global__ __launch_bounds__(256) void k_vocab4(
    const float* __restrict__ emb,
    const float* __restrict__ W0, const float* __restrict__ b0,
    const float* __restrict__ W1, const float* __restrict__ b1,
    const float* __restrict__ W2, const float* __restrict__ b2,
    const float* __restrict__ W3, const float* __restrict__ b3){
  __shared__ float As[8][64];
  __shared__ float Bs[8][128];
  int which = blockIdx.z;
  const float* W    = (which==0)?W0:(which==1)?W1:(which==2)?W2:W3;
  const float* bias = (which==0)?b0:(which==1)?b1:(which==2)?b2:b3;
  float* T = (which==0)?g_Tz:(which==1)?g_Th:(which==2)?g_Tr:g_Tg;
  int bm = blockIdx.x*64, bn = blockIdx.y*128;
  int tid = threadIdx.x, ty = tid>>4, tx = tid&15;
  float acc[4][8] = {};
  int lr = tid>>2, lk = (tid&3)*2;
  int rr = bm + lr; if (rr >= Vv) rr = Vv-1;
  const float* Ar = emb + (size_t)rr*Hh;
  int kr = tid>>5, nc = (tid&31)*4;

  for (int k0=0; k0<Hh; k0+=8){
    {
      int gk = k0 + lk;
      float2 v = (gk<Hh)? *(const float2*)(Ar+gk) : make_float2(0.f,0.f);
      As[lk][lr] = v.x; As[lk+1][lr] = v.y;
    }
    {
      int gk = k0 + kr;
      const float* Br = W + (size_t)gk*Hh;
      #pragma unroll
      for (int u=0;u<4;u+=2){
        int gn = bn + nc + u;
        float2 v = (gk<Hh && gn<Hh)? *(const float2*)(Br+gn) : make_float2(0.f,0.f);
        Bs[kr][nc+u] = v.x; Bs[kr][nc+u+1] = v.y;
      }
    }
    __syncthreads();
    #pragma unroll
    for (int kk=0; kk<8; kk++){
      float4 a0 = *(const float4*)&As[kk][ty*4];
      float4 b0v = *(const float4*)&Bs[kk][tx*8];
      float4 b1v = *(const float4*)&Bs[kk][tx*8+4];
      float a[4] = {a0.x,a0.y,a0.z,a0.w};
      float b[8] = {b0v.x,b0v.y,b0v.z,b0v.w,b1v.x,b1v.y,b1v.z,b1v.w};
      #pragma unroll
      for (int i=0;i<4;i++)
        #pragma unroll
        for (int j=0;j<8;j++) acc[i][j] = fmaf(a[i], b[j], acc[i][j]);
    }
    __syncthreads();
  }
  #pragma unroll
  for (int i=0;i<4;i++){
    int r = bm + ty*4 + i;
    if (r >= Vv) continue;
    #pragma unroll
    for (int j=0;j<8;j+=2){
      int c = bn + tx*8 + j;
      if (c >= Hh) continue;
      float2 bv = *(const float2*)(bias + c);
      *(float2*)(T + (size_t)r*Hh + c) =
          make_float2(acc[i][j]+bv.x, acc[i][j+1]+bv.y);
    }
  }
}

// ---------------------------------------------------------------------------
// Tm table: Tm[w] = sigmoid(Tz[w]) * tanh(Th[w])   (pointwise, 780x450)
// ---------------------------------------------------------------------------
__global__ void k_tm(){
  int i2 = blockIdx.x*blockDim.x + threadIdx.x;
  const int N2 = Vv*Hh/2;
  if (i2 < N2){
    float2 a = ((const float2*)g_Tz)[i2];
    float2 b = ((const float2*)g_Th)[i2];
    ((float2*)g_Tm)[i2] = make_float2(sigmoidf_(a.x)*tanhf(b.x),
                                      sigmoidf_(a.y)*tanhf(b.y));
  }
}

// ---------------------------------------------------------------------------
// Vocab TR GEMM: g_TR = g_Tm @ Ur   (M=780, N=K=450)
// 64x64x8 tile, 4x4 microtile -> 104 blocks
// ---------------------------------------------------------------------------
__global__ __launch_bounds__(256) void k_vocabTR(const float* __restrict__ Ur){
  __shared__ float As[8][64];
  __shared__ float Bs[8][64];
  int bm = blockIdx.x*64, bn = blockIdx.y*64;
  int tid = threadIdx.x, ty = tid>>4, tx = tid&15;
  float acc[4][4] = {};
  int lr = tid>>2, lk = (tid&3)*2;
  int rr = bm + lr; if (rr >= Vv) rr = Vv-1;
  const float* Ar = g_Tm + (size_t)rr*Hh;
  int kr = tid>>5, cn = (tid&31)*2;

  for (int k0=0; k0<Hh; k0+=8){
    {
      int gk = k0 + lk;
      float2 v = (gk<Hh)? *(const float2*)(Ar+gk) : make_float2(0.f,0.f);
      As[lk][lr] = v.x; As[lk+1][lr] = v.y;
    }
    {
      int gk = k0 + kr, gn = bn + cn;
      float2 v = (gk<Hh && gn<Hh)? *(const float2*)(Ur + (size_t)gk*Hh + gn)
                                 : make_float2(0.f,0.f);
      Bs[kr][cn] = v.x; Bs[kr][cn+1] = v.y;
    }
    __syncthreads();
    #pragma unroll
    for (int kk=0; kk<8; kk++){
      float4 a0 = *(const float4*)&As[kk][ty*4];
      float4 b0 = *(const float4*)&Bs[kk][tx*4];
      float a[4] = {a0.x,a0.y,a0.z,a0.w};
      float b[4] = {b0.x,b0.y,b0.z,b0.w};
      #pragma unroll
      for (int i=0;i<4;i++)
        #pragma unroll
        for (int j=0;j<4;j++) acc[i][j] = fmaf(a[i], b[j], acc[i][j]);
    }
    __syncthreads();
  }
  #pragma unroll
  for (int i=0;i<4;i++){
    int r = bm + ty*4 + i;
    if (r >= Vv) continue;
    #pragma unroll
    for (int j=0;j<4;j+=2){
      int c = bn + tx*4 + j;
      if (c >= Hh) continue;
      *(float2*)(g_TR + (size_t)r*Hh + c) = make_float2(acc[i][j], acc[i][j+1]);
    }
  }
}

// ---------------------------------------------------------------------------
// Leaf level (lvl0): one block per SIBLING PAIR. STOREs nm/nrm (first write).
// ---------------------------------------------------------------------------
__global__ void k_leaf(const int* __restrict__ sched, const int* __restrict__ srcv,
                       const int* __restrict__ dstv, const int* __restrict__ wid){
  int b  = blockIdx.x;
  int e0 = sched[2*b], e1 = sched[2*b+1];
  int w0 = wid[srcv[e0]], w1 = wid[srcv[e1]];
  int d  = dstv[e0];                // sibling pair shares dst
  int wd = wid[d];
  int c = threadIdx.x*2;
  if (c >= Hh) return;
  float2 tm0 = *(const float2*)(g_Tm + (size_t)w0*Hh + c);
  float2 tm1 = *(const float2*)(g_Tm + (size_t)w1*Hh + c);
  float2 tr0 = *(const float2*)(g_TR + (size_t)w0*Hh + c);
  float2 tr1 = *(const float2*)(g_TR + (size_t)w1*Hh + c);
  float2 xr  = *(const float2*)(g_Tr + (size_t)wd*Hh + c);
  float2 rm0 = make_float2(sigmoidf_(tr0.x+xr.x)*tm0.x, sigmoidf_(tr0.y+xr.y)*tm0.y);
  float2 rm1 = make_float2(sigmoidf_(tr1.x+xr.x)*tm1.x, sigmoidf_(tr1.y+xr.y)*tm1.y);
  *(float2*)(g_m  + (size_t)e0*Hh + c) = tm0;
  *(float2*)(g_m  + (size_t)e1*Hh + c) = tm1;
  *(float2*)(g_rm + (size_t)e0*Hh + c) = rm0;
  *(float2*)(g_rm + (size_t)e1*Hh + c) = rm1;
  size_t idx = (size_t)d*Hh + c;
  *(float2*)(g_nm+idx)  = make_float2(tm0.x+tm1.x, tm0.y+tm1.y);   // STORE
  *(float2*)(g_nrm+idx) = make_float2(rm0.x+rm1.x, rm0.y+rm1.y);   // STORE
}

// ---------------------------------------------------------------------------
// GEMM A big (dual, 128x64x8, 8x4 microtile, reg-prefetch):
//   Z = S@WzB, MT = ARM@WhB ; m_new = (1-z)*s + z*mt
// dstout=0: write g_m[e];  dstout=1 (lvl11): write g_nm[dst[e]] directly
// ---------------------------------------------------------------------------
__global__ __launch_bounds__(256) void k_gemmA_b(
    const int* __restrict__ sched, const int* __restrict__ srcv,
    const int* __restrict__ revv,  const int* __restrict__ dstv,
    const int* __restrict__ wid,
    const float* __restrict__ WzB, const float* __restrict__ WhB,
    int sub, int dstout){
  __shared__ float Ss[8][128], Rs[8][128];
  __shared__ float Bz[8][64],  Bh[8][64];
  __shared__ int s_out[128], s_se[128], s_rv[128], s_w[128];
  int bm = blockIdx.x*128, bn = blockIdx.y*64;
  int tid = threadIdx.x;
  if (tid < 128){
    int e = sched[bm + tid];
    int se = srcv[e];
    s_out[tid] = dstout ? dstv[e] : e;
    s_se[tid] = se; s_rv[tid] = revv[e]; s_w[tid] = wid[se];
  }
  __syncthreads();
  int ty = tid>>4, tx = tid&15;
  float accZ[8][4] = {}, accH[8][4] = {};
  int lr = tid>>1, lk = (tid&1)*4;
  const float* nmr = g_nm  + (size_t)s_se[lr]*Hh;
  const float* nrr = g_nrm + (size_t)s_se[lr]*Hh;
  const float* mr  = g_m   + (size_t)s_rv[lr]*Hh;
  const float* rmr = g_rm  + (size_t)s_rv[lr]*Hh;
  int kr = tid>>5, ncB = (tid&31)*2;

  float2 pm[2], pr[2], pz, ph;
  #pragma unroll
  for (int u=0;u<2;u++){
    int gk = lk + 2*u;
    float2 vm = make_float2(0.f,0.f), vr = make_float2(0.f,0.f);
    if (gk < Hh){
      vm = *(const float2*)(nmr+gk); vr = *(const float2*)(nrr+gk);
      if (sub){
        float2 a = *(const float2*)(mr+gk), b = *(const float2*)(rmr+gk);
        vm.x -= a.x; vm.y -= a.y; vr.x -= b.x; vr.y -= b.y;
      }
    }
    pm[u] = vm; pr[u] = vr;
  }
  {
    int gk = kr, gn = bn + ncB;
    bool ok = (gk<Hh) && (gn<Hh);
    pz = ok? *(const float2*)(WzB + (size_t)gk*Hh + gn) : make_float2(0.f,0.f);
    ph = ok? *(const float2*)(WhB + (size_t)gk*Hh + gn) : make_float2(0.f,0.f);
  }

  for (int k0=0; k0<Hh; k0+=8){
    Ss[lk  ][lr] = pm[0].x; Ss[lk+1][lr] = pm[0].y;
    Ss[lk+2][lr] = pm[1].x; Ss[lk+3][lr] = pm[1].y;
    Rs[lk  ][lr] = pr[0].x; Rs[lk+1][lr] = pr[0].y;
    Rs[lk+2][lr] = pr[1].x; Rs[lk+3][lr] = pr[1].y;
    Bz[kr][ncB] = pz.x; Bz[kr][ncB+1] = pz.y;
    Bh[kr][ncB] = ph.x; Bh[kr][ncB+1] = ph.y;
    __syncthreads();
    int kn = k0 + 8;
    if (kn < Hh){
      #pragma unroll
      for (int u=0;u<2;u++){
        int gk = kn + lk + 2*u;
        float2 vm = make_float2(0.f,0.f), vr = make_float2(0.f,0.f);
        if (gk < Hh){
          vm = *(const float2*)(nmr+gk); vr = *(const float2*)(nrr+gk);
          if (sub){
            float2 a = *(const float2*)(mr+gk), b = *(const float2*)(rmr+gk);
            vm.x -= a.x; vm.y -= a.y; vr.x -= b.x; vr.y -= b.y;
          }
        }
        pm[u] = vm; pr[u] = vr;
      }
      int gk = kn + kr, gn = bn + ncB;
      bool ok = (gk<Hh) && (gn<Hh);
      pz = ok? *(const float2*)(WzB + (size_t)gk*Hh + gn) : make_float2(0.f,0.f);
      ph = ok? *(const float2*)(WhB + (size_t)gk*Hh + gn) : make_float2(0.f,0.f);
    }
    #pragma unroll
    for (int kk=0; kk<8; kk++){
      float4 a0 = *(const float4*)&Ss[kk][ty*8];
      float4 a1 = *(const float4*)&Ss[kk][ty*8+4];
      float4 r0 = *(const float4*)&Rs[kk][ty*8];
      float4 r1 = *(const float4*)&Rs[kk][ty*8+4];
      float4 bz = *(const float4*)&Bz[kk][tx*4];
      float4 bh = *(const float4*)&Bh[kk][tx*4];
      float a[8] = {a0.x,a0.y,a0.z,a0.w,a1.x,a1.y,a1.z,a1.w};
      float w[8] = {r0.x,r0.y,r0.z,r0.w,r1.x,r1.y,r1.z,r1.w};
      float vz[4] = {bz.x,bz.y,bz.z,bz.w};
      float vh[4] = {bh.x,bh.y,bh.z,bh.w};
      #pragma unroll
      for (int i=0;i<8;i++)
        #pragma unroll
        for (int j=0;j<4;j++){
          accZ[i][j] = fmaf(a[i], vz[j], accZ[i][j]);
          accH[i][j] = fmaf(w[i], vh[j], accH[i][j]);
        }
    }
    __syncthreads();
  }
  #pragma unroll
  for (int i=0;i<8;i++){
    int r = ty*8 + i;
    int se = s_se[r], oidx = s_out[r], rv = s_rv[r], w = s_w[r];
    const float* xz = g_Tz + (size_t)w*Hh;
    const float* xh = g_Th + (size_t)w*Hh;
    const float* nm = g_nm + (size_t)se*Hh;
    const float* mrr= g_m  + (size_t)rv*Hh;
    float* mo = (dstout ? g_nm : g_m) + (size_t)oidx*Hh;
    #pragma unroll
    for (int j=0;j<4;j+=2){
      int c = bn + tx*4 + j;
      if (c >= Hh) continue;
      float2 xzv = *(const float2*)(xz+c), xhv = *(const float2*)(xh+c);
      float2 nmv = *(const float2*)(nm+c);
      float2 mv  = sub ? *(const float2*)(mrr+c) : make_float2(0.f,0.f);
      float z0 = sigmoidf_(accZ[i][j]   + xzv.x), mt0 = tanhf(accH[i][j]   + xhv.x);
      float z1 = sigmoidf_(accZ[i][j+1] + xzv.y), mt1 = tanhf(accH[i][j+1] + xhv.y);
      float s0 = nmv.x - mv.x, s1 = nmv.y - mv.y;
      *(float2*)(mo+c) = make_float2((1.f-z0)*s0 + z0*mt0,
                                     (1.f-z1)*s1 + z1*mt1);
    }
  }
}

// ---------------------------------------------------------------------------
// GEMM A mid (dual, 64x64x16, 4x4 microtile): for Ne == 2048 only
// (256 blocks vs 128 — fills the chip where gemmA_b leaves half idle)
// ---------------------------------------------------------------------------
__global__ __launch_bounds__(256) void k_gemmA_m(
    const int* __restrict__ sched, const int* __restrict__ srcv,
    const int* __restrict__ revv,  const int* __restrict__ wid,
    const float* __restrict__ WzB, const float* __restrict__ WhB, int sub){
  __shared__ float Ss[16][64], Rs[16][64];
  __shared__ float Bz[16][64], Bh[16][64];
  __shared__ int s_eid[64], s_se[64], s_rv[64], s_w[64];
  int bm = blockIdx.x*64, bn = blockIdx.y*64;
  int tid = threadIdx.x;
  if (tid < 64){
    int e = sched[bm + tid];
    int se = srcv[e];
    s_eid[tid] = e; s_se[tid] = se; s_rv[tid] = revv[e]; s_w[tid] = wid[se];
  }
  __syncthreads();
  int ty = tid>>4, tx = tid&15;
  float accZ[4][4] = {}, accH[4][4] = {};
  int lr = tid>>2, lk = (tid&3)*4;
  const float* nmr = g_nm  + (size_t)s_se[lr]*Hh;
  const float* nrr = g_nrm + (size_t)s_se[lr]*Hh;
  const float* mr  = g_m   + (size_t)s_rv[lr]*Hh;
  const float* rmr = g_rm  + (size_t)s_rv[lr]*Hh;
  int kr = tid>>4, nc = (tid&15)*4;

  for (int k0=0; k0<Hh; k0+=16){
    #pragma unroll
    for (int u=0;u<2;u++){
      int gk = k0 + lk + 2*u;
      float2 vm = make_float2(0.f,0.f), vr = make_float2(0.f,0.f);
      if (gk < Hh){
        vm = *(const float2*)(nmr+gk); vr = *(const float2*)(nrr+gk);
        if (sub){
          float2 a = *(const float2*)(mr+gk), b = *(const float2*)(rmr+gk);
          vm.x -= a.x; vm.y -= a.y; vr.x -= b.x; vr.y -= b.y;
        }
      }
      Ss[lk+2*u][lr] = vm.x; Ss[lk+2*u+1][lr] = vm.y;
      Rs[lk+2*u][lr] = vr.x; Rs[lk+2*u+1][lr] = vr.y;
    }
    {
      int gk = k0 + kr;
      const float* zr = WzB + (size_t)gk*Hh;
      const float* hr = WhB + (size_t)gk*Hh;
      #pragma unroll
      for (int u=0;u<2;u++){
        int gn = bn + nc + 2*u;
        bool ok = (gk<Hh) && (gn<Hh);
        float2 vz = ok? *(const float2*)(zr+gn) : make_float2(0.f,0.f);
        float2 vh = ok? *(const float2*)(hr+gn) : make_float2(0.f,0.f);
        Bz[kr][nc+2*u] = vz.x; Bz[kr][nc+2*u+1] = vz.y;
        Bh[kr][nc+2*u] = vh.x; Bh[kr][nc+2*u+1] = vh.y;
      }
    }
    __syncthreads();
    #pragma unroll
    for (int kk=0; kk<16; kk++){
      float4 a0 = *(const float4*)&Ss[kk][ty*4];
      float4 r0 = *(const float4*)&Rs[kk][ty*4];
      float4 bz = *(const float4*)&Bz[kk][tx*4];
      float4 bh = *(const float4*)&Bh[kk][tx*4];
      float a[4] = {a0.x,a0.y,a0.z,a0.w};
      float w[4] = {r0.x,r0.y,r0.z,r0.w};
      float vz[4] = {bz.x,bz.y,bz.z,bz.w};
      float vh[4] = {bh.x,bh.y,bh.z,bh.w};
      #pragma unroll
      for (int i=0;i<4;i++)
        #pragma unroll
        for (int j=0;j<4;j++){
          accZ[i][j] = fmaf(a[i], vz[j], accZ[i][j]);
          accH[i][j] = fmaf(w[i], vh[j], accH[i][j]);
        }
    }
    __syncthreads();
  }
  #pragma unroll
  for (int i=0;i<4;i++){
    int r = ty*4 + i;
    int se = s_se[r], e = s_eid[r], rv = s_rv[r], w = s_w[r];
    const float* xz = g_Tz + (size_t)w*Hh;
    const float* xh = g_Th + (size_t)w*Hh;
    const float* nm = g_nm + (size_t)se*Hh;
    const float* mrr= g_m  + (size_t)rv*Hh;
    float* mo = g_m + (size_t)e*Hh;
    #pragma unroll
    for (int j=0;j<4;j+=2){
      int c = bn + tx*4 + j;
      if (c >= Hh) continue;
      float2 xzv = *(const float2*)(xz+c), xhv = *(const float2*)(xh+c);
      float2 nmv = *(const float2*)(nm+c);
      float2 mv  = sub ? *(const float2*)(mrr+c) : make_float2(0.f,0.f);
      float z0 = sigmoidf_(accZ[i][j]   + xzv.x), mt0 = tanhf(accH[i][j]   + xhv.x);
      float z1 = sigmoidf_(accZ[i][j+1] + xzv.y), mt1 = tanhf(accH[i][j+1] + xhv.y);
      float s0 = nmv.x - mv.x, s1 = nmv.y - mv.y;
      *(float2*)(mo+c) = make_float2((1.f-z0)*s0 + z0*mt0,
                                     (1.f-z1)*s1 + z1*mt1);
    }
  }
}

// ---------------------------------------------------------------------------
// GEMM B mid (64x128x16, 4x8 microtile): for Ne >= 2048
// up=1: STORE nm/nrm (sibling pair) + write g_rm; up=0: accumulate, skip g_rm
// ---------------------------------------------------------------------------
__global__ __launch_bounds__(256) void k_gemmB_m(
    const int* __restrict__ sched, const int* __restrict__ dstv,
    const int* __restrict__ wid, const float* __restrict__ Ur, int up){
  __shared__ float As[16][64];
  __shared__ float Bs[16][128];
  __shared__ int s_eid[64], s_de[64], s_wd[64];
  int bm = blockIdx.x*64, bn = blockIdx.y*128;
  int tid = threadIdx.x;
  if (tid < 64){
    int e = sched[bm + tid];
    int de = dstv[e];
    s_eid[tid] = e; s_de[tid] = de; s_wd[tid] = wid[de];
  }
  __syncthreads();
  int ty = tid>>4, tx = tid&15;
  float acc[4][8] = {};
  int lr = tid>>2, lk = (tid&3)*4;
  const float* Ar = g_m + (size_t)s_eid[lr]*Hh;
  int kr = tid>>4, nc = (tid&15)*8;

  for (int k0=0; k0<Hh; k0+=16){
    #pragma unroll
    for (int u=0;u<2;u++){
      int gk = k0 + lk + 2*u;
      float2 v = (gk<Hh)? *(const float2*)(Ar+gk) : make_float2(0.f,0.f);
      As[lk+2*u][lr] = v.x; As[lk+2*u+1][lr] = v.y;
    }
    {
      int gk = k0 + kr;
      const float* Br = Ur + (size_t)gk*Hh;
      #pragma unroll
      for (int u=0;u<4;u++){
        int gn = bn + nc + 2*u;
        float2 v = (gk<Hh && gn<Hh)? *(const float2*)(Br+gn) : make_float2(0.f,0.f);
        Bs[kr][nc+2*u] = v.x; Bs[kr][nc+2*u+1] = v.y;
      }
    }
    __syncthreads();
    #pragma unroll
    for (int kk=0; kk<16; kk++){
      float4 a0 = *(const float4*)&As[kk][ty*4];
      float4 b0 = *(const float4*)&Bs[kk][tx*8];
      float4 b1 = *(const float4*)&Bs[kk][tx*8+4];
      float a[4] = {a0.x,a0.y,a0.z,a0.w};
      float b[8] = {b0.x,b0.y,b0.z,b0.w,b1.x,b1.y,b1.z,b1.w};
      #pragma unroll
      for (int i=0;i<4;i++)
        #pragma unroll
        for (int j=0;j<8;j++) acc[i][j] = fmaf(a[i], b[j], acc[i][j]);
    }
    __syncthreads();
  }
  #pragma unroll
  for (int q=0;q<4;q++){
    int c = bn + tx*8 + 2*q;
    if (c >= Hh) continue;
    #pragma unroll
    for (int i=0;i<4;i+=2){
      int r0 = ty*4 + i, r1 = r0 + 1;
      int e0 = s_eid[r0], e1 = s_eid[r1];
      int d0 = s_de[r0],  d1 = s_de[r1];
      int w0 = s_wd[r0],  w1 = s_wd[r1];
      float2 mv0 = *(const float2*)(g_m + (size_t)e0*Hh + c);
      float2 mv1 = *(const float2*)(g_m + (size_t)e1*Hh + c);
      float2 x0  = *(const float2*)(g_Tr + (size_t)w0*Hh + c);
      float2 x1  = *(const float2*)(g_Tr + (size_t)w1*Hh + c);
      float2 rm0 = make_float2(sigmoidf_(acc[i][2*q]+x0.x)*mv0.x,
                               sigmoidf_(acc[i][2*q+1]+x0.y)*mv0.y);
      float2 rm1 = make_float2(sigmoidf_(acc[i+1][2*q]+x1.x)*mv1.x,
                               sigmoidf_(acc[i+1][2*q+1]+x1.y)*mv1.y);
      if (up){
        *(float2*)(g_rm + (size_t)e0*Hh + c) = rm0;
        *(float2*)(g_rm + (size_t)e1*Hh + c) = rm1;
        size_t idx = (size_t)d0*Hh + c;               // sibling pair: STORE
        *(float2*)(g_nm+idx)  = make_float2(mv0.x+mv1.x, mv0.y+mv1.y);
        *(float2*)(g_nrm+idx) = make_float2(rm0.x+rm1.x, rm0.y+rm1.y);
      } else {                                        // down: accumulate
        size_t i0 = (size_t)d0*Hh + c, i1 = (size_t)d1*Hh + c;
        float2 a0v = *(float2*)(g_nm+i0), b0v = *(float2*)(g_nrm+i0);
        a0v.x += mv0.x; a0v.y += mv0.y; b0v.x += rm0.x; b0v.y += rm0.y;
        *(float2*)(g_nm+i0) = a0v; *(float2*)(g_nrm+i0) = b0v;
        float2 a1v = *(float2*)(g_nm+i1), b1v = *(float2*)(g_nrm+i1);
        a1v.x += mv1.x; a1v.y += mv1.y; b1v.x += rm1.x; b1v.y += rm1.y;
        *(float2*)(g_nm+i1) = a1v; *(float2*)(g_nrm+i1) = b1v;
      }
    }
  }
}

// ---------------------------------------------------------------------------
// Small-level variants (32x32x32, 2x2 microtile, 256 threads)
// ---------------------------------------------------------------------------
__global__ __launch_bounds__(256) void k_gemmA_s(
    const int* __restrict__ sched, const int* __restrict__ srcv,
    const int* __restrict__ revv,  const int* __restrict__ wid,
    const float* __restrict__ WzB, const float* __restrict__ WhB, int sub){
  __shared__ float Ss[32][32], Rs[32][32], Bz[32][32], Bh[32][32];
  __shared__ int s_eid[32], s_se[32], s_rv[32], s_w[32];
  int bm = blockIdx.x*32, bn = blockIdx.y*32;
  int tid = threadIdx.x;
  if (tid < 32){
    int e = sched[bm + tid];
    int se = srcv[e];
    s_eid[tid] = e; s_se[tid] = se; s_rv[tid] = revv[e]; s_w[tid] = wid[se];
  }
  __syncthreads();
  int ty = tid>>4, tx = tid&15;
  float accZ[2][2] = {}, accH[2][2] = {};
  int lr = tid>>3, lk = (tid&7)*4;     // 4 k-floats per thread (2 float2)
  const float* nmr = g_nm  + (size_t)s_se[lr]*Hh;
  const float* nrr = g_nrm + (size_t)s_se[lr]*Hh;
  const float* mr  = g_m   + (size_t)s_rv[lr]*Hh;
  const float* rmr = g_rm  + (size_t)s_rv[lr]*Hh;
  int kr = tid>>3, cn = (tid&7)*4;     // B: 4 cols per thread

  for (int k0=0; k0<Hh; k0+=32){
    #pragma unroll
    for (int u=0;u<2;u++){
      int gk = k0 + lk + 2*u;
      float2 vm = make_float2(0.f,0.f), vr = make_float2(0.f,0.f);
      if (gk < Hh){
        vm = *(const float2*)(nmr+gk); vr = *(const float2*)(nrr+gk);
        if (sub){
          float2 a = *(const float2*)(mr+gk), b = *(const float2*)(rmr+gk);
          vm.x -= a.x; vm.y -= a.y; vr.x -= b.x; vr.y -= b.y;
        }
      }
      Ss[lk+2*u][lr] = vm.x; Ss[lk+2*u+1][lr] = vm.y;
      Rs[lk+2*u][lr] = vr.x; Rs[lk+2*u+1][lr] = vr.y;
    }
    {
      int gk = k0 + kr;
      const float* zr = WzB + (size_t)gk*Hh;
      const float* hr = WhB + (size_t)gk*Hh;
      #pragma unroll
      for (int u=0;u<2;u++){
        int gn = bn + cn + 2*u;
        bool ok = (gk<Hh) && (gn<Hh);
        float2 vz = ok? *(const float2*)(zr+gn) : make_float2(0.f,0.f);
        float2 vh = ok? *(const float2*)(hr+gn) : make_float2(0.f,0.f);
        Bz[kr][cn+2*u] = vz.x; Bz[kr][cn+2*u+1] = vz.y;
        Bh[kr][cn+2*u] = vh.x; Bh[kr][cn+2*u+1] = vh.y;
      }
    }
    __syncthreads();
    #pragma unroll
    for (int kk=0; kk<32; kk++){
      float a0=Ss[kk][ty*2], a1=Ss[kk][ty*2+1];
      float w0=Rs[kk][ty*2], w1=Rs[kk][ty*2+1];
      float z0=Bz[kk][tx*2], z1=Bz[kk][tx*2+1];
      float h0=Bh[kk][tx*2], h1=Bh[kk][tx*2+1];
      accZ[0][0]=fmaf(a0,z0,accZ[0][0]); accZ[0][1]=fmaf(a0,z1,accZ[0][1]);
      accZ[1][0]=fmaf(a1,z0,accZ[1][0]); accZ[1][1]=fmaf(a1,z1,accZ[1][1]);
      accH[0][0]=fmaf(w0,h0,accH[0][0]); accH[0][1]=fmaf(w0,h1,accH[0][1]);
      accH[1][0]=fmaf(w1,h0,accH[1][0]); accH[1][1]=fmaf(w1,h1,accH[1][1]);
    }
    __syncthreads();
  }
  #pragma unroll
  for (int i=0;i<2;i++){
    int r = ty*2 + i;
    int se = s_se[r], e = s_eid[r], rv = s_rv[r], w = s_w[r];
    #pragma unroll
    for (int j=0;j<2;j++){
      int c = bn + tx*2 + j;
      if (c >= Hh) continue;
      float z  = sigmoidf_(accZ[i][j] + g_Tz[(size_t)w*Hh + c]);
      float mt = tanhf   (accH[i][j] + g_Th[(size_t)w*Hh + c]);
      float s  = g_nm[(size_t)se*Hh + c] - (sub ? g_m[(size_t)rv*Hh + c] : 0.f);
      g_m[(size_t)e*Hh + c] = (1.f - z)*s + z*mt;
    }
  }
}

__global__ __launch_bounds__(256) void k_gemmB_s(
    const int* __restrict__ sched, const int* __restrict__ dstv,
    const int* __restrict__ wid, const float* __restrict__ Ur, int up){
  __shared__ float As[32][32], Bs[32][32];
  __shared__ int s_eid[32], s_de[32], s_wd[32];
  int bm = blockIdx.x*32, bn = blockIdx.y*32;
  int tid = threadIdx.x;
  if (tid < 32){
    int e = sched[bm + tid];
    int de = dstv[e];
    s_eid[tid] = e; s_de[tid] = de; s_wd[tid] = wid[de];
  }
  __syncthreads();
  int ty = tid>>4, tx = tid&15;
  float acc[2][2] = {};
  int lr = tid>>3, lk = (tid&7)*4;
  const float* Ar = g_m + (size_t)s_eid[lr]*Hh;
  int kr = tid>>3, cn = (tid&7)*4;

  for (int k0=0; k0<Hh; k0+=32){
    #pragma unroll
    for (int u=0;u<2;u++){
      int gk = k0 + lk + 2*u;
      float2 v = (gk<Hh)? *(const float2*)(Ar+gk) : make_float2(0.f,0.f);
      As[lk+2*u][lr] = v.x; As[lk+2*u+1][lr] = v.y;
    }
    {
      int gk = k0 + kr;
      const float* Br = Ur + (size_t)gk*Hh;
      #pragma unroll
      for (int u=0;u<2;u++){
        int gn = bn + cn + 2*u;
        float2 v = ((gk<Hh)&&(gn<Hh))? *(const float2*)(Br+gn)
                                     : make_float2(0.f,0.f);
        Bs[kr][cn+2*u] = v.x; Bs[kr][cn+2*u+1] = v.y;
      }
    }
    __syncthreads();
    #pragma unroll
    for (int kk=0; kk<32; kk++){
      float a0=As[kk][ty*2], a1=As[kk][ty*2+1];
      float b0=Bs[kk][tx*2], b1=Bs[kk][tx*2+1];
      acc[0][0]=fmaf(a0,b0,acc[0][0]); acc[0][1]=fmaf(a0,b1,acc[0][1]);
      acc[1][0]=fmaf(a1,b0,acc[1][0]); acc[1][1]=fmaf(a1,b1,acc[1][1]);
    }
    __syncthreads();
  }
  int r0 = ty*2, r1 = ty*2+1;
  int e0 = s_eid[r0], e1 = s_eid[r1];
  int d0 = s_de[r0],  d1 = s_de[r1];
  int w0 = s_wd[r0],  w1 = s_wd[r1];
  #pragma unroll
  for (int j=0;j<2;j++){
    int c = bn + tx*2 + j;
    if (c >= Hh) continue;
    float mv0 = g_m[(size_t)e0*Hh + c];
    float mv1 = g_m[(size_t)e1*Hh + c];
    float rm0 = sigmoidf_(acc[0][j] + g_Tr[(size_t)w0*Hh + c]) * mv0;
    float rm1 = sigmoidf_(acc[1][j] + g_Tr[(size_t)w1*Hh + c]) * mv1;
    if (up){
      g_rm[(size_t)e0*Hh + c] = rm0;
      g_rm[(size_t)e1*Hh + c] = rm1;
      size_t idx = (size_t)d0*Hh + c;   // sibling pair: STORE
      g_nm[idx]  = mv0 + mv1;
      g_nrm[idx] = rm0 + rm1;
    } else {
      g_nm[(size_t)d0*Hh + c]  += mv0;
      g_nrm[(size_t)d0*Hh + c] += rm0;
      g_nm[(size_t)d1*Hh + c]  += mv1;
      g_nrm[(size_t)d1*Hh + c] += rm1;
    }
  }
}

// ---------------------------------------------------------------------------
// Final readout (cp.async double-buffered, 2 CTAs/SM):
// out = relu(Tg[wid[r]] + node_m @ WgB)
// ---------------------------------------------------------------------------
__global__ __launch_bounds__(256,2) void k_final(
    const int* __restrict__ wid, const float* __restrict__ WgB,
    float* __restrict__ out){
  __shared__ float2 As2[2][8][128];
  __shared__ float  Bs [2][16][128];
  int bm = blockIdx.x*128, bn = blockIdx.y*128;
  int tid = threadIdx.x, ty = tid>>4, tx = tid&15;
  float acc[8][8] = {};
  int lr = tid>>1, lk = (tid&1)*8;
  const float* Ar = g_nm + (size_t)(bm+lr)*Hh;
  int kr = tid>>4, nc = (tid&15)*8;

  const int T = (Hh + 15)/16;
  {
    #pragma unroll
    for (int u=0;u<4;u++){
      int gk = lk + 2*u;
      cpa8(sptr(&As2[0][(lk>>1)+u][lr]), Ar + gk, gk < Hh);
    }
    const float* Br = WgB + (size_t)kr*Hh;
    #pragma unroll
    for (int u=0;u<4;u++){
      int gn = bn + nc + 2*u;
      cpa8(sptr(&Bs[0][kr][nc+2*u]), Br + ((gn<Hh)? gn : 0), (kr<Hh) && (gn<Hh));
    }
    CP_COMMIT();
  }
  for (int t=0; t<T; t++){
    int buf = t & 1;
    if (t+1 < T){
      int k0 = (t+1)*16, nb = buf^1;
      #pragma unroll
      for (int u=0;u<4;u++){
        int gk = k0 + lk + 2*u;
        cpa8(sptr(&As2[nb][(lk>>1)+u][lr]), Ar + ((gk<Hh)? gk : 0), gk < Hh);
      }
      int gkB = k0 + kr;
      const float* Br = WgB + (size_t)((gkB<Hh)? gkB : 0)*Hh;
      #pragma unroll
      for (int u=0;u<4;u++){
        int gn = bn + nc + 2*u;
        cpa8(sptr(&Bs[nb][kr][nc+2*u]), Br + ((gn<Hh)? gn : 0),
             (gkB<Hh) && (gn<Hh));
      }
      CP_COMMIT();
      CP_WAIT1();
    } else {
      CP_WAIT0();
    }
    __syncthreads();
    #pragma unroll
    for (int kp=0; kp<8; kp++){
      float2 a2[8];
      #pragma unroll
      for (int i=0;i<8;i+=2){
        float4 t4 = *(const float4*)&As2[buf][kp][ty*8+i];
        a2[i]   = make_float2(t4.x, t4.y);
        a2[i+1] = make_float2(t4.z, t4.w);
      }
      float4 b00 = *(const float4*)&Bs[buf][2*kp  ][tx*8];
      float4 b01 = *(const float4*)&Bs[buf][2*kp  ][tx*8+4];
      float4 b10 = *(const float4*)&Bs[buf][2*kp+1][tx*8];
      float4 b11 = *(const float4*)&Bs[buf][2*kp+1][tx*8+4];
      float b0[8] = {b00.x,b00.y,b00.z,b00.w,b01.x,b01.y,b01.z,b01.w};
      float b1[8] = {b10.x,b10.y,b10.z,b10.w,b11.x,b11.y,b11.z,b11.w};
      #pragma unroll
      for (int i=0;i<8;i++)
        #pragma unroll
        for (int j=0;j<8;j++){
          acc[i][j] = fmaf(a2[i].x, b0[j], acc[i][j]);
          acc[i][j] = fmaf(a2[i].y, b1[j], acc[i][j]);
        }
    }
    __syncthreads();
  }
  #pragma unroll
  for (int i=0;i<8;i++){
    int r = bm + ty*8 + i;
    const float* xg = g_Tg + (size_t)wid[r]*Hh;
    #pragma unroll
    for (int j=0;j<8;j+=2){
      int c = bn + tx*8 + j;
      if (c >= Hh) continue;
      float2 xv = *(const float2*)(xg + c);
      *(float2*)(out + (size_t)r*Hh + c) =
          make_float2(fmaxf(acc[i][j]+xv.x,0.f), fmaxf(acc[i][j+1]+xv.y,0.f));
    }
  }
}

// ---------------------------------------------------------------------------
// kernel_launch
// Inputs: 0 wid, 1 src, 2 dst, 3 rev, 4 sched, 5 emb, 6 Wz, 7 bz,
//         8 Wr, 9 Ur, 10 bur, 11 Wh, 12 bh, 13 Wg, 14 bg
// ---------------------------------------------------------------------------
extern "C" void kernel_launch(void* const* d_in, const int* in_sizes, int n_in,
                              void* d_out, int out_size) {
  const int*   wid   = (const int*)  d_in[0];
  const int*   srcv  = (const int*)  d_in[1];
  const int*   dstv  = (const int*)  d_in[2];
  const int*   revv  = (const int*)  d_in[3];
  const int*   sched = (const int*)  d_in[4];
  const float* emb   = (const float*)d_in[5];
  const float* Wz    = (const float*)d_in[6];
  const float* bz    = (const float*)d_in[7];
  const float* Wr    = (const float*)d_in[8];
  const float* Ur    = (const float*)d_in[9];
  const float* bur   = (const float*)d_in[10];
  const float* Wh    = (const float*)d_in[11];
  const float* bh    = (const float*)d_in[12];
  const float* Wg    = (const float*)d_in[13];
  const float* bg    = (const float*)d_in[14];
  float* out = (float*)d_out;

  const int lmax = in_sizes[4] / 12;   // 8192
  static const int NeTab[12] = {8192,4096,2048,1024,512,256,
                                 256,512,1024,2048,4096,8192};

  // vocab tables (no zero-init needed anywhere)
  dim3 gv((Vv + 63)/64, 4, 4);
  k_vocab4<<<gv, 256>>>(emb, Wz, bz, Wh, bh, Wr, bur, Wg, bg);
  k_tm<<<(Vv*(Hh/2) + 255)/256, 256>>>();
  dim3 gtr((Vv + 63)/64, 8);
  k_vocabTR<<<gtr, 256>>>(Ur);

  // level 0: vocab-table gather + sibling-pair STORE scatter (no edge GEMM)
  k_leaf<<<NeTab[0]/2, 256>>>(sched, srcv, dstv, wid);

  // levels 1..10
  for (int lvl = 1; lvl < 11; lvl++) {
    int Ne  = NeTab[lvl];
    int sub = (lvl >= 6) ? 1 : 0;
    int up  = (lvl <  6) ? 1 : 0;
    const int* sc = sched + lvl*lmax;
    if (Ne >= 4096){
      dim3 gA(Ne/128, 8);
      k_gemmA_b<<<gA, 256>>>(sc, srcv, revv, dstv, wid,
                             Wz + Hh*Hh, Wh + Hh*Hh, sub, 0);
      dim3 gB(Ne/64, 4);
      k_gemmB_m<<<gB, 256>>>(sc, dstv, wid, Ur, up);
    } else if (Ne == 2048){
      dim3 gA(Ne/64, 8);     // 256 blocks — fills the chip
      k_gemmA_m<<<gA, 256>>>(sc, srcv, revv, wid, Wz + Hh*Hh, Wh + Hh*Hh, sub);
      dim3 gB(Ne/64, 4);
      k_gemmB_m<<<gB, 256>>>(sc, dstv, wid, Ur, up);
    } else {
      dim3 g(Ne/32, 15);
      k_gemmA_s<<<g, 256>>>(sc, srcv, revv, wid, Wz + Hh*Hh, Wh + Hh*Hh, sub);
      k_gemmB_s<<<g, 256>>>(sc, dstv, wid, Ur, up);
    }
  }
  // level 11: m_new GEMM writing DIRECTLY into nm[dst] (replaces scat11)
  {
    const int* sc = sched + 11*lmax;
    dim3 gA(NeTab[11]/128, 8);
    k_gemmA_b<<<gA, 256>>>(sc, srcv, revv, dstv, wid,
                           Wz + Hh*Hh, Wh + Hh*Hh, 1, 1);
  }

  // readout
  dim3 gf(NNODE/128, 4);
  k_final<<<gf, 256>>>(wid, Wg + Hh*Hh, out);
}

// round 15
// speedup vs baseline: 1.0845x; 1.0165x over previous
#include <cuda_runtime.h>
#include <cstdint>
#include <math.h>

// Problem constants (B=128 trees, depth D=6, NPT=127)
#define Hh     450
#define NNODE  16256   // 128*127
#define NEDGE  32256   // 2*128*126
#define Vv     780     // vocabulary size

// Scratch (static device globals; allocation-free kernel_launch)
// No zero-init needed — every nm/nrm location is STOREd before any
// accumulate or read (up levels store sibling sums; lvl11 stores leaf nm).
__device__ float g_Tz [Vv*Hh];
__device__ float g_Th [Vv*Hh];
__device__ float g_Tr [Vv*Hh];
__device__ float g_Tg [Vv*Hh];
__device__ float g_Tm [Vv*Hh];     // leaf message table sigmoid(Tz)*tanh(Th)
__device__ float g_TR [Vv*Hh];     // TRu = Tm @ Ur
__device__ float g_m  [NEDGE*Hh];
__device__ float g_rm [NEDGE*Hh];
__device__ float g_nm [NNODE*Hh];
__device__ float g_nrm[NNODE*Hh];

__device__ __forceinline__ float sigmoidf_(float v){ return 1.0f/(1.0f+expf(-v)); }

// 8-byte cp.async with zero-fill when invalid (used by k_final)
__device__ __forceinline__ void cpa8(unsigned int dst, const float* src, bool valid){
  int sz = valid ? 8 : 0;
  asm volatile("cp.async.ca.shared.global [%0], [%1], 8, %2;\n"
               :: "r"(dst), "l"(src), "r"(sz));
}
__device__ __forceinline__ unsigned int sptr(const void* p){
  return (unsigned int)__cvta_generic_to_shared(p);
}
#define CP_COMMIT() asm volatile("cp.async.commit_group;\n" ::)
#define CP_WAIT1()  asm volatile("cp.async.wait_group 1;\n" ::)
#define CP_WAIT0()  asm volatile("cp.async.wait_group 0;\n" ::)

// ---------------------------------------------------------------------------
// Fused vocab-table GEMM: T[z] = emb @ W[z] + bias[z]   (M=780, N=K=450)
// ---------------------------------------------------------------------------
__global__ __launch_bounds__(256) void k_vocab4(
    const float* __restrict__ emb,
    const float* __restrict__ W0, const float* __restrict__ b0,
    const float* __restrict__ W1, const float* __restrict__ b1,
    const float* __restrict__ W2, const float* __restrict__ b2,
    const float* __restrict__ W3, const float* __restrict__ b3){
  __shared__ float As[8][64];
  __shared__ float Bs[8][128];
  int which = blockIdx.z;
  const float* W    = (which==0)?W0:(which==1)?W1:(which==2)?W2:W3;
  const float* bias = (which==0)?b0:(which==1)?b1:(which==2)?b2:b3;
  float* T = (which==0)?g_Tz:(which==1)?g_Th:(which==2)?g_Tr:g_Tg;
  int bm = blockIdx.x*64, bn = blockIdx.y*128;
  int tid = threadIdx.x, ty = tid>>4, tx = tid&15;
  float acc[4][8] = {};
  int lr = tid>>2, lk = (tid&3)*2;
  int rr = bm + lr; if (rr >= Vv) rr = Vv-1;
  const float* Ar = emb + (size_t)rr*Hh;
  int kr = tid>>5, nc = (tid&31)*4;

  for (int k0=0; k0<Hh; k0+=8){
    {
      int gk = k0 + lk;
      float2 v = (gk<Hh)? *(const float2*)(Ar+gk) : make_float2(0.f,0.f);
      As[lk][lr] = v.x; As[lk+1][lr] = v.y;
    }
    {
      int gk = k0 + kr;
      const float* Br = W + (size_t)gk*Hh;
      #pragma unroll
      for (int u=0;u<4;u+=2){
        int gn = bn + nc + u;
        float2 v = (gk<Hh && gn<Hh)? *(const float2*)(Br+gn) : make_float2(0.f,0.f);
        Bs[kr][nc+u] = v.x; Bs[kr][nc+u+1] = v.y;
      }
    }
    __syncthreads();
    #pragma unroll
    for (int kk=0; kk<8; kk++){
      float4 a0 = *(const float4*)&As[kk][ty*4];
      float4 b0v = *(const float4*)&Bs[kk][tx*8];
      float4 b1v = *(const float4*)&Bs[kk][tx*8+4];
      float a[4] = {a0.x,a0.y,a0.z,a0.w};
      float b[8] = {b0v.x,b0v.y,b0v.z,b0v.w,b1v.x,b1v.y,b1v.z,b1v.w};
      #pragma unroll
      for (int i=0;i<4;i++)
        #pragma unroll
        for (int j=0;j<8;j++) acc[i][j] = fmaf(a[i], b[j], acc[i][j]);
    }
    __syncthreads();
  }
  #pragma unroll
  for (int i=0;i<4;i++){
    int r = bm + ty*4 + i;
    if (r >= Vv) continue;
    #pragma unroll
    for (int j=0;j<8;j+=2){
      int c = bn + tx*8 + j;
      if (c >= Hh) continue;
      float2 bv = *(const float2*)(bias + c);
      *(float2*)(T + (size_t)r*Hh + c) =
          make_float2(acc[i][j]+bv.x, acc[i][j+1]+bv.y);
    }
  }
}

// ---------------------------------------------------------------------------
// Tm table: Tm[w] = sigmoid(Tz[w]) * tanh(Th[w])   (pointwise, 780x450)
// ---------------------------------------------------------------------------
__global__ void k_tm(){
  int i2 = blockIdx.x*blockDim.x + threadIdx.x;
  const int N2 = Vv*Hh/2;
  if (i2 < N2){
    float2 a = ((const float2*)g_Tz)[i2];
    float2 b = ((const float2*)g_Th)[i2];
    ((float2*)g_Tm)[i2] = make_float2(sigmoidf_(a.x)*tanhf(b.x),
                                      sigmoidf_(a.y)*tanhf(b.y));
  }
}

// ---------------------------------------------------------------------------
// Vocab TR GEMM: g_TR = g_Tm @ Ur   (M=780, N=K=450)
// 64x64x8 tile, 4x4 microtile -> 104 blocks
// ---------------------------------------------------------------------------
__global__ __launch_bounds__(256) void k_vocabTR(const float* __restrict__ Ur){
  __shared__ float As[8][64];
  __shared__ float Bs[8][64];
  int bm = blockIdx.x*64, bn = blockIdx.y*64;
  int tid = threadIdx.x, ty = tid>>4, tx = tid&15;
  float acc[4][4] = {};
  int lr = tid>>2, lk = (tid&3)*2;
  int rr = bm + lr; if (rr >= Vv) rr = Vv-1;
  const float* Ar = g_Tm + (size_t)rr*Hh;
  int kr = tid>>5, cn = (tid&31)*2;

  for (int k0=0; k0<Hh; k0+=8){
    {
      int gk = k0 + lk;
      float2 v = (gk<Hh)? *(const float2*)(Ar+gk) : make_float2(0.f,0.f);
      As[lk][lr] = v.x; As[lk+1][lr] = v.y;
    }
    {
      int gk = k0 + kr, gn = bn + cn;
      float2 v = (gk<Hh && gn<Hh)? *(const float2*)(Ur + (size_t)gk*Hh + gn)
                                 : make_float2(0.f,0.f);
      Bs[kr][cn] = v.x; Bs[kr][cn+1] = v.y;
    }
    __syncthreads();
    #pragma unroll
    for (int kk=0; kk<8; kk++){
      float4 a0 = *(const float4*)&As[kk][ty*4];
      float4 b0 = *(const float4*)&Bs[kk][tx*4];
      float a[4] = {a0.x,a0.y,a0.z,a0.w};
      float b[4] = {b0.x,b0.y,b0.z,b0.w};
      #pragma unroll
      for (int i=0;i<4;i++)
        #pragma unroll
        for (int j=0;j<4;j++) acc[i][j] = fmaf(a[i], b[j], acc[i][j]);
    }
    __syncthreads();
  }
  #pragma unroll
  for (int i=0;i<4;i++){
    int r = bm + ty*4 + i;
    if (r >= Vv) continue;
    #pragma unroll
    for (int j=0;j<4;j+=2){
      int c = bn + tx*4 + j;
      if (c >= Hh) continue;
      *(float2*)(g_TR + (size_t)r*Hh + c) = make_float2(acc[i][j], acc[i][j+1]);
    }
  }
}

// ---------------------------------------------------------------------------
// Leaf level (lvl0): one block per SIBLING PAIR. STOREs nm/nrm (first write).
// ---------------------------------------------------------------------------
__global__ void k_leaf(const int* __restrict__ sched, const int* __restrict__ srcv,
                       const int* __restrict__ dstv, const int* __restrict__ wid){
  int b  = blockIdx.x;
  int e0 = sched[2*b], e1 = sched[2*b+1];
  int w0 = wid[srcv[e0]], w1 = wid[srcv[e1]];
  int d  = dstv[e0];                // sibling pair shares dst
  int wd = wid[d];
  int c = threadIdx.x*2;
  if (c >= Hh) return;
  float2 tm0 = *(const float2*)(g_Tm + (size_t)w0*Hh + c);
  float2 tm1 = *(const float2*)(g_Tm + (size_t)w1*Hh + c);
  float2 tr0 = *(const float2*)(g_TR + (size_t)w0*Hh + c);
  float2 tr1 = *(const float2*)(g_TR + (size_t)w1*Hh + c);
  float2 xr  = *(const float2*)(g_Tr + (size_t)wd*Hh + c);
  float2 rm0 = make_float2(sigmoidf_(tr0.x+xr.x)*tm0.x, sigmoidf_(tr0.y+xr.y)*tm0.y);
  float2 rm1 = make_float2(sigmoidf_(tr1.x+xr.x)*tm1.x, sigmoidf_(tr1.y+xr.y)*tm1.y);
  *(float2*)(g_m  + (size_t)e0*Hh + c) = tm0;
  *(float2*)(g_m  + (size_t)e1*Hh + c) = tm1;
  *(float2*)(g_rm + (size_t)e0*Hh + c) = rm0;
  *(float2*)(g_rm + (size_t)e1*Hh + c) = rm1;
  size_t idx = (size_t)d*Hh + c;
  *(float2*)(g_nm+idx)  = make_float2(tm0.x+tm1.x, tm0.y+tm1.y);   // STORE
  *(float2*)(g_nrm+idx) = make_float2(rm0.x+rm1.x, rm0.y+rm1.y);   // STORE
}

// ---------------------------------------------------------------------------
// GEMM A big (dual, 128x64x8, 8x4 microtile, reg-prefetch):
//   Z = S@WzB, MT = ARM@WhB ; m_new = (1-z)*s + z*mt
// dstout=0: write g_m[e];  dstout=1 (lvl11): write g_nm[dst[e]] directly
// ---------------------------------------------------------------------------
__global__ __launch_bounds__(256) void k_gemmA_b(
    const int* __restrict__ sched, const int* __restrict__ srcv,
    const int* __restrict__ revv,  const int* __restrict__ dstv,
    const int* __restrict__ wid,
    const float* __restrict__ WzB, const float* __restrict__ WhB,
    int sub, int dstout){
  __shared__ float Ss[8][128], Rs[8][128];
  __shared__ float Bz[8][64],  Bh[8][64];
  __shared__ int s_out[128], s_se[128], s_rv[128], s_w[128];
  int bm = blockIdx.x*128, bn = blockIdx.y*64;
  int tid = threadIdx.x;
  if (tid < 128){
    int e = sched[bm + tid];
    int se = srcv[e];
    s_out[tid] = dstout ? dstv[e] : e;
    s_se[tid] = se; s_rv[tid] = revv[e]; s_w[tid] = wid[se];
  }
  __syncthreads();
  int ty = tid>>4, tx = tid&15;
  float accZ[8][4] = {}, accH[8][4] = {};
  int lr = tid>>1, lk = (tid&1)*4;
  const float* nmr = g_nm  + (size_t)s_se[lr]*Hh;
  const float* nrr = g_nrm + (size_t)s_se[lr]*Hh;
  const float* mr  = g_m   + (size_t)s_rv[lr]*Hh;
  const float* rmr = g_rm  + (size_t)s_rv[lr]*Hh;
  int kr = tid>>5, ncB = (tid&31)*2;

  float2 pm[2], pr[2], pz, ph;
  #pragma unroll
  for (int u=0;u<2;u++){
    int gk = lk + 2*u;
    float2 vm = make_float2(0.f,0.f), vr = make_float2(0.f,0.f);
    if (gk < Hh){
      vm = *(const float2*)(nmr+gk); vr = *(const float2*)(nrr+gk);
      if (sub){
        float2 a = *(const float2*)(mr+gk), b = *(const float2*)(rmr+gk);
        vm.x -= a.x; vm.y -= a.y; vr.x -= b.x; vr.y -= b.y;
      }
    }
    pm[u] = vm; pr[u] = vr;
  }
  {
    int gk = kr, gn = bn + ncB;
    bool ok = (gk<Hh) && (gn<Hh);
    pz = ok? *(const float2*)(WzB + (size_t)gk*Hh + gn) : make_float2(0.f,0.f);
    ph = ok? *(const float2*)(WhB + (size_t)gk*Hh + gn) : make_float2(0.f,0.f);
  }

  for (int k0=0; k0<Hh; k0+=8){
    Ss[lk  ][lr] = pm[0].x; Ss[lk+1][lr] = pm[0].y;
    Ss[lk+2][lr] = pm[1].x; Ss[lk+3][lr] = pm[1].y;
    Rs[lk  ][lr] = pr[0].x; Rs[lk+1][lr] = pr[0].y;
    Rs[lk+2][lr] = pr[1].x; Rs[lk+3][lr] = pr[1].y;
    Bz[kr][ncB] = pz.x; Bz[kr][ncB+1] = pz.y;
    Bh[kr][ncB] = ph.x; Bh[kr][ncB+1] = ph.y;
    __syncthreads();
    int kn = k0 + 8;
    if (kn < Hh){
      #pragma unroll
      for (int u=0;u<2;u++){
        int gk = kn + lk + 2*u;
        float2 vm = make_float2(0.f,0.f), vr = make_float2(0.f,0.f);
        if (gk < Hh){
          vm = *(const float2*)(nmr+gk); vr = *(const float2*)(nrr+gk);
          if (sub){
            float2 a = *(const float2*)(mr+gk), b = *(const float2*)(rmr+gk);
            vm.x -= a.x; vm.y -= a.y; vr.x -= b.x; vr.y -= b.y;
          }
        }
        pm[u] = vm; pr[u] = vr;
      }
      int gk = kn + kr, gn = bn + ncB;
      bool ok = (gk<Hh) && (gn<Hh);
      pz = ok? *(const float2*)(WzB + (size_t)gk*Hh + gn) : make_float2(0.f,0.f);
      ph = ok? *(const float2*)(WhB + (size_t)gk*Hh + gn) : make_float2(0.f,0.f);
    }
    #pragma unroll
    for (int kk=0; kk<8; kk++){
      float4 a0 = *(const float4*)&Ss[kk][ty*8];
      float4 a1 = *(const float4*)&Ss[kk][ty*8+4];
      float4 r0 = *(const float4*)&Rs[kk][ty*8];
      float4 r1 = *(const float4*)&Rs[kk][ty*8+4];
      float4 bz = *(const float4*)&Bz[kk][tx*4];
      float4 bh = *(const float4*)&Bh[kk][tx*4];
      float a[8] = {a0.x,a0.y,a0.z,a0.w,a1.x,a1.y,a1.z,a1.w};
      float w[8] = {r0.x,r0.y,r0.z,r0.w,r1.x,r1.y,r1.z,r1.w};
      float vz[4] = {bz.x,bz.y,bz.z,bz.w};
      float vh[4] = {bh.x,bh.y,bh.z,bh.w};
      #pragma unroll
      for (int i=0;i<8;i++)
        #pragma unroll
        for (int j=0;j<4;j++){
          accZ[i][j] = fmaf(a[i], vz[j], accZ[i][j]);
          accH[i][j] = fmaf(w[i], vh[j], accH[i][j]);
        }
    }
    __syncthreads();
  }
  #pragma unroll
  for (int i=0;i<8;i++){
    int r = ty*8 + i;
    int se = s_se[r], oidx = s_out[r], rv = s_rv[r], w = s_w[r];
    const float* xz = g_Tz + (size_t)w*Hh;
    const float* xh = g_Th + (size_t)w*Hh;
    const float* nm = g_nm + (size_t)se*Hh;
    const float* mrr= g_m  + (size_t)rv*Hh;
    float* mo = (dstout ? g_nm : g_m) + (size_t)oidx*Hh;
    #pragma unroll
    for (int j=0;j<4;j+=2){
      int c = bn + tx*4 + j;
      if (c >= Hh) continue;
      float2 xzv = *(const float2*)(xz+c), xhv = *(const float2*)(xh+c);
      float2 nmv = *(const float2*)(nm+c);
      float2 mv  = sub ? *(const float2*)(mrr+c) : make_float2(0.f,0.f);
      float z0 = sigmoidf_(accZ[i][j]   + xzv.x), mt0 = tanhf(accH[i][j]   + xhv.x);
      float z1 = sigmoidf_(accZ[i][j+1] + xzv.y), mt1 = tanhf(accH[i][j+1] + xhv.y);
      float s0 = nmv.x - mv.x, s1 = nmv.y - mv.y;
      *(float2*)(mo+c) = make_float2((1.f-z0)*s0 + z0*mt0,
                                     (1.f-z1)*s1 + z1*mt1);
    }
  }
}

// ---------------------------------------------------------------------------
// GEMM A mid (dual, 64x64x16, 4x4 microtile): for Ne == 2048 only
// ---------------------------------------------------------------------------
__global__ __launch_bounds__(256) void k_gemmA_m(
    const int* __restrict__ sched, const int* __restrict__ srcv,
    const int* __restrict__ revv,  const int* __restrict__ wid,
    const float* __restrict__ WzB, const float* __restrict__ WhB, int sub){
  __shared__ float Ss[16][64], Rs[16][64];
  __shared__ float Bz[16][64], Bh[16][64];
  __shared__ int s_eid[64], s_se[64], s_rv[64], s_w[64];
  int bm = blockIdx.x*64, bn = blockIdx.y*64;
  int tid = threadIdx.x;
  if (tid < 64){
    int e = sched[bm + tid];
    int se = srcv[e];
    s_eid[tid] = e; s_se[tid] = se; s_rv[tid] = revv[e]; s_w[tid] = wid[se];
  }
  __syncthreads();
  int ty = tid>>4, tx = tid&15;
  float accZ[4][4] = {}, accH[4][4] = {};
  int lr = tid>>2, lk = (tid&3)*4;
  const float* nmr = g_nm  + (size_t)s_se[lr]*Hh;
  const float* nrr = g_nrm + (size_t)s_se[lr]*Hh;
  const float* mr  = g_m   + (size_t)s_rv[lr]*Hh;
  const float* rmr = g_rm  + (size_t)s_rv[lr]*Hh;
  int kr = tid>>4, nc = (tid&15)*4;

  for (int k0=0; k0<Hh; k0+=16){
    #pragma unroll
    for (int u=0;u<2;u++){
      int gk = k0 + lk + 2*u;
      float2 vm = make_float2(0.f,0.f), vr = make_float2(0.f,0.f);
      if (gk < Hh){
        vm = *(const float2*)(nmr+gk); vr = *(const float2*)(nrr+gk);
        if (sub){
          float2 a = *(const float2*)(mr+gk), b = *(const float2*)(rmr+gk);
          vm.x -= a.x; vm.y -= a.y; vr.x -= b.x; vr.y -= b.y;
        }
      }
      Ss[lk+2*u][lr] = vm.x; Ss[lk+2*u+1][lr] = vm.y;
      Rs[lk+2*u][lr] = vr.x; Rs[lk+2*u+1][lr] = vr.y;
    }
    {
      int gk = k0 + kr;
      const float* zr = WzB + (size_t)gk*Hh;
      const float* hr = WhB + (size_t)gk*Hh;
      #pragma unroll
      for (int u=0;u<2;u++){
        int gn = bn + nc + 2*u;
        bool ok = (gk<Hh) && (gn<Hh);
        float2 vz = ok? *(const float2*)(zr+gn) : make_float2(0.f,0.f);
        float2 vh = ok? *(const float2*)(hr+gn) : make_float2(0.f,0.f);
        Bz[kr][nc+2*u] = vz.x; Bz[kr][nc+2*u+1] = vz.y;
        Bh[kr][nc+2*u] = vh.x; Bh[kr][nc+2*u+1] = vh.y;
      }
    }
    __syncthreads();
    #pragma unroll
    for (int kk=0; kk<16; kk++){
      float4 a0 = *(const float4*)&Ss[kk][ty*4];
      float4 r0 = *(const float4*)&Rs[kk][ty*4];
      float4 bz = *(const float4*)&Bz[kk][tx*4];
      float4 bh = *(const float4*)&Bh[kk][tx*4];
      float a[4] = {a0.x,a0.y,a0.z,a0.w};
      float w[4] = {r0.x,r0.y,r0.z,r0.w};
      float vz[4] = {bz.x,bz.y,bz.z,bz.w};
      float vh[4] = {bh.x,bh.y,bh.z,bh.w};
      #pragma unroll
      for (int i=0;i<4;i++)
        #pragma unroll
        for (int j=0;j<4;j++){
          accZ[i][j] = fmaf(a[i], vz[j], accZ[i][j]);
          accH[i][j] = fmaf(w[i], vh[j], accH[i][j]);
        }
    }
    __syncthreads();
  }
  #pragma unroll
  for (int i=0;i<4;i++){
    int r = ty*4 + i;
    int se = s_se[r], e = s_eid[r], rv = s_rv[r], w = s_w[r];
    const float* xz = g_Tz + (size_t)w*Hh;
    const float* xh = g_Th + (size_t)w*Hh;
    const float* nm = g_nm + (size_t)se*Hh;
    const float* mrr= g_m  + (size_t)rv*Hh;
    float* mo = g_m + (size_t)e*Hh;
    #pragma unroll
    for (int j=0;j<4;j+=2){
      int c = bn + tx*4 + j;
      if (c >= Hh) continue;
      float2 xzv = *(const float2*)(xz+c), xhv = *(const float2*)(xh+c);
      float2 nmv = *(const float2*)(nm+c);
      float2 mv  = sub ? *(const float2*)(mrr+c) : make_float2(0.f,0.f);
      float z0 = sigmoidf_(accZ[i][j]   + xzv.x), mt0 = tanhf(accH[i][j]   + xhv.x);
      float z1 = sigmoidf_(accZ[i][j+1] + xzv.y), mt1 = tanhf(accH[i][j+1] + xhv.y);
      float s0 = nmv.x - mv.x, s1 = nmv.y - mv.y;
      *(float2*)(mo+c) = make_float2((1.f-z0)*s0 + z0*mt0,
                                     (1.f-z1)*s1 + z1*mt1);
    }
  }
}

// ---------------------------------------------------------------------------
// GEMM B mid (64x128x16, 4x8 microtile): for Ne >= 4096
// up=1: STORE nm/nrm (sibling pair) + write g_rm; up=0: accumulate, skip g_rm
// ---------------------------------------------------------------------------
__global__ __launch_bounds__(256) void k_gemmB_m(
    const int* __restrict__ sched, const int* __restrict__ dstv,
    const int* __restrict__ wid, const float* __restrict__ Ur, int up){
  __shared__ float As[16][64];
  __shared__ float Bs[16][128];
  __shared__ int s_eid[64], s_de[64], s_wd[64];
  int bm = blockIdx.x*64, bn = blockIdx.y*128;
  int tid = threadIdx.x;
  if (tid < 64){
    int e = sched[bm + tid];
    int de = dstv[e];
    s_eid[tid] = e; s_de[tid] = de; s_wd[tid] = wid[de];
  }
  __syncthreads();
  int ty = tid>>4, tx = tid&15;
  float acc[4][8] = {};
  int lr = tid>>2, lk = (tid&3)*4;
  const float* Ar = g_m + (size_t)s_eid[lr]*Hh;
  int kr = tid>>4, nc = (tid&15)*8;

  for (int k0=0; k0<Hh; k0+=16){
    #pragma unroll
    for (int u=0;u<2;u++){
      int gk = k0 + lk + 2*u;
      float2 v = (gk<Hh)? *(const float2*)(Ar+gk) : make_float2(0.f,0.f);
      As[lk+2*u][lr] = v.x; As[lk+2*u+1][lr] = v.y;
    }
    {
      int gk = k0 + kr;
      const float* Br = Ur + (size_t)gk*Hh;
      #pragma unroll
      for (int u=0;u<4;u++){
        int gn = bn + nc + 2*u;
        float2 v = (gk<Hh && gn<Hh)? *(const float2*)(Br+gn) : make_float2(0.f,0.f);
        Bs[kr][nc+2*u] = v.x; Bs[kr][nc+2*u+1] = v.y;
      }
    }
    __syncthreads();
    #pragma unroll
    for (int kk=0; kk<16; kk++){
      float4 a0 = *(const float4*)&As[kk][ty*4];
      float4 b0 = *(const float4*)&Bs[kk][tx*8];
      float4 b1 = *(const float4*)&Bs[kk][tx*8+4];
      float a[4] = {a0.x,a0.y,a0.z,a0.w};
      float b[8] = {b0.x,b0.y,b0.z,b0.w,b1.x,b1.y,b1.z,b1.w};
      #pragma unroll
      for (int i=0;i<4;i++)
        #pragma unroll
        for (int j=0;j<8;j++) acc[i][j] = fmaf(a[i], b[j], acc[i][j]);
    }
    __syncthreads();
  }
  #pragma unroll
  for (int q=0;q<4;q++){
    int c = bn + tx*8 + 2*q;
    if (c >= Hh) continue;
    #pragma unroll
    for (int i=0;i<4;i+=2){
      int r0 = ty*4 + i, r1 = r0 + 1;
      int e0 = s_eid[r0], e1 = s_eid[r1];
      int d0 = s_de[r0],  d1 = s_de[r1];
      int w0 = s_wd[r0],  w1 = s_wd[r1];
      float2 mv0 = *(const float2*)(g_m + (size_t)e0*Hh + c);
      float2 mv1 = *(const float2*)(g_m + (size_t)e1*Hh + c);
      float2 x0  = *(const float2*)(g_Tr + (size_t)w0*Hh + c);
      float2 x1  = *(const float2*)(g_Tr + (size_t)w1*Hh + c);
      float2 rm0 = make_float2(sigmoidf_(acc[i][2*q]+x0.x)*mv0.x,
                               sigmoidf_(acc[i][2*q+1]+x0.y)*mv0.y);
      float2 rm1 = make_float2(sigmoidf_(acc[i+1][2*q]+x1.x)*mv1.x,
                               sigmoidf_(acc[i+1][2*q+1]+x1.y)*mv1.y);
      if (up){
        *(float2*)(g_rm + (size_t)e0*Hh + c) = rm0;
        *(float2*)(g_rm + (size_t)e1*Hh + c) = rm1;
        size_t idx = (size_t)d0*Hh + c;               // sibling pair: STORE
        *(float2*)(g_nm+idx)  = make_float2(mv0.x+mv1.x, mv0.y+mv1.y);
        *(float2*)(g_nrm+idx) = make_float2(rm0.x+rm1.x, rm0.y+rm1.y);
      } else {                                        // down: accumulate
        size_t i0 = (size_t)d0*Hh + c, i1 = (size_t)d1*Hh + c;
        float2 a0v = *(float2*)(g_nm+i0), b0v = *(float2*)(g_nrm+i0);
        a0v.x += mv0.x; a0v.y += mv0.y; b0v.x += rm0.x; b0v.y += rm0.y;
        *(float2*)(g_nm+i0) = a0v; *(float2*)(g_nrm+i0) = b0v;
        float2 a1v = *(float2*)(g_nm+i1), b1v = *(float2*)(g_nrm+i1);
        a1v.x += mv1.x; a1v.y += mv1.y; b1v.x += rm1.x; b1v.y += rm1.y;
        *(float2*)(g_nm+i1) = a1v; *(float2*)(g_nrm+i1) = b1v;
      }
    }
  }
}

// ---------------------------------------------------------------------------
// GEMM B mid64 (64x64x16, 4x4 microtile): for Ne == 2048 (256 blocks)
// ---------------------------------------------------------------------------
__global__ __launch_bounds__(256) void k_gemmB_m64(
    const int* __restrict__ sched, const int* __restrict__ dstv,
    const int* __restrict__ wid, const float* __restrict__ Ur, int up){
  __shared__ float As[16][64];
  __shared__ float Bs[16][64];
  __shared__ int s_eid[64], s_de[64], s_wd[64];
  int bm = blockIdx.x*64, bn = blockIdx.y*64;
  int tid = threadIdx.x;
  if (tid < 64){
    int e = sched[bm + tid];
    int de = dstv[e];
    s_eid[tid] = e; s_de[tid] = de; s_wd[tid] = wid[de];
  }
  __syncthreads();
  int ty = tid>>4, tx = tid&15;
  float acc[4][4] = {};
  int lr = tid>>2, lk = (tid&3)*4;
  const float* Ar = g_m + (size_t)s_eid[lr]*Hh;
  int kr = tid>>4, nc = (tid&15)*4;

  for (int k0=0; k0<Hh; k0+=16){
    #pragma unroll
    for (int u=0;u<2;u++){
      int gk = k0 + lk + 2*u;
      float2 v = (gk<Hh)? *(const float2*)(Ar+gk) : make_float2(0.f,0.f);
      As[lk+2*u][lr] = v.x; As[lk+2*u+1][lr] = v.y;
    }
    {
      int gk = k0 + kr;
      const float* Br = Ur + (size_t)gk*Hh;
      #pragma unroll
      for (int u=0;u<2;u++){
        int gn = bn + nc + 2*u;
        float2 v = (gk<Hh && gn<Hh)? *(const float2*)(Br+gn) : make_float2(0.f,0.f);
        Bs[kr][nc+2*u] = v.x; Bs[kr][nc+2*u+1] = v.y;
      }
    }
    __syncthreads();
    #pragma unroll
    for (int kk=0; kk<16; kk++){
      float4 a0 = *(const float4*)&As[kk][ty*4];
      float4 b0 = *(const float4*)&Bs[kk][tx*4];
      float a[4] = {a0.x,a0.y,a0.z,a0.w};
      float b[4] = {b0.x,b0.y,b0.z,b0.w};
      #pragma unroll
      for (int i=0;i<4;i++)
        #pragma unroll
        for (int j=0;j<4;j++) acc[i][j] = fmaf(a[i], b[j], acc[i][j]);
    }
    __syncthreads();
  }
  #pragma unroll
  for (int q=0;q<2;q++){
    int c = bn + tx*4 + 2*q;
    if (c >= Hh) continue;
    #pragma unroll
    for (int i=0;i<4;i+=2){
      int r0 = ty*4 + i, r1 = r0 + 1;
      int e0 = s_eid[r0], e1 = s_eid[r1];
      int d0 = s_de[r0],  d1 = s_de[r1];
      int w0 = s_wd[r0],  w1 = s_wd[r1];
      float2 mv0 = *(const float2*)(g_m + (size_t)e0*Hh + c);
      float2 mv1 = *(const float2*)(g_m + (size_t)e1*Hh + c);
      float2 x0  = *(const float2*)(g_Tr + (size_t)w0*Hh + c);
      float2 x1  = *(const float2*)(g_Tr + (size_t)w1*Hh + c);
      float2 rm0 = make_float2(sigmoidf_(acc[i][2*q]+x0.x)*mv0.x,
                               sigmoidf_(acc[i][2*q+1]+x0.y)*mv0.y);
      float2 rm1 = make_float2(sigmoidf_(acc[i+1][2*q]+x1.x)*mv1.x,
                               sigmoidf_(acc[i+1][2*q+1]+x1.y)*mv1.y);
      if (up){
        *(float2*)(g_rm + (size_t)e0*Hh + c) = rm0;
        *(float2*)(g_rm + (size_t)e1*Hh + c) = rm1;
        size_t idx = (size_t)d0*Hh + c;               // sibling pair: STORE
        *(float2*)(g_nm+idx)  = make_float2(mv0.x+mv1.x, mv0.y+mv1.y);
        *(float2*)(g_nrm+idx) = make_float2(rm0.x+rm1.x, rm0.y+rm1.y);
      } else {                                        // down: accumulate
        size_t i0 = (size_t)d0*Hh + c, i1 = (size_t)d1*Hh + c;
        float2 a0v = *(float2*)(g_nm+i0), b0v = *(float2*)(g_nrm+i0);
        a0v.x += mv0.x; a0v.y += mv0.y; b0v.x += rm0.x; b0v.y += rm0.y;
        *(float2*)(g_nm+i0) = a0v; *(float2*)(g_nrm+i0) = b0v;
        float2 a1v = *(float2*)(g_nm+i1), b1v = *(float2*)(g_nrm+i1);
        a1v.x += mv1.x; a1v.y += mv1.y; b1v.x += rm1.x; b1v.y += rm1.y;
        *(float2*)(g_nm+i1) = a1v; *(float2*)(g_nrm+i1) = b1v;
      }
    }
  }
}

// ---------------------------------------------------------------------------
// Small-level variants (32x32x32, 2x2 microtile, 256 threads)
// ---------------------------------------------------------------------------
__global__ __launch_bounds__(256) void k_gemmA_s(
    const int* __restrict__ sched, const int* __restrict__ srcv,
    const int* __restrict__ revv,  const int* __restrict__ wid,
    const float* __restrict__ WzB, const float* __restrict__ WhB, int sub){
  __shared__ float Ss[32][32], Rs[32][32], Bz[32][32], Bh[32][32];
  __shared__ int s_eid[32], s_se[32], s_rv[32], s_w[32];
  int bm = blockIdx.x*32, bn = blockIdx.y*32;
  int tid = threadIdx.x;
  if (tid < 32){
    int e = sched[bm + tid];
    int se = srcv[e];
    s_eid[tid] = e; s_se[tid] = se; s_rv[tid] = revv[e]; s_w[tid] = wid[se];
  }
  __syncthreads();
  int ty = tid>>4, tx = tid&15;
  float accZ[2][2] = {}, accH[2][2] = {};
  int lr = tid>>3, lk = (tid&7)*4;     // 4 k-floats per thread (2 float2)
  const float* nmr = g_nm  + (size_t)s_se[lr]*Hh;
  const float* nrr = g_nrm + (size_t)s_se[lr]*Hh;
  const float* mr  = g_m   + (size_t)s_rv[lr]*Hh;
  const float* rmr = g_rm  + (size_t)s_rv[lr]*Hh;
  int kr = tid>>3, cn = (tid&7)*4;     // B: 4 cols per thread

  for (int k0=0; k0<Hh; k0+=32){
    #pragma unroll
    for (int u=0;u<2;u++){
      int gk = k0 + lk + 2*u;
      float2 vm = make_float2(0.f,0.f), vr = make_float2(0.f,0.f);
      if (gk < Hh){
        vm = *(const float2*)(nmr+gk); vr = *(const float2*)(nrr+gk);
        if (sub){
          float2 a = *(const float2*)(mr+gk), b = *(const float2*)(rmr+gk);
          vm.x -= a.x; vm.y -= a.y; vr.x -= b.x; vr.y -= b.y;
        }
      }
      Ss[lk+2*u][lr] = vm.x; Ss[lk+2*u+1][lr] = vm.y;
      Rs[lk+2*u][lr] = vr.x; Rs[lk+2*u+1][lr] = vr.y;
    }
    {
      int gk = k0 + kr;
      const float* zr = WzB + (size_t)gk*Hh;
      const float* hr = WhB + (size_t)gk*Hh;
      #pragma unroll
      for (int u=0;u<2;u++){
        int gn = bn + cn + 2*u;
        bool ok = (gk<Hh) && (gn<Hh);
        float2 vz = ok? *(const float2*)(zr+gn) : make_float2(0.f,0.f);
        float2 vh = ok? *(const float2*)(hr+gn) : make_float2(0.f,0.f);
        Bz[kr][cn+2*u] = vz.x; Bz[kr][cn+2*u+1] = vz.y;
        Bh[kr][cn+2*u] = vh.x; Bh[kr][cn+2*u+1] = vh.y;
      }
    }
    __syncthreads();
    #pragma unroll
    for (int kk=0; kk<32; kk++){
      float a0=Ss[kk][ty*2], a1=Ss[kk][ty*2+1];
      float w0=Rs[kk][ty*2], w1=Rs[kk][ty*2+1];
      float z0=Bz[kk][tx*2], z1=Bz[kk][tx*2+1];
      float h0=Bh[kk][tx*2], h1=Bh[kk][tx*2+1];
      accZ[0][0]=fmaf(a0,z0,accZ[0][0]); accZ[0][1]=fmaf(a0,z1,accZ[0][1]);
      accZ[1][0]=fmaf(a1,z0,accZ[1][0]); accZ[1][1]=fmaf(a1,z1,accZ[1][1]);
      accH[0][0]=fmaf(w0,h0,accH[0][0]); accH[0][1]=fmaf(w0,h1,accH[0][1]);
      accH[1][0]=fmaf(w1,h0,accH[1][0]); accH[1][1]=fmaf(w1,h1,accH[1][1]);
    }
    __syncthreads();
  }
  #pragma unroll
  for (int i=0;i<2;i++){
    int r = ty*2 + i;
    int se = s_se[r], e = s_eid[r], rv = s_rv[r], w = s_w[r];
    #pragma unroll
    for (int j=0;j<2;j++){
      int c = bn + tx*2 + j;
      if (c >= Hh) continue;
      float z  = sigmoidf_(accZ[i][j] + g_Tz[(size_t)w*Hh + c]);
      float mt = tanhf   (accH[i][j] + g_Th[(size_t)w*Hh + c]);
      float s  = g_nm[(size_t)se*Hh + c] - (sub ? g_m[(size_t)rv*Hh + c] : 0.f);
      g_m[(size_t)e*Hh + c] = (1.f - z)*s + z*mt;
    }
  }
}

__global__ __launch_bounds__(256) void k_gemmB_s(
    const int* __restrict__ sched, const int* __restrict__ dstv,
    const int* __restrict__ wid, const float* __restrict__ Ur, int up){
  __shared__ float As[32][32], Bs[32][32];
  __shared__ int s_eid[32], s_de[32], s_wd[32];
  int bm = blockIdx.x*32, bn = blockIdx.y*32;
  int tid = threadIdx.x;
  if (tid < 32){
    int e = sched[bm + tid];
    int de = dstv[e];
    s_eid[tid] = e; s_de[tid] = de; s_wd[tid] = wid[de];
  }
  __syncthreads();
  int ty = tid>>4, tx = tid&15;
  float acc[2][2] = {};
  int lr = tid>>3, lk = (tid&7)*4;
  const float* Ar = g_m + (size_t)s_eid[lr]*Hh;
  int kr = tid>>3, cn = (tid&7)*4;

  for (int k0=0; k0<Hh; k0+=32){
    #pragma unroll
    for (int u=0;u<2;u++){
      int gk = k0 + lk + 2*u;
      float2 v = (gk<Hh)? *(const float2*)(Ar+gk) : make_float2(0.f,0.f);
      As[lk+2*u][lr] = v.x; As[lk+2*u+1][lr] = v.y;
    }
    {
      int gk = k0 + kr;
      const float* Br = Ur + (size_t)gk*Hh;
      #pragma unroll
      for (int u=0;u<2;u++){
        int gn = bn + cn + 2*u;
        float2 v = ((gk<Hh)&&(gn<Hh))? *(const float2*)(Br+gn)
                                     : make_float2(0.f,0.f);
        Bs[kr][cn+2*u] = v.x; Bs[kr][cn+2*u+1] = v.y;
      }
    }
    __syncthreads();
    #pragma unroll
    for (int kk=0; kk<32; kk++){
      float a0=As[kk][ty*2], a1=As[kk][ty*2+1];
      float b0=Bs[kk][tx*2], b1=Bs[kk][tx*2+1];
      acc[0][0]=fmaf(a0,b0,acc[0][0]); acc[0][1]=fmaf(a0,b1,acc[0][1]);
      acc[1][0]=fmaf(a1,b0,acc[1][0]); acc[1][1]=fmaf(a1,b1,acc[1][1]);
    }
    __syncthreads();
  }
  int r0 = ty*2, r1 = ty*2+1;
  int e0 = s_eid[r0], e1 = s_eid[r1];
  int d0 = s_de[r0],  d1 = s_de[r1];
  int w0 = s_wd[r0],  w1 = s_wd[r1];
  #pragma unroll
  for (int j=0;j<2;j++){
    int c = bn + tx*2 + j;
    if (c >= Hh) continue;
    float mv0 = g_m[(size_t)e0*Hh + c];
    float mv1 = g_m[(size_t)e1*Hh + c];
    float rm0 = sigmoidf_(acc[0][j] + g_Tr[(size_t)w0*Hh + c]) * mv0;
    float rm1 = sigmoidf_(acc[1][j] + g_Tr[(size_t)w1*Hh + c]) * mv1;
    if (up){
      g_rm[(size_t)e0*Hh + c] = rm0;
      g_rm[(size_t)e1*Hh + c] = rm1;
      size_t idx = (size_t)d0*Hh + c;   // sibling pair: STORE
      g_nm[idx]  = mv0 + mv1;
      g_nrm[idx] = rm0 + rm1;
    } else {
      g_nm[(size_t)d0*Hh + c]  += mv0;
      g_nrm[(size_t)d0*Hh + c] += rm0;
      g_nm[(size_t)d1*Hh + c]  += mv1;
      g_nrm[(size_t)d1*Hh + c] += rm1;
    }
  }
}

// ---------------------------------------------------------------------------
// Final readout (cp.async double-buffered, 2 CTAs/SM):
// out = relu(Tg[wid[r]] + node_m @ WgB)
// ---------------------------------------------------------------------------
__global__ __launch_bounds__(256,2) void k_final(
    const int* __restrict__ wid, const float* __restrict__ WgB,
    float* __restrict__ out){
  __shared__ float2 As2[2][8][128];
  __shared__ float  Bs [2][16][128];
  int bm = blockIdx.x*128, bn = blockIdx.y*128;
  int tid = threadIdx.x, ty = tid>>4, tx = tid&15;
  float acc[8][8] = {};
  int lr = tid>>1, lk = (tid&1)*8;
  const float* Ar = g_nm + (size_t)(bm+lr)*Hh;
  int kr = tid>>4, nc = (tid&15)*8;

  const int T = (Hh + 15)/16;
  {
    #pragma unroll
    for (int u=0;u<4;u++){
      int gk = lk + 2*u;
      cpa8(sptr(&As2[0][(lk>>1)+u][lr]), Ar + gk, gk < Hh);
    }
    const float* Br = WgB + (size_t)kr*Hh;
    #pragma unroll
    for (int u=0;u<4;u++){
      int gn = bn + nc + 2*u;
      cpa8(sptr(&Bs[0][kr][nc+2*u]), Br + ((gn<Hh)? gn : 0), (kr<Hh) && (gn<Hh));
    }
    CP_COMMIT();
  }
  for (int t=0; t<T; t++){
    int buf = t & 1;
    if (t+1 < T){
      int k0 = (t+1)*16, nb = buf^1;
      #pragma unroll
      for (int u=0;u<4;u++){
        int gk = k0 + lk + 2*u;
        cpa8(sptr(&As2[nb][(lk>>1)+u][lr]), Ar + ((gk<Hh)? gk : 0), gk < Hh);
      }
      int gkB = k0 + kr;
      const float* Br = WgB + (size_t)((gkB<Hh)? gkB : 0)*Hh;
      #pragma unroll
      for (int u=0;u<4;u++){
        int gn = bn + nc + 2*u;
        cpa8(sptr(&Bs[nb][kr][nc+2*u]), Br + ((gn<Hh)? gn : 0),
             (gkB<Hh) && (gn<Hh));
      }
      CP_COMMIT();
      CP_WAIT1();
    } else {
      CP_WAIT0();
    }
    __syncthreads();
    #pragma unroll
    for (int kp=0; kp<8; kp++){
      float2 a2[8];
      #pragma unroll
      for (int i=0;i<8;i+=2){
        float4 t4 = *(const float4*)&As2[buf][kp][ty*8+i];
        a2[i]   = make_float2(t4.x, t4.y);
        a2[i+1] = make_float2(t4.z, t4.w);
      }
      float4 b00 = *(const float4*)&Bs[buf][2*kp  ][tx*8];
      float4 b01 = *(const float4*)&Bs[buf][2*kp  ][tx*8+4];
      float4 b10 = *(const float4*)&Bs[buf][2*kp+1][tx*8];
      float4 b11 = *(const float4*)&Bs[buf][2*kp+1][tx*8+4];
      float b0[8] = {b00.x,b00.y,b00.z,b00.w,b01.x,b01.y,b01.z,b01.w};
      float b1[8] = {b10.x,b10.y,b10.z,b10.w,b11.x,b11.y,b11.z,b11.w};
      #pragma unroll
      for (int i=0;i<8;i++)
        #pragma unroll
        for (int j=0;j<8;j++){
          acc[i][j] = fmaf(a2[i].x, b0[j], acc[i][j]);
          acc[i][j] = fmaf(a2[i].y, b1[j], acc[i][j]);
        }
    }
    __syncthreads();
  }
  #pragma unroll
  for (int i=0;i<8;i++){
    int r = bm + ty*8 + i;
    const float* xg = g_Tg + (size_t)wid[r]*Hh;
    #pragma unroll
    for (int j=0;j<8;j+=2){
      int c = bn + tx*8 + j;
      if (c >= Hh) continue;
      float2 xv = *(const float2*)(xg + c);
      *(float2*)(out + (size_t)r*Hh + c) =
          make_float2(fmaxf(acc[i][j]+xv.x,0.f), fmaxf(acc[i][j+1]+xv.y,0.f));
    }
  }
}

// ---------------------------------------------------------------------------
// kernel_launch
// Inputs: 0 wid, 1 src, 2 dst, 3 rev, 4 sched, 5 emb, 6 Wz, 7 bz,
//         8 Wr, 9 Ur, 10 bur, 11 Wh, 12 bh, 13 Wg, 14 bg
// ---------------------------------------------------------------------------
extern "C" void kernel_launch(void* const* d_in, const int* in_sizes, int n_in,
                              void* d_out, int out_size) {
  const int*   wid   = (const int*)  d_in[0];
  const int*   srcv  = (const int*)  d_in[1];
  const int*   dstv  = (const int*)  d_in[2];
  const int*   revv  = (const int*)  d_in[3];
  const int*   sched = (const int*)  d_in[4];
  const float* emb   = (const float*)d_in[5];
  const float* Wz    = (const float*)d_in[6];
  const float* bz    = (const float*)d_in[7];
  const float* Wr    = (const float*)d_in[8];
  const float* Ur    = (const float*)d_in[9];
  const float* bur   = (const float*)d_in[10];
  const float* Wh    = (const float*)d_in[11];
  const float* bh    = (const float*)d_in[12];
  const float* Wg    = (const float*)d_in[13];
  const float* bg    = (const float*)d_in[14];
  float* out = (float*)d_out;

  const int lmax = in_sizes[4] / 12;   // 8192
  static const int NeTab[12] = {8192,4096,2048,1024,512,256,
                                 256,512,1024,2048,4096,8192};

  // vocab tables (no zero-init needed anywhere)
  dim3 gv((Vv + 63)/64, 4, 4);
  k_vocab4<<<gv, 256>>>(emb, Wz, bz, Wh, bh, Wr, bur, Wg, bg);
  k_tm<<<(Vv*(Hh/2) + 255)/256, 256>>>();
  dim3 gtr((Vv + 63)/64, 8);
  k_vocabTR<<<gtr, 256>>>(Ur);

  // level 0: vocab-table gather + sibling-pair STORE scatter (no edge GEMM)
  k_leaf<<<NeTab[0]/2, 256>>>(sched, srcv, dstv, wid);

  // levels 1..10
  for (int lvl = 1; lvl < 11; lvl++) {
    int Ne  = NeTab[lvl];
    int sub = (lvl >= 6) ? 1 : 0;
    int up  = (lvl <  6) ? 1 : 0;
    const int* sc = sched + lvl*lmax;
    if (Ne >= 4096){
      dim3 gA(Ne/128, 8);
      k_gemmA_b<<<gA, 256>>>(sc, srcv, revv, dstv, wid,
                             Wz + Hh*Hh, Wh + Hh*Hh, sub, 0);
      dim3 gB(Ne/64, 4);
      k_gemmB_m<<<gB, 256>>>(sc, dstv, wid, Ur, up);
    } else if (Ne == 2048){
      dim3 gA(Ne/64, 8);     // 256 blocks — fills the chip
      k_gemmA_m<<<gA, 256>>>(sc, srcv, revv, wid, Wz + Hh*Hh, Wh + Hh*Hh, sub);
      dim3 gB(Ne/64, 8);     // 256 blocks — fills the chip
      k_gemmB_m64<<<gB, 256>>>(sc, dstv, wid, Ur, up);
    } else {
      dim3 g(Ne/32, 15);
      k_gemmA_s<<<g, 256>>>(sc, srcv, revv, wid, Wz + Hh*Hh, Wh + Hh*Hh, sub);
      k_gemmB_s<<<g, 256>>>(sc, dstv, wid, Ur, up);
    }
  }
  // level 11: m_new GEMM writing DIRECTLY into nm[dst] (replaces scat11)
  {
    const int* sc = sched + 11*lmax;
    dim3 gA(NeTab[11]/128, 8);
    k_gemmA_b<<<gA, 256>>>(sc, srcv, revv, dstv, wid,
                           Wz + Hh*Hh, Wh + Hh*Hh, 1, 1);
  }

  // readout
  dim3 gf(NNODE/128, 4);
  k_final<<<gf, 256>>>(wid, Wg + Hh*Hh, out);
}

// round 16
// speedup vs baseline: 1.1241x; 1.0365x over previous
#include <cuda_runtime.h>
#include <cstdint>
#include <math.h>

// Problem constants (B=128 trees, depth D=6, NPT=127)
#define Hh     450
#define NNODE  16256   // 128*127
#define NEDGE  32256   // 2*128*126
#define Vv     780     // vocabulary size

// Scratch (static device globals; allocation-free kernel_launch)
// No zero-init needed — every nm/nrm location is STOREd before any
// accumulate or read (up levels store sibling sums; lvl11 stores leaf nm).
__device__ float g_Tz [Vv*Hh];
__device__ float g_Th [Vv*Hh];
__device__ float g_Tr [Vv*Hh];
__device__ float g_Tg [Vv*Hh];
__device__ float g_Tm [Vv*Hh];     // leaf message table sigmoid(Tz)*tanh(Th)
__device__ float g_TR [Vv*Hh];     // TRu = Tm @ Ur
__device__ float g_m  [NEDGE*Hh];
__device__ float g_rm [NEDGE*Hh];
__device__ float g_nm [NNODE*Hh];
__device__ float g_nrm[NNODE*Hh];

__device__ __forceinline__ float sigmoidf_(float v){ return 1.0f/(1.0f+expf(-v)); }

// 8-byte cp.async with zero-fill when invalid (used by k_final)
__device__ __forceinline__ void cpa8(unsigned int dst, const float* src, bool valid){
  int sz = valid ? 8 : 0;
  asm volatile("cp.async.ca.shared.global [%0], [%1], 8, %2;\n"
               :: "r"(dst), "l"(src), "r"(sz));
}
__device__ __forceinline__ unsigned int sptr(const void* p){
  return (unsigned int)__cvta_generic_to_shared(p);
}
#define CP_COMMIT() asm volatile("cp.async.commit_group;\n" ::)
#define CP_WAIT1()  asm volatile("cp.async.wait_group 1;\n" ::)
#define CP_WAIT0()  asm volatile("cp.async.wait_group 0;\n" ::)

// ---------------------------------------------------------------------------
// Fused vocab-table GEMM: T[z] = emb @ W[z] + bias[z]   (M=780, N=K=450)
// ---------------------------------------------------------------------------
__global__ __launch_bounds__(256) void k_vocab4(
    const float* __restrict__ emb,
    const float* __restrict__ W0, const float* __restrict__ b0,
    const float* __restrict__ W1, const float* __restrict__ b1,
    const float* __restrict__ W2, const float* __restrict__ b2,
    const float* __restrict__ W3, const float* __restrict__ b3){
  __shared__ float As[8][64];
  __shared__ float Bs[8][128];
  int which = blockIdx.z;
  const float* W    = (which==0)?W0:(which==1)?W1:(which==2)?W2:W3;
  const float* bias = (which==0)?b0:(which==1)?b1:(which==2)?b2:b3;
  float* T = (which==0)?g_Tz:(which==1)?g_Th:(which==2)?g_Tr:g_Tg;
  int bm = blockIdx.x*64, bn = blockIdx.y*128;
  int tid = threadIdx.x, ty = tid>>4, tx = tid&15;
  float acc[4][8] = {};
  int lr = tid>>2, lk = (tid&3)*2;
  int rr = bm + lr; if (rr >= Vv) rr = Vv-1;
  const float* Ar = emb + (size_t)rr*Hh;
  int kr = tid>>5, nc = (tid&31)*4;

  for (int k0=0; k0<Hh; k0+=8){
    {
      int gk = k0 + lk;
      float2 v = (gk<Hh)? *(const float2*)(Ar+gk) : make_float2(0.f,0.f);
      As[lk][lr] = v.x; As[lk+1][lr] = v.y;
    }
    {
      int gk = k0 + kr;
      const float* Br = W + (size_t)gk*Hh;
      #pragma unroll
      for (int u=0;u<4;u+=2){
        int gn = bn + nc + u;
        float2 v = (gk<Hh && gn<Hh)? *(const float2*)(Br+gn) : make_float2(0.f,0.f);
        Bs[kr][nc+u] = v.x; Bs[kr][nc+u+1] = v.y;
      }
    }
    __syncthreads();
    #pragma unroll
    for (int kk=0; kk<8; kk++){
      float4 a0 = *(const float4*)&As[kk][ty*4];
      float4 b0v = *(const float4*)&Bs[kk][tx*8];
      float4 b1v = *(const float4*)&Bs[kk][tx*8+4];
      float a[4] = {a0.x,a0.y,a0.z,a0.w};
      float b[8] = {b0v.x,b0v.y,b0v.z,b0v.w,b1v.x,b1v.y,b1v.z,b1v.w};
      #pragma unroll
      for (int i=0;i<4;i++)
        #pragma unroll
        for (int j=0;j<8;j++) acc[i][j] = fmaf(a[i], b[j], acc[i][j]);
    }
    __syncthreads();
  }
  #pragma unroll
  for (int i=0;i<4;i++){
    int r = bm + ty*4 + i;
    if (r >= Vv) continue;
    #pragma unroll
    for (int j=0;j<8;j+=2){
      int c = bn + tx*8 + j;
      if (c >= Hh) continue;
      float2 bv = *(const float2*)(bias + c);
      *(float2*)(T + (size_t)r*Hh + c) =
          make_float2(acc[i][j]+bv.x, acc[i][j+1]+bv.y);
    }
  }
}

// ---------------------------------------------------------------------------
// Tm table: Tm[w] = sigmoid(Tz[w]) * tanh(Th[w])   (pointwise, 780x450)
// ---------------------------------------------------------------------------
__global__ void k_tm(){
  int i2 = blockIdx.x*blockDim.x + threadIdx.x;
  const int N2 = Vv*Hh/2;
  if (i2 < N2){
    float2 a = ((const float2*)g_Tz)[i2];
    float2 b = ((const float2*)g_Th)[i2];
    ((float2*)g_Tm)[i2] = make_float2(sigmoidf_(a.x)*tanhf(b.x),
                                      sigmoidf_(a.y)*tanhf(b.y));
  }
}

// ---------------------------------------------------------------------------
// Vocab TR GEMM: g_TR = g_Tm @ Ur   (M=780, N=K=450)
// 64x64x8 tile, 4x4 microtile -> 104 blocks
// ---------------------------------------------------------------------------
__global__ __launch_bounds__(256) void k_vocabTR(const float* __restrict__ Ur){
  __shared__ float As[8][64];
  __shared__ float Bs[8][64];
  int bm = blockIdx.x*64, bn = blockIdx.y*64;
  int tid = threadIdx.x, ty = tid>>4, tx = tid&15;
  float acc[4][4] = {};
  int lr = tid>>2, lk = (tid&3)*2;
  int rr = bm + lr; if (rr >= Vv) rr = Vv-1;
  const float* Ar = g_Tm + (size_t)rr*Hh;
  int kr = tid>>5, cn = (tid&31)*2;

  for (int k0=0; k0<Hh; k0+=8){
    {
      int gk = k0 + lk;
      float2 v = (gk<Hh)? *(const float2*)(Ar+gk) : make_float2(0.f,0.f);
      As[lk][lr] = v.x; As[lk+1][lr] = v.y;
    }
    {
      int gk = k0 + kr, gn = bn + cn;
      float2 v = (gk<Hh && gn<Hh)? *(const float2*)(Ur + (size_t)gk*Hh + gn)
                                 : make_float2(0.f,0.f);
      Bs[kr][cn] = v.x; Bs[kr][cn+1] = v.y;
    }
    __syncthreads();
    #pragma unroll
    for (int kk=0; kk<8; kk++){
      float4 a0 = *(const float4*)&As[kk][ty*4];
      float4 b0 = *(const float4*)&Bs[kk][tx*4];
      float a[4] = {a0.x,a0.y,a0.z,a0.w};
      float b[4] = {b0.x,b0.y,b0.z,b0.w};
      #pragma unroll
      for (int i=0;i<4;i++)
        #pragma unroll
        for (int j=0;j<4;j++) acc[i][j] = fmaf(a[i], b[j], acc[i][j]);
    }
    __syncthreads();
  }
  #pragma unroll
  for (int i=0;i<4;i++){
    int r = bm + ty*4 + i;
    if (r >= Vv) continue;
    #pragma unroll
    for (int j=0;j<4;j+=2){
      int c = bn + tx*4 + j;
      if (c >= Hh) continue;
      *(float2*)(g_TR + (size_t)r*Hh + c) = make_float2(acc[i][j], acc[i][j+1]);
    }
  }
}

// ---------------------------------------------------------------------------
// Leaf level (lvl0): one block per SIBLING PAIR. STOREs nm/nrm (first write).
// ---------------------------------------------------------------------------
__global__ void k_leaf(const int* __restrict__ sched, const int* __restrict__ srcv,
                       const int* __restrict__ dstv, const int* __restrict__ wid){
  int b  = blockIdx.x;
  int e0 = sched[2*b], e1 = sched[2*b+1];
  int w0 = wid[srcv[e0]], w1 = wid[srcv[e1]];
  int d  = dstv[e0];                // sibling pair shares dst
  int wd = wid[d];
  int c = threadIdx.x*2;
  if (c >= Hh) return;
  float2 tm0 = *(const float2*)(g_Tm + (size_t)w0*Hh + c);
  float2 tm1 = *(const float2*)(g_Tm + (size_t)w1*Hh + c);
  float2 tr0 = *(const float2*)(g_TR + (size_t)w0*Hh + c);
  float2 tr1 = *(const float2*)(g_TR + (size_t)w1*Hh + c);
  float2 xr  = *(const float2*)(g_Tr + (size_t)wd*Hh + c);
  float2 rm0 = make_float2(sigmoidf_(tr0.x+xr.x)*tm0.x, sigmoidf_(tr0.y+xr.y)*tm0.y);
  float2 rm1 = make_float2(sigmoidf_(tr1.x+xr.x)*tm1.x, sigmoidf_(tr1.y+xr.y)*tm1.y);
  *(float2*)(g_m  + (size_t)e0*Hh + c) = tm0;
  *(float2*)(g_m  + (size_t)e1*Hh + c) = tm1;
  *(float2*)(g_rm + (size_t)e0*Hh + c) = rm0;
  *(float2*)(g_rm + (size_t)e1*Hh + c) = rm1;
  size_t idx = (size_t)d*Hh + c;
  *(float2*)(g_nm+idx)  = make_float2(tm0.x+tm1.x, tm0.y+tm1.y);   // STORE
  *(float2*)(g_nrm+idx) = make_float2(rm0.x+rm1.x, rm0.y+rm1.y);   // STORE
}

// ---------------------------------------------------------------------------
// GEMM A big (dual, 128x64x8, 8x4 microtile, reg-prefetch):
//   Z = S@WzB, MT = ARM@WhB ; m_new = (1-z)*s + z*mt
// dstout=0: write g_m[e];  dstout=1 (lvl11): write g_nm[dst[e]] directly
// ---------------------------------------------------------------------------
__global__ __launch_bounds__(256) void k_gemmA_b(
    const int* __restrict__ sched, const int* __restrict__ srcv,
    const int* __restrict__ revv,  const int* __restrict__ dstv,
    const int* __restrict__ wid,
    const float* __restrict__ WzB, const float* __restrict__ WhB,
    int sub, int dstout){
  __shared__ float Ss[8][128], Rs[8][128];
  __shared__ float Bz[8][64],  Bh[8][64];
  __shared__ int s_out[128], s_se[128], s_rv[128], s_w[128];
  int bm = blockIdx.x*128, bn = blockIdx.y*64;
  int tid = threadIdx.x;
  if (tid < 128){
    int e = sched[bm + tid];
    int se = srcv[e];
    s_out[tid] = dstout ? dstv[e] : e;
    s_se[tid] = se; s_rv[tid] = revv[e]; s_w[tid] = wid[se];
  }
  __syncthreads();
  int ty = tid>>4, tx = tid&15;
  float accZ[8][4] = {}, accH[8][4] = {};
  int lr = tid>>1, lk = (tid&1)*4;
  const float* nmr = g_nm  + (size_t)s_se[lr]*Hh;
  const float* nrr = g_nrm + (size_t)s_se[lr]*Hh;
  const float* mr  = g_m   + (size_t)s_rv[lr]*Hh;
  const float* rmr = g_rm  + (size_t)s_rv[lr]*Hh;
  int kr = tid>>5, ncB = (tid&31)*2;

  float2 pm[2], pr[2], pz, ph;
  #pragma unroll
  for (int u=0;u<2;u++){
    int gk = lk + 2*u;
    float2 vm = make_float2(0.f,0.f), vr = make_float2(0.f,0.f);
    if (gk < Hh){
      vm = *(const float2*)(nmr+gk); vr = *(const float2*)(nrr+gk);
      if (sub){
        float2 a = *(const float2*)(mr+gk), b = *(const float2*)(rmr+gk);
        vm.x -= a.x; vm.y -= a.y; vr.x -= b.x; vr.y -= b.y;
      }
    }
    pm[u] = vm; pr[u] = vr;
  }
  {
    int gk = kr, gn = bn + ncB;
    bool ok = (gk<Hh) && (gn<Hh);
    pz = ok? *(const float2*)(WzB + (size_t)gk*Hh + gn) : make_float2(0.f,0.f);
    ph = ok? *(const float2*)(WhB + (size_t)gk*Hh + gn) : make_float2(0.f,0.f);
  }

  for (int k0=0; k0<Hh; k0+=8){
    Ss[lk  ][lr] = pm[0].x; Ss[lk+1][lr] = pm[0].y;
    Ss[lk+2][lr] = pm[1].x; Ss[lk+3][lr] = pm[1].y;
    Rs[lk  ][lr] = pr[0].x; Rs[lk+1][lr] = pr[0].y;
    Rs[lk+2][lr] = pr[1].x; Rs[lk+3][lr] = pr[1].y;
    Bz[kr][ncB] = pz.x; Bz[kr][ncB+1] = pz.y;
    Bh[kr][ncB] = ph.x; Bh[kr][ncB+1] = ph.y;
    __syncthreads();
    int kn = k0 + 8;
    if (kn < Hh){
      #pragma unroll
      for (int u=0;u<2;u++){
        int gk = kn + lk + 2*u;
        float2 vm = make_float2(0.f,0.f), vr = make_float2(0.f,0.f);
        if (gk < Hh){
          vm = *(const float2*)(nmr+gk); vr = *(const float2*)(nrr+gk);
          if (sub){
            float2 a = *(const float2*)(mr+gk), b = *(const float2*)(rmr+gk);
            vm.x -= a.x; vm.y -= a.y; vr.x -= b.x; vr.y -= b.y;
          }
        }
        pm[u] = vm; pr[u] = vr;
      }
      int gk = kn + kr, gn = bn + ncB;
      bool ok = (gk<Hh) && (gn<Hh);
      pz = ok? *(const float2*)(WzB + (size_t)gk*Hh + gn) : make_float2(0.f,0.f);
      ph = ok? *(const float2*)(WhB + (size_t)gk*Hh + gn) : make_float2(0.f,0.f);
    }
    #pragma unroll
    for (int kk=0; kk<8; kk++){
      float4 a0 = *(const float4*)&Ss[kk][ty*8];
      float4 a1 = *(const float4*)&Ss[kk][ty*8+4];
      float4 r0 = *(const float4*)&Rs[kk][ty*8];
      float4 r1 = *(const float4*)&Rs[kk][ty*8+4];
      float4 bz = *(const float4*)&Bz[kk][tx*4];
      float4 bh = *(const float4*)&Bh[kk][tx*4];
      float a[8] = {a0.x,a0.y,a0.z,a0.w,a1.x,a1.y,a1.z,a1.w};
      float w[8] = {r0.x,r0.y,r0.z,r0.w,r1.x,r1.y,r1.z,r1.w};
      float vz[4] = {bz.x,bz.y,bz.z,bz.w};
      float vh[4] = {bh.x,bh.y,bh.z,bh.w};
      #pragma unroll
      for (int i=0;i<8;i++)
        #pragma unroll
        for (int j=0;j<4;j++){
          accZ[i][j] = fmaf(a[i], vz[j], accZ[i][j]);
          accH[i][j] = fmaf(w[i], vh[j], accH[i][j]);
        }
    }
    __syncthreads();
  }
  #pragma unroll
  for (int i=0;i<8;i++){
    int r = ty*8 + i;
    int se = s_se[r], oidx = s_out[r], rv = s_rv[r], w = s_w[r];
    const float* xz = g_Tz + (size_t)w*Hh;
    const float* xh = g_Th + (size_t)w*Hh;
    const float* nm = g_nm + (size_t)se*Hh;
    const float* mrr= g_m  + (size_t)rv*Hh;
    float* mo = (dstout ? g_nm : g_m) + (size_t)oidx*Hh;
    #pragma unroll
    for (int j=0;j<4;j+=2){
      int c = bn + tx*4 + j;
      if (c >= Hh) continue;
      float2 xzv = *(const float2*)(xz+c), xhv = *(const float2*)(xh+c);
      float2 nmv = *(const float2*)(nm+c);
      float2 mv  = sub ? *(const float2*)(mrr+c) : make_float2(0.f,0.f);
      float z0 = sigmoidf_(accZ[i][j]   + xzv.x), mt0 = tanhf(accH[i][j]   + xhv.x);
      float z1 = sigmoidf_(accZ[i][j+1] + xzv.y), mt1 = tanhf(accH[i][j+1] + xhv.y);
      float s0 = nmv.x - mv.x, s1 = nmv.y - mv.y;
      *(float2*)(mo+c) = make_float2((1.f-z0)*s0 + z0*mt0,
                                     (1.f-z1)*s1 + z1*mt1);
    }
  }
}

// ---------------------------------------------------------------------------
// GEMM A mid (dual, 64x64x16, 4x4 microtile): for Ne in {1024, 2048}
// ---------------------------------------------------------------------------
__global__ __launch_bounds__(256) void k_gemmA_m(
    const int* __restrict__ sched, const int* __restrict__ srcv,
    const int* __restrict__ revv,  const int* __restrict__ wid,
    const float* __restrict__ WzB, const float* __restrict__ WhB, int sub){
  __shared__ float Ss[16][64], Rs[16][64];
  __shared__ float Bz[16][64], Bh[16][64];
  __shared__ int s_eid[64], s_se[64], s_rv[64], s_w[64];
  int bm = blockIdx.x*64, bn = blockIdx.y*64;
  int tid = threadIdx.x;
  if (tid < 64){
    int e = sched[bm + tid];
    int se = srcv[e];
    s_eid[tid] = e; s_se[tid] = se; s_rv[tid] = revv[e]; s_w[tid] = wid[se];
  }
  __syncthreads();
  int ty = tid>>4, tx = tid&15;
  float accZ[4][4] = {}, accH[4][4] = {};
  int lr = tid>>2, lk = (tid&3)*4;
  const float* nmr = g_nm  + (size_t)s_se[lr]*Hh;
  const float* nrr = g_nrm + (size_t)s_se[lr]*Hh;
  const float* mr  = g_m   + (size_t)s_rv[lr]*Hh;
  const float* rmr = g_rm  + (size_t)s_rv[lr]*Hh;
  int kr = tid>>4, nc = (tid&15)*4;

  for (int k0=0; k0<Hh; k0+=16){
    #pragma unroll
    for (int u=0;u<2;u++){
      int gk = k0 + lk + 2*u;
      float2 vm = make_float2(0.f,0.f), vr = make_float2(0.f,0.f);
      if (gk < Hh){
        vm = *(const float2*)(nmr+gk); vr = *(const float2*)(nrr+gk);
        if (sub){
          float2 a = *(const float2*)(mr+gk), b = *(const float2*)(rmr+gk);
          vm.x -= a.x; vm.y -= a.y; vr.x -= b.x; vr.y -= b.y;
        }
      }
      Ss[lk+2*u][lr] = vm.x; Ss[lk+2*u+1][lr] = vm.y;
      Rs[lk+2*u][lr] = vr.x; Rs[lk+2*u+1][lr] = vr.y;
    }
    {
      int gk = k0 + kr;
      const float* zr = WzB + (size_t)gk*Hh;
      const float* hr = WhB + (size_t)gk*Hh;
      #pragma unroll
      for (int u=0;u<2;u++){
        int gn = bn + nc + 2*u;
        bool ok = (gk<Hh) && (gn<Hh);
        float2 vz = ok? *(const float2*)(zr+gn) : make_float2(0.f,0.f);
        float2 vh = ok? *(const float2*)(hr+gn) : make_float2(0.f,0.f);
        Bz[kr][nc+2*u] = vz.x; Bz[kr][nc+2*u+1] = vz.y;
        Bh[kr][nc+2*u] = vh.x; Bh[kr][nc+2*u+1] = vh.y;
      }
    }
    __syncthreads();
    #pragma unroll
    for (int kk=0; kk<16; kk++){
      float4 a0 = *(const float4*)&Ss[kk][ty*4];
      float4 r0 = *(const float4*)&Rs[kk][ty*4];
      float4 bz = *(const float4*)&Bz[kk][tx*4];
      float4 bh = *(const float4*)&Bh[kk][tx*4];
      float a[4] = {a0.x,a0.y,a0.z,a0.w};
      float w[4] = {r0.x,r0.y,r0.z,r0.w};
      float vz[4] = {bz.x,bz.y,bz.z,bz.w};
      float vh[4] = {bh.x,bh.y,bh.z,bh.w};
      #pragma unroll
      for (int i=0;i<4;i++)
        #pragma unroll
        for (int j=0;j<4;j++){
          accZ[i][j] = fmaf(a[i], vz[j], accZ[i][j]);
          accH[i][j] = fmaf(w[i], vh[j], accH[i][j]);
        }
    }
    __syncthreads();
  }
  #pragma unroll
  for (int i=0;i<4;i++){
    int r = ty*4 + i;
    int se = s_se[r], e = s_eid[r], rv = s_rv[r], w = s_w[r];
    const float* xz = g_Tz + (size_t)w*Hh;
    const float* xh = g_Th + (size_t)w*Hh;
    const float* nm = g_nm + (size_t)se*Hh;
    const float* mrr= g_m  + (size_t)rv*Hh;
    float* mo = g_m + (size_t)e*Hh;
    #pragma unroll
    for (int j=0;j<4;j+=2){
      int c = bn + tx*4 + j;
      if (c >= Hh) continue;
      float2 xzv = *(const float2*)(xz+c), xhv = *(const float2*)(xh+c);
      float2 nmv = *(const float2*)(nm+c);
      float2 mv  = sub ? *(const float2*)(mrr+c) : make_float2(0.f,0.f);
      float z0 = sigmoidf_(accZ[i][j]   + xzv.x), mt0 = tanhf(accH[i][j]   + xhv.x);
      float z1 = sigmoidf_(accZ[i][j+1] + xzv.y), mt1 = tanhf(accH[i][j+1] + xhv.y);
      float s0 = nmv.x - mv.x, s1 = nmv.y - mv.y;
      *(float2*)(mo+c) = make_float2((1.f-z0)*s0 + z0*mt0,
                                     (1.f-z1)*s1 + z1*mt1);
    }
  }
}

// ---------------------------------------------------------------------------
// GEMM B mid (64x128x16, 4x8 microtile): for Ne >= 4096
// up=1: STORE nm/nrm (sibling pair) + write g_rm; up=0: accumulate, skip g_rm
// ---------------------------------------------------------------------------
__global__ __launch_bounds__(256) void k_gemmB_m(
    const int* __restrict__ sched, const int* __restrict__ dstv,
    const int* __restrict__ wid, const float* __restrict__ Ur, int up){
  __shared__ float As[16][64];
  __shared__ float Bs[16][128];
  __shared__ int s_eid[64], s_de[64], s_wd[64];
  int bm = blockIdx.x*64, bn = blockIdx.y*128;
  int tid = threadIdx.x;
  if (tid < 64){
    int e = sched[bm + tid];
    int de = dstv[e];
    s_eid[tid] = e; s_de[tid] = de; s_wd[tid] = wid[de];
  }
  __syncthreads();
  int ty = tid>>4, tx = tid&15;
  float acc[4][8] = {};
  int lr = tid>>2, lk = (tid&3)*4;
  const float* Ar = g_m + (size_t)s_eid[lr]*Hh;
  int kr = tid>>4, nc = (tid&15)*8;

  for (int k0=0; k0<Hh; k0+=16){
    #pragma unroll
    for (int u=0;u<2;u++){
      int gk = k0 + lk + 2*u;
      float2 v = (gk<Hh)? *(const float2*)(Ar+gk) : make_float2(0.f,0.f);
      As[lk+2*u][lr] = v.x; As[lk+2*u+1][lr] = v.y;
    }
    {
      int gk = k0 + kr;
      const float* Br = Ur + (size_t)gk*Hh;
      #pragma unroll
      for (int u=0;u<4;u++){
        int gn = bn + nc + 2*u;
        float2 v = (gk<Hh && gn<Hh)? *(const float2*)(Br+gn) : make_float2(0.f,0.f);
        Bs[kr][nc+2*u] = v.x; Bs[kr][nc+2*u+1] = v.y;
      }
    }
    __syncthreads();
    #pragma unroll
    for (int kk=0; kk<16; kk++){
      float4 a0 = *(const float4*)&As[kk][ty*4];
      float4 b0 = *(const float4*)&Bs[kk][tx*8];
      float4 b1 = *(const float4*)&Bs[kk][tx*8+4];
      float a[4] = {a0.x,a0.y,a0.z,a0.w};
      float b[8] = {b0.x,b0.y,b0.z,b0.w,b1.x,b1.y,b1.z,b1.w};
      #pragma unroll
      for (int i=0;i<4;i++)
        #pragma unroll
        for (int j=0;j<8;j++) acc[i][j] = fmaf(a[i], b[j], acc[i][j]);
    }
    __syncthreads();
  }
  #pragma unroll
  for (int q=0;q<4;q++){
    int c = bn + tx*8 + 2*q;
    if (c >= Hh) continue;
    #pragma unroll
    for (int i=0;i<4;i+=2){
      int r0 = ty*4 + i, r1 = r0 + 1;
      int e0 = s_eid[r0], e1 = s_eid[r1];
      int d0 = s_de[r0],  d1 = s_de[r1];
      int w0 = s_wd[r0],  w1 = s_wd[r1];
      float2 mv0 = *(const float2*)(g_m + (size_t)e0*Hh + c);
      float2 mv1 = *(const float2*)(g_m + (size_t)e1*Hh + c);
      float2 x0  = *(const float2*)(g_Tr + (size_t)w0*Hh + c);
      float2 x1  = *(const float2*)(g_Tr + (size_t)w1*Hh + c);
      float2 rm0 = make_float2(sigmoidf_(acc[i][2*q]+x0.x)*mv0.x,
                               sigmoidf_(acc[i][2*q+1]+x0.y)*mv0.y);
      float2 rm1 = make_float2(sigmoidf_(acc[i+1][2*q]+x1.x)*mv1.x,
                               sigmoidf_(acc[i+1][2*q+1]+x1.y)*mv1.y);
      if (up){
        *(float2*)(g_rm + (size_t)e0*Hh + c) = rm0;
        *(float2*)(g_rm + (size_t)e1*Hh + c) = rm1;
        size_t idx = (size_t)d0*Hh + c;               // sibling pair: STORE
        *(float2*)(g_nm+idx)  = make_float2(mv0.x+mv1.x, mv0.y+mv1.y);
        *(float2*)(g_nrm+idx) = make_float2(rm0.x+rm1.x, rm0.y+rm1.y);
      } else {                                        // down: accumulate
        size_t i0 = (size_t)d0*Hh + c, i1 = (size_t)d1*Hh + c;
        float2 a0v = *(float2*)(g_nm+i0), b0v = *(float2*)(g_nrm+i0);
        a0v.x += mv0.x; a0v.y += mv0.y; b0v.x += rm0.x; b0v.y += rm0.y;
        *(float2*)(g_nm+i0) = a0v; *(float2*)(g_nrm+i0) = b0v;
        float2 a1v = *(float2*)(g_nm+i1), b1v = *(float2*)(g_nrm+i1);
        a1v.x += mv1.x; a1v.y += mv1.y; b1v.x += rm1.x; b1v.y += rm1.y;
        *(float2*)(g_nm+i1) = a1v; *(float2*)(g_nrm+i1) = b1v;
      }
    }
  }
}

// ---------------------------------------------------------------------------
// GEMM B mid64 (64x64x16, 4x4 microtile): for Ne in {1024, 2048}
// ---------------------------------------------------------------------------
__global__ __launch_bounds__(256) void k_gemmB_m64(
    const int* __restrict__ sched, const int* __restrict__ dstv,
    const int* __restrict__ wid, const float* __restrict__ Ur, int up){
  __shared__ float As[16][64];
  __shared__ float Bs[16][64];
  __shared__ int s_eid[64], s_de[64], s_wd[64];
  int bm = blockIdx.x*64, bn = blockIdx.y*64;
  int tid = threadIdx.x;
  if (tid < 64){
    int e = sched[bm + tid];
    int de = dstv[e];
    s_eid[tid] = e; s_de[tid] = de; s_wd[tid] = wid[de];
  }
  __syncthreads();
  int ty = tid>>4, tx = tid&15;
  float acc[4][4] = {};
  int lr = tid>>2, lk = (tid&3)*4;
  const float* Ar = g_m + (size_t)s_eid[lr]*Hh;
  int kr = tid>>4, nc = (tid&15)*4;

  for (int k0=0; k0<Hh; k0+=16){
    #pragma unroll
    for (int u=0;u<2;u++){
      int gk = k0 + lk + 2*u;
      float2 v = (gk<Hh)? *(const float2*)(Ar+gk) : make_float2(0.f,0.f);
      As[lk+2*u][lr] = v.x; As[lk+2*u+1][lr] = v.y;
    }
    {
      int gk = k0 + kr;
      const float* Br = Ur + (size_t)gk*Hh;
      #pragma unroll
      for (int u=0;u<2;u++){
        int gn = bn + nc + 2*u;
        float2 v = (gk<Hh && gn<Hh)? *(const float2*)(Br+gn) : make_float2(0.f,0.f);
        Bs[kr][nc+2*u] = v.x; Bs[kr][nc+2*u+1] = v.y;
      }
    }
    __syncthreads();
    #pragma unroll
    for (int kk=0; kk<16; kk++){
      float4 a0 = *(const float4*)&As[kk][ty*4];
      float4 b0 = *(const float4*)&Bs[kk][tx*4];
      float a[4] = {a0.x,a0.y,a0.z,a0.w};
      float b[4] = {b0.x,b0.y,b0.z,b0.w};
      #pragma unroll
      for (int i=0;i<4;i++)
        #pragma unroll
        for (int j=0;j<4;j++) acc[i][j] = fmaf(a[i], b[j], acc[i][j]);
    }
    __syncthreads();
  }
  #pragma unroll
  for (int q=0;q<2;q++){
    int c = bn + tx*4 + 2*q;
    if (c >= Hh) continue;
    #pragma unroll
    for (int i=0;i<4;i+=2){
      int r0 = ty*4 + i, r1 = r0 + 1;
      int e0 = s_eid[r0], e1 = s_eid[r1];
      int d0 = s_de[r0],  d1 = s_de[r1];
      int w0 = s_wd[r0],  w1 = s_wd[r1];
      float2 mv0 = *(const float2*)(g_m + (size_t)e0*Hh + c);
      float2 mv1 = *(const float2*)(g_m + (size_t)e1*Hh + c);
      float2 x0  = *(const float2*)(g_Tr + (size_t)w0*Hh + c);
      float2 x1  = *(const float2*)(g_Tr + (size_t)w1*Hh + c);
      float2 rm0 = make_float2(sigmoidf_(acc[i][2*q]+x0.x)*mv0.x,
                               sigmoidf_(acc[i][2*q+1]+x0.y)*mv0.y);
      float2 rm1 = make_float2(sigmoidf_(acc[i+1][2*q]+x1.x)*mv1.x,
                               sigmoidf_(acc[i+1][2*q+1]+x1.y)*mv1.y);
      if (up){
        *(float2*)(g_rm + (size_t)e0*Hh + c) = rm0;
        *(float2*)(g_rm + (size_t)e1*Hh + c) = rm1;
        size_t idx = (size_t)d0*Hh + c;               // sibling pair: STORE
        *(float2*)(g_nm+idx)  = make_float2(mv0.x+mv1.x, mv0.y+mv1.y);
        *(float2*)(g_nrm+idx) = make_float2(rm0.x+rm1.x, rm0.y+rm1.y);
      } else {                                        // down: accumulate
        size_t i0 = (size_t)d0*Hh + c, i1 = (size_t)d1*Hh + c;
        float2 a0v = *(float2*)(g_nm+i0), b0v = *(float2*)(g_nrm+i0);
        a0v.x += mv0.x; a0v.y += mv0.y; b0v.x += rm0.x; b0v.y += rm0.y;
        *(float2*)(g_nm+i0) = a0v; *(float2*)(g_nrm+i0) = b0v;
        float2 a1v = *(float2*)(g_nm+i1), b1v = *(float2*)(g_nrm+i1);
        a1v.x += mv1.x; a1v.y += mv1.y; b1v.x += rm1.x; b1v.y += rm1.y;
        *(float2*)(g_nm+i1) = a1v; *(float2*)(g_nrm+i1) = b1v;
      }
    }
  }
}

// ---------------------------------------------------------------------------
// Small-level variants (32x32x32, 2x2 microtile, 256 threads)
// ---------------------------------------------------------------------------
__global__ __launch_bounds__(256) void k_gemmA_s(
    const int* __restrict__ sched, const int* __restrict__ srcv,
    const int* __restrict__ revv,  const int* __restrict__ wid,
    const float* __restrict__ WzB, const float* __restrict__ WhB, int sub){
  __shared__ float Ss[32][32], Rs[32][32], Bz[32][32], Bh[32][32];
  __shared__ int s_eid[32], s_se[32], s_rv[32], s_w[32];
  int bm = blockIdx.x*32, bn = blockIdx.y*32;
  int tid = threadIdx.x;
  if (tid < 32){
    int e = sched[bm + tid];
    int se = srcv[e];
    s_eid[tid] = e; s_se[tid] = se; s_rv[tid] = revv[e]; s_w[tid] = wid[se];
  }
  __syncthreads();
  int ty = tid>>4, tx = tid&15;
  float accZ[2][2] = {}, accH[2][2] = {};
  int lr = tid>>3, lk = (tid&7)*4;     // 4 k-floats per thread (2 float2)
  const float* nmr = g_nm  + (size_t)s_se[lr]*Hh;
  const float* nrr = g_nrm + (size_t)s_se[lr]*Hh;
  const float* mr  = g_m   + (size_t)s_rv[lr]*Hh;
  const float* rmr = g_rm  + (size_t)s_rv[lr]*Hh;
  int kr = tid>>3, cn = (tid&7)*4;     // B: 4 cols per thread

  for (int k0=0; k0<Hh; k0+=32){
    #pragma unroll
    for (int u=0;u<2;u++){
      int gk = k0 + lk + 2*u;
      float2 vm = make_float2(0.f,0.f), vr = make_float2(0.f,0.f);
      if (gk < Hh){
        vm = *(const float2*)(nmr+gk); vr = *(const float2*)(nrr+gk);
        if (sub){
          float2 a = *(const float2*)(mr+gk), b = *(const float2*)(rmr+gk);
          vm.x -= a.x; vm.y -= a.y; vr.x -= b.x; vr.y -= b.y;
        }
      }
      Ss[lk+2*u][lr] = vm.x; Ss[lk+2*u+1][lr] = vm.y;
      Rs[lk+2*u][lr] = vr.x; Rs[lk+2*u+1][lr] = vr.y;
    }
    {
      int gk = k0 + kr;
      const float* zr = WzB + (size_t)gk*Hh;
      const float* hr = WhB + (size_t)gk*Hh;
      #pragma unroll
      for (int u=0;u<2;u++){
        int gn = bn + cn + 2*u;
        bool ok = (gk<Hh) && (gn<Hh);
        float2 vz = ok? *(const float2*)(zr+gn) : make_float2(0.f,0.f);
        float2 vh = ok? *(const float2*)(hr+gn) : make_float2(0.f,0.f);
        Bz[kr][cn+2*u] = vz.x; Bz[kr][cn+2*u+1] = vz.y;
        Bh[kr][cn+2*u] = vh.x; Bh[kr][cn+2*u+1] = vh.y;
      }
    }
    __syncthreads();
    #pragma unroll
    for (int kk=0; kk<32; kk++){
      float a0=Ss[kk][ty*2], a1=Ss[kk][ty*2+1];
      float w0=Rs[kk][ty*2], w1=Rs[kk][ty*2+1];
      float z0=Bz[kk][tx*2], z1=Bz[kk][tx*2+1];
      float h0=Bh[kk][tx*2], h1=Bh[kk][tx*2+1];
      accZ[0][0]=fmaf(a0,z0,accZ[0][0]); accZ[0][1]=fmaf(a0,z1,accZ[0][1]);
      accZ[1][0]=fmaf(a1,z0,accZ[1][0]); accZ[1][1]=fmaf(a1,z1,accZ[1][1]);
      accH[0][0]=fmaf(w0,h0,accH[0][0]); accH[0][1]=fmaf(w0,h1,accH[0][1]);
      accH[1][0]=fmaf(w1,h0,accH[1][0]); accH[1][1]=fmaf(w1,h1,accH[1][1]);
    }
    __syncthreads();
  }
  #pragma unroll
  for (int i=0;i<2;i++){
    int r = ty*2 + i;
    int se = s_se[r], e = s_eid[r], rv = s_rv[r], w = s_w[r];
    #pragma unroll
    for (int j=0;j<2;j++){
      int c = bn + tx*2 + j;
      if (c >= Hh) continue;
      float z  = sigmoidf_(accZ[i][j] + g_Tz[(size_t)w*Hh + c]);
      float mt = tanhf   (accH[i][j] + g_Th[(size_t)w*Hh + c]);
      float s  = g_nm[(size_t)se*Hh + c] - (sub ? g_m[(size_t)rv*Hh + c] : 0.f);
      g_m[(size_t)e*Hh + c] = (1.f - z)*s + z*mt;
    }
  }
}

__global__ __launch_bounds__(256) void k_gemmB_s(
    const int* __restrict__ sched, const int* __restrict__ dstv,
    const int* __restrict__ wid, const float* __restrict__ Ur, int up){
  __shared__ float As[32][32], Bs[32][32];
  __shared__ int s_eid[32], s_de[32], s_wd[32];
  int bm = blockIdx.x*32, bn = blockIdx.y*32;
  int tid = threadIdx.x;
  if (tid < 32){
    int e = sched[bm + tid];
    int de = dstv[e];
    s_eid[tid] = e; s_de[tid] = de; s_wd[tid] = wid[de];
  }
  __syncthreads();
  int ty = tid>>4, tx = tid&15;
  float acc[2][2] = {};
  int lr = tid>>3, lk = (tid&7)*4;
  const float* Ar = g_m + (size_t)s_eid[lr]*Hh;
  int kr = tid>>3, cn = (tid&7)*4;

  for (int k0=0; k0<Hh; k0+=32){
    #pragma unroll
    for (int u=0;u<2;u++){
      int gk = k0 + lk + 2*u;
      float2 v = (gk<Hh)? *(const float2*)(Ar+gk) : make_float2(0.f,0.f);
      As[lk+2*u][lr] = v.x; As[lk+2*u+1][lr] = v.y;
    }
    {
      int gk = k0 + kr;
      const float* Br = Ur + (size_t)gk*Hh;
      #pragma unroll
      for (int u=0;u<2;u++){
        int gn = bn + cn + 2*u;
        float2 v = ((gk<Hh)&&(gn<Hh))? *(const float2*)(Br+gn)
                                     : make_float2(0.f,0.f);
        Bs[kr][cn+2*u] = v.x; Bs[kr][cn+2*u+1] = v.y;
      }
    }
    __syncthreads();
    #pragma unroll
    for (int kk=0; kk<32; kk++){
      float a0=As[kk][ty*2], a1=As[kk][ty*2+1];
      float b0=Bs[kk][tx*2], b1=Bs[kk][tx*2+1];
      acc[0][0]=fmaf(a0,b0,acc[0][0]); acc[0][1]=fmaf(a0,b1,acc[0][1]);
      acc[1][0]=fmaf(a1,b0,acc[1][0]); acc[1][1]=fmaf(a1,b1,acc[1][1]);
    }
    __syncthreads();
  }
  int r0 = ty*2, r1 = ty*2+1;
  int e0 = s_eid[r0], e1 = s_eid[r1];
  int d0 = s_de[r0],  d1 = s_de[r1];
  int w0 = s_wd[r0],  w1 = s_wd[r1];
  #pragma unroll
  for (int j=0;j<2;j++){
    int c = bn + tx*2 + j;
    if (c >= Hh) continue;
    float mv0 = g_m[(size_t)e0*Hh + c];
    float mv1 = g_m[(size_t)e1*Hh + c];
    float rm0 = sigmoidf_(acc[0][j] + g_Tr[(size_t)w0*Hh + c]) * mv0;
    float rm1 = sigmoidf_(acc[1][j] + g_Tr[(size_t)w1*Hh + c]) * mv1;
    if (up){
      g_rm[(size_t)e0*Hh + c] = rm0;
      g_rm[(size_t)e1*Hh + c] = rm1;
      size_t idx = (size_t)d0*Hh + c;   // sibling pair: STORE
      g_nm[idx]  = mv0 + mv1;
      g_nrm[idx] = rm0 + rm1;
    } else {
      g_nm[(size_t)d0*Hh + c]  += mv0;
      g_nrm[(size_t)d0*Hh + c] += rm0;
      g_nm[(size_t)d1*Hh + c]  += mv1;
      g_nrm[(size_t)d1*Hh + c] += rm1;
    }
  }
}

// ---------------------------------------------------------------------------
// Final readout (cp.async double-buffered, 2 CTAs/SM):
// out = relu(Tg[wid[r]] + node_m @ WgB)
// ---------------------------------------------------------------------------
__global__ __launch_bounds__(256,2) void k_final(
    const int* __restrict__ wid, const float* __restrict__ WgB,
    float* __restrict__ out){
  __shared__ float2 As2[2][8][128];
  __shared__ float  Bs [2][16][128];
  int bm = blockIdx.x*128, bn = blockIdx.y*128;
  int tid = threadIdx.x, ty = tid>>4, tx = tid&15;
  float acc[8][8] = {};
  int lr = tid>>1, lk = (tid&1)*8;
  const float* Ar = g_nm + (size_t)(bm+lr)*Hh;
  int kr = tid>>4, nc = (tid&15)*8;

  const int T = (Hh + 15)/16;
  {
    #pragma unroll
    for (int u=0;u<4;u++){
      int gk = lk + 2*u;
      cpa8(sptr(&As2[0][(lk>>1)+u][lr]), Ar + gk, gk < Hh);
    }
    const float* Br = WgB + (size_t)kr*Hh;
    #pragma unroll
    for (int u=0;u<4;u++){
      int gn = bn + nc + 2*u;
      cpa8(sptr(&Bs[0][kr][nc+2*u]), Br + ((gn<Hh)? gn : 0), (kr<Hh) && (gn<Hh));
    }
    CP_COMMIT();
  }
  for (int t=0; t<T; t++){
    int buf = t & 1;
    if (t+1 < T){
      int k0 = (t+1)*16, nb = buf^1;
      #pragma unroll
      for (int u=0;u<4;u++){
        int gk = k0 + lk + 2*u;
        cpa8(sptr(&As2[nb][(lk>>1)+u][lr]), Ar + ((gk<Hh)? gk : 0), gk < Hh);
      }
      int gkB = k0 + kr;
      const float* Br = WgB + (size_t)((gkB<Hh)? gkB : 0)*Hh;
      #pragma unroll
      for (int u=0;u<4;u++){
        int gn = bn + nc + 2*u;
        cpa8(sptr(&Bs[nb][kr][nc+2*u]), Br + ((gn<Hh)? gn : 0),
             (gkB<Hh) && (gn<Hh));
      }
      CP_COMMIT();
      CP_WAIT1();
    } else {
      CP_WAIT0();
    }
    __syncthreads();
    #pragma unroll
    for (int kp=0; kp<8; kp++){
      float2 a2[8];
      #pragma unroll
      for (int i=0;i<8;i+=2){
        float4 t4 = *(const float4*)&As2[buf][kp][ty*8+i];
        a2[i]   = make_float2(t4.x, t4.y);
        a2[i+1] = make_float2(t4.z, t4.w);
      }
      float4 b00 = *(const float4*)&Bs[buf][2*kp  ][tx*8];
      float4 b01 = *(const float4*)&Bs[buf][2*kp  ][tx*8+4];
      float4 b10 = *(const float4*)&Bs[buf][2*kp+1][tx*8];
      float4 b11 = *(const float4*)&Bs[buf][2*kp+1][tx*8+4];
      float b0[8] = {b00.x,b00.y,b00.z,b00.w,b01.x,b01.y,b01.z,b01.w};
      float b1[8] = {b10.x,b10.y,b10.z,b10.w,b11.x,b11.y,b11.z,b11.w};
      #pragma unroll
      for (int i=0;i<8;i++)
        #pragma unroll
        for (int j=0;j<8;j++){
          acc[i][j] = fmaf(a2[i].x, b0[j], acc[i][j]);
          acc[i][j] = fmaf(a2[i].y, b1[j], acc[i][j]);
        }
    }
    __syncthreads();
  }
  #pragma unroll
  for (int i=0;i<8;i++){
    int r = bm + ty*8 + i;
    const float* xg = g_Tg + (size_t)wid[r]*Hh;
    #pragma unroll
    for (int j=0;j<8;j+=2){
      int c = bn + tx*8 + j;
      if (c >= Hh) continue;
      float2 xv = *(const float2*)(xg + c);
      *(float2*)(out + (size_t)r*Hh + c) =
          make_float2(fmaxf(acc[i][j]+xv.x,0.f), fmaxf(acc[i][j+1]+xv.y,0.f));
    }
  }
}

// ---------------------------------------------------------------------------
// kernel_launch
// Inputs: 0 wid, 1 src, 2 dst, 3 rev, 4 sched, 5 emb, 6 Wz, 7 bz,
//         8 Wr, 9 Ur, 10 bur, 11 Wh, 12 bh, 13 Wg, 14 bg
// ---------------------------------------------------------------------------
extern "C" void kernel_launch(void* const* d_in, const int* in_sizes, int n_in,
                              void* d_out, int out_size) {
  const int*   wid   = (const int*)  d_in[0];
  const int*   srcv  = (const int*)  d_in[1];
  const int*   dstv  = (const int*)  d_in[2];
  const int*   revv  = (const int*)  d_in[3];
  const int*   sched = (const int*)  d_in[4];
  const float* emb   = (const float*)d_in[5];
  const float* Wz    = (const float*)d_in[6];
  const float* bz    = (const float*)d_in[7];
  const float* Wr    = (const float*)d_in[8];
  const float* Ur    = (const float*)d_in[9];
  const float* bur   = (const float*)d_in[10];
  const float* Wh    = (const float*)d_in[11];
  const float* bh    = (const float*)d_in[12];
  const float* Wg    = (const float*)d_in[13];
  const float* bg    = (const float*)d_in[14];
  float* out = (float*)d_out;

  const int lmax = in_sizes[4] / 12;   // 8192
  static const int NeTab[12] = {8192,4096,2048,1024,512,256,
                                 256,512,1024,2048,4096,8192};

  // vocab tables (no zero-init needed anywhere)
  dim3 gv((Vv + 63)/64, 4, 4);
  k_vocab4<<<gv, 256>>>(emb, Wz, bz, Wh, bh, Wr, bur, Wg, bg);
  k_tm<<<(Vv*(Hh/2) + 255)/256, 256>>>();
  dim3 gtr((Vv + 63)/64, 8);
  k_vocabTR<<<gtr, 256>>>(Ur);

  // level 0: vocab-table gather + sibling-pair STORE scatter (no edge GEMM)
  k_leaf<<<NeTab[0]/2, 256>>>(sched, srcv, dstv, wid);

  // levels 1..10
  for (int lvl = 1; lvl < 11; lvl++) {
    int Ne  = NeTab[lvl];
    int sub = (lvl >= 6) ? 1 : 0;
    int up  = (lvl <  6) ? 1 : 0;
    const int* sc = sched + lvl*lmax;
    if (Ne >= 4096){
      dim3 gA(Ne/128, 8);
      k_gemmA_b<<<gA, 256>>>(sc, srcv, revv, dstv, wid,
                             Wz + Hh*Hh, Wh + Hh*Hh, sub, 0);
      dim3 gB(Ne/64, 4);
      k_gemmB_m<<<gB, 256>>>(sc, dstv, wid, Ur, up);
    } else if (Ne >= 1024){
      dim3 gA(Ne/64, 8);
      k_gemmA_m<<<gA, 256>>>(sc, srcv, revv, wid, Wz + Hh*Hh, Wh + Hh*Hh, sub);
      dim3 gB(Ne/64, 8);
      k_gemmB_m64<<<gB, 256>>>(sc, dstv, wid, Ur, up);
    } else {
      dim3 g(Ne/32, 15);
      k_gemmA_s<<<g, 256>>>(sc, srcv, revv, wid, Wz + Hh*Hh, Wh + Hh*Hh, sub);
      k_gemmB_s<<<g, 256>>>(sc, dstv, wid, Ur, up);
    }
  }
  // level 11: m_new GEMM writing DIRECTLY into nm[dst] (replaces scat11)
  {
    const int* sc = sched + 11*lmax;
    dim3 gA(NeTab[11]/128, 8);
    k_gemmA_b<<<gA, 256>>>(sc, srcv, revv, dstv, wid,
                           Wz + Hh*Hh, Wh + Hh*Hh, 1, 1);
  }

  // readout
  dim3 gf(NNODE/128, 4);
  k_final<<<gf, 256>>>(wid, Wg + Hh*Hh, out);
}